// round 1
// baseline (speedup 1.0000x reference)
#include <cuda_runtime.h>
#include <math.h>

// ---------------------------------------------------------------------------
// Mamba2-style SSD block, fp32 SIMT baseline.
// Stages:
//   1. gemm128:  zxbcdt = x @ in_proj_w^T            [4096 x 8512]
//   2. conv_silu: causal conv1d(k=4) + SiLU on xBC   [4096 x 4352]
//   3. dt_kernel: dt = softplus(dt_raw + bias), dA = dt * (-exp(A_log))
//   4. cumsum:   per-(chunk,head) inclusive cumsum of dA -> dAc
//   5. gemm128:  CB[c][l][s] = C[l,:]·B[s,:] per chunk (G=1, shared over heads)
//   6. states:   per-(chunk,head) states[p][n] = sum_l decay*xdt[l,p]*B[l,n]
//   7. chunkscan: sequential inter-chunk state recurrence
//   8. ydiag_off: fused y_diag (masked L*CB @ xdt) + y_off (C @ prev^T) + D*x
//   9. gatenorm: y *= silu(z); RMSNorm * norm_w
//  10. gemm128:  out = y @ out_proj_w^T              [4096 x 2048]
// ---------------------------------------------------------------------------

#define S_LEN   4096
#define DIM_    2048
#define HID_    4096
#define D_IN_   8512
#define CONVD_  4352
#define NH_     64
#define HD_     64
#define NST_    128
#define CH_     256
#define NC_     16

// Scratch (device globals; no allocation anywhere).
__device__ float g_zx[(size_t)S_LEN * D_IN_];        // 139.5 MB
__device__ float g_conv[(size_t)S_LEN * CONVD_];     // 71.3 MB
__device__ float g_dt[S_LEN * NH_];
__device__ float g_dAc[S_LEN * NH_];
__device__ float g_CB[NC_ * CH_ * CH_];              // 4 MB
__device__ float g_states[NC_ * NH_ * HD_ * NST_];   // 33.5 MB
__device__ float g_prev[NC_ * NH_ * HD_ * NST_];     // 33.5 MB
__device__ float g_y[(size_t)S_LEN * HID_];          // 67 MB

// ---------------------------------------------------------------------------
// Generic tiled SGEMM: C[M,N] = A[M,K] @ B[N,K]^T   (both operands K-contiguous)
// 128x128 block tile, BK=8, 256 threads, 8x8 microtile.
// Requires: M % 128 == 0, K % 8 == 0. N may be ragged (guarded).
// ---------------------------------------------------------------------------
__global__ __launch_bounds__(256) void gemm128(
    int M, int N, int K,
    const float* __restrict__ A, int lda, int strideA,
    const float* __restrict__ B, int ldb, int strideB,
    float* __restrict__ C, int ldc, int strideC)
{
    __shared__ float As[8 * 128];
    __shared__ float Bs[8 * 128];
    const int bz = blockIdx.z;
    A += (size_t)bz * strideA;
    B += (size_t)bz * strideB;
    C += (size_t)bz * strideC;
    const int m0 = blockIdx.y * 128;
    const int n0 = blockIdx.x * 128;
    const int tid = threadIdx.x;
    const int lrow = tid >> 1;          // 0..127
    const int lseg = (tid & 1) * 4;     // 0 or 4
    const int ty = tid >> 4;            // 0..15
    const int tx = tid & 15;            // 0..15

    float acc[8][8];
#pragma unroll
    for (int i = 0; i < 8; i++)
#pragma unroll
        for (int j = 0; j < 8; j++) acc[i][j] = 0.f;

    const bool bok = (n0 + lrow) < N;
    const float* aptr = A + (size_t)(m0 + lrow) * lda + lseg;
    const float* bptr = B + (size_t)(bok ? (n0 + lrow) : 0) * ldb + lseg;

    for (int k0 = 0; k0 < K; k0 += 8) {
        float4 a4 = *(const float4*)(aptr + k0);
        float4 b4 = make_float4(0.f, 0.f, 0.f, 0.f);
        if (bok) b4 = *(const float4*)(bptr + k0);
        As[(lseg + 0) * 128 + lrow] = a4.x;
        As[(lseg + 1) * 128 + lrow] = a4.y;
        As[(lseg + 2) * 128 + lrow] = a4.z;
        As[(lseg + 3) * 128 + lrow] = a4.w;
        Bs[(lseg + 0) * 128 + lrow] = b4.x;
        Bs[(lseg + 1) * 128 + lrow] = b4.y;
        Bs[(lseg + 2) * 128 + lrow] = b4.z;
        Bs[(lseg + 3) * 128 + lrow] = b4.w;
        __syncthreads();
#pragma unroll
        for (int k = 0; k < 8; k++) {
            float ar[8], br[8];
            *(float4*)&ar[0] = *(const float4*)&As[k * 128 + ty * 8];
            *(float4*)&ar[4] = *(const float4*)&As[k * 128 + ty * 8 + 4];
            *(float4*)&br[0] = *(const float4*)&Bs[k * 128 + tx * 8];
            *(float4*)&br[4] = *(const float4*)&Bs[k * 128 + tx * 8 + 4];
#pragma unroll
            for (int i = 0; i < 8; i++)
#pragma unroll
                for (int j = 0; j < 8; j++)
                    acc[i][j] = fmaf(ar[i], br[j], acc[i][j]);
        }
        __syncthreads();
    }

#pragma unroll
    for (int i = 0; i < 8; i++) {
        const int m = m0 + ty * 8 + i;
#pragma unroll
        for (int j4 = 0; j4 < 8; j4 += 4) {
            const int n = n0 + tx * 8 + j4;
            if (n + 4 <= N) {
                *(float4*)(C + (size_t)m * ldc + n) =
                    make_float4(acc[i][j4], acc[i][j4 + 1], acc[i][j4 + 2], acc[i][j4 + 3]);
            } else {
#pragma unroll
                for (int j = 0; j < 4; j++)
                    if (n + j < N) C[(size_t)m * ldc + n + j] = acc[i][j4 + j];
            }
        }
    }
}

// ---------------------------------------------------------------------------
// Causal conv1d (k=4) + SiLU over all 4352 xBC channels.
// ---------------------------------------------------------------------------
__global__ void conv_silu_kernel(const float* __restrict__ w)
{
    const int idx = blockIdx.x * blockDim.x + threadIdx.x;
    if (idx >= S_LEN * CONVD_) return;
    const int c = idx % CONVD_;
    const int t = idx / CONVD_;
    float s = 0.f;
#pragma unroll
    for (int i = 0; i < 4; i++) {
        const int tt = t - 3 + i;
        if (tt >= 0) s += g_zx[(size_t)tt * D_IN_ + HID_ + c] * w[c * 4 + i];
    }
    g_conv[idx] = s / (1.f + expf(-s));
}

// ---------------------------------------------------------------------------
// dt = softplus(raw + bias); dA = dt * (-exp(A_log))  (pre-cumsum, into g_dAc)
// ---------------------------------------------------------------------------
__global__ void dt_kernel(const float* __restrict__ dt_bias,
                          const float* __restrict__ A_log)
{
    const int idx = blockIdx.x * blockDim.x + threadIdx.x;
    if (idx >= S_LEN * NH_) return;
    const int h = idx % NH_;
    const int t = idx / NH_;
    const float raw = g_zx[(size_t)t * D_IN_ + (HID_ + CONVD_) + h] + dt_bias[h];
    const float dt = (raw > 20.f) ? raw : log1pf(expf(raw));
    g_dt[idx] = dt;
    g_dAc[idx] = dt * (-expf(A_log[h]));
}

// ---------------------------------------------------------------------------
// Per-(chunk,head) inclusive cumsum of dA -> dAc (in place, 256-wide scan).
// ---------------------------------------------------------------------------
__global__ __launch_bounds__(CH_) void cumsum_kernel()
{
    const int c = blockIdx.x, h = blockIdx.y;
    const int l = threadIdx.x;
    __shared__ float sbuf[CH_];
    const int gi = (c * CH_ + l) * NH_ + h;
    sbuf[l] = g_dAc[gi];
    __syncthreads();
    for (int off = 1; off < CH_; off <<= 1) {
        const float add = (l >= off) ? sbuf[l - off] : 0.f;
        __syncthreads();
        sbuf[l] += add;
        __syncthreads();
    }
    g_dAc[gi] = sbuf[l];
}

// ---------------------------------------------------------------------------
// states[c][h][p][n] = sum_l (xdt[l,p] * exp(dA_last - dAc[l])) * B[l,n]
// One block per (chunk, head). 64x128 output, micro 4x8, K=256 in 16-tiles.
// ---------------------------------------------------------------------------
__global__ __launch_bounds__(256) void states_kernel()
{
    const int c = blockIdx.x, h = blockIdx.y;
    __shared__ float sdecay[CH_];
    __shared__ float Xs[16 * 64];
    __shared__ float Bs[16 * 128];
    const int tid = threadIdx.x;
    const float dalast = g_dAc[(c * CH_ + CH_ - 1) * NH_ + h];
    {
        const int gi = (c * CH_ + tid) * NH_ + h;
        sdecay[tid] = g_dt[gi] * expf(dalast - g_dAc[gi]);
    }
    __syncthreads();
    const int ty = tid >> 4, tx = tid & 15;
    float acc[4][8];
#pragma unroll
    for (int i = 0; i < 4; i++)
#pragma unroll
        for (int j = 0; j < 8; j++) acc[i][j] = 0.f;

    const int sr = tid >> 4;
    const int p4 = (tid & 15) * 4;
    const int n8 = (tid & 15) * 8;

    for (int s0 = 0; s0 < CH_; s0 += 16) {
        const int t = c * CH_ + s0 + sr;
        const float sc = sdecay[s0 + sr];
        float4 x4 = *(const float4*)&g_conv[(size_t)t * CONVD_ + h * HD_ + p4];
        Xs[sr * 64 + p4 + 0] = x4.x * sc;
        Xs[sr * 64 + p4 + 1] = x4.y * sc;
        Xs[sr * 64 + p4 + 2] = x4.z * sc;
        Xs[sr * 64 + p4 + 3] = x4.w * sc;
        float4 b0 = *(const float4*)&g_conv[(size_t)t * CONVD_ + HID_ + n8];
        float4 b1 = *(const float4*)&g_conv[(size_t)t * CONVD_ + HID_ + n8 + 4];
        Bs[sr * 128 + n8 + 0] = b0.x; Bs[sr * 128 + n8 + 1] = b0.y;
        Bs[sr * 128 + n8 + 2] = b0.z; Bs[sr * 128 + n8 + 3] = b0.w;
        Bs[sr * 128 + n8 + 4] = b1.x; Bs[sr * 128 + n8 + 5] = b1.y;
        Bs[sr * 128 + n8 + 6] = b1.z; Bs[sr * 128 + n8 + 7] = b1.w;
        __syncthreads();
#pragma unroll
        for (int k = 0; k < 16; k++) {
            float ar[4], br[8];
            *(float4*)&ar[0] = *(const float4*)&Xs[k * 64 + ty * 4];
            *(float4*)&br[0] = *(const float4*)&Bs[k * 128 + tx * 8];
            *(float4*)&br[4] = *(const float4*)&Bs[k * 128 + tx * 8 + 4];
#pragma unroll
            for (int i = 0; i < 4; i++)
#pragma unroll
                for (int j = 0; j < 8; j++)
                    acc[i][j] = fmaf(ar[i], br[j], acc[i][j]);
        }
        __syncthreads();
    }
    const size_t base = ((size_t)(c * NH_ + h)) * HD_ * NST_;
#pragma unroll
    for (int i = 0; i < 4; i++) {
        const int p = ty * 4 + i;
        *(float4*)&g_states[base + (size_t)p * NST_ + tx * 8] =
            make_float4(acc[i][0], acc[i][1], acc[i][2], acc[i][3]);
        *(float4*)&g_states[base + (size_t)p * NST_ + tx * 8 + 4] =
            make_float4(acc[i][4], acc[i][5], acc[i][6], acc[i][7]);
    }
}

// ---------------------------------------------------------------------------
// Inter-chunk recurrence: prev[c] = prev[c-1]*decay[c-1] + states[c-1]
// ---------------------------------------------------------------------------
__global__ void chunkscan_kernel()
{
    const int idx = blockIdx.x * blockDim.x + threadIdx.x;
    if (idx >= NH_ * HD_ * NST_) return;
    const int h = idx / (HD_ * NST_);
    const int rem = idx % (HD_ * NST_);
    float carry = 0.f;
#pragma unroll
    for (int c = 0; c < NC_; c++) {
        const size_t off = ((size_t)(c * NH_ + h)) * HD_ * NST_ + rem;
        g_prev[off] = carry;
        const float dec = expf(g_dAc[(c * CH_ + CH_ - 1) * NH_ + h]);
        carry = carry * dec + g_states[off];
    }
}

// ---------------------------------------------------------------------------
// Fused y kernel per (l-tile, chunk, head):
//   y = (L .* CB) @ xdt  +  exp(dAc) * (C @ prev^T)  +  D * x
// 64x64 output tile, micro 4x4.
// ---------------------------------------------------------------------------
__global__ __launch_bounds__(256) void ydiag_off_kernel(const float* __restrict__ Dp)
{
    const int lt = blockIdx.x, c = blockIdx.y, h = blockIdx.z;
    __shared__ float sdAc[CH_];
    __shared__ float sdt[CH_];
    __shared__ float Ms[16 * 64];
    __shared__ float Xs[16 * 64];
    const int tid = threadIdx.x;
    {
        const int gi = (c * CH_ + tid) * NH_ + h;
        sdAc[tid] = g_dAc[gi];
        sdt[tid] = g_dt[gi];
    }
    __syncthreads();
    const int ty = tid >> 4, tx = tid & 15;
    const int l0 = lt * 64;
    float accA[4][4], acc2[4][4];
#pragma unroll
    for (int i = 0; i < 4; i++)
#pragma unroll
        for (int j = 0; j < 4; j++) { accA[i][j] = 0.f; acc2[i][j] = 0.f; }

    const int lr = tid >> 2;            // 0..63 (row within 64-l tile)
    const int si4 = (tid & 3) * 4;      // 0,4,8,12
    const int sr = tid >> 4;            // 0..15
    const int p4 = (tid & 15) * 4;      // 0..60

    // Phase A: masked diagonal part, K over s-tiles up to l-range
    const int smax = l0 + 64;
    for (int s0 = 0; s0 < smax; s0 += 16) {
        float4 cb4 = *(const float4*)&g_CB[c * (CH_ * CH_) + (l0 + lr) * CH_ + s0 + si4];
        const float dacl = sdAc[l0 + lr];
        float mv[4] = {cb4.x, cb4.y, cb4.z, cb4.w};
#pragma unroll
        for (int j = 0; j < 4; j++) {
            const int sj = s0 + si4 + j;
            float v = 0.f;
            if (sj <= l0 + lr) v = mv[j] * expf(dacl - sdAc[sj]);
            Ms[(si4 + j) * 64 + lr] = v;
        }
        const int t = c * CH_ + s0 + sr;
        const float dtv = sdt[s0 + sr];
        float4 x4 = *(const float4*)&g_conv[(size_t)t * CONVD_ + h * HD_ + p4];
        Xs[sr * 64 + p4 + 0] = x4.x * dtv;
        Xs[sr * 64 + p4 + 1] = x4.y * dtv;
        Xs[sr * 64 + p4 + 2] = x4.z * dtv;
        Xs[sr * 64 + p4 + 3] = x4.w * dtv;
        __syncthreads();
#pragma unroll
        for (int k = 0; k < 16; k++) {
            float4 a4 = *(const float4*)&Ms[k * 64 + ty * 4];
            float4 b4 = *(const float4*)&Xs[k * 64 + tx * 4];
            float ar[4] = {a4.x, a4.y, a4.z, a4.w};
            float br[4] = {b4.x, b4.y, b4.z, b4.w};
#pragma unroll
            for (int i = 0; i < 4; i++)
#pragma unroll
                for (int j = 0; j < 4; j++)
                    accA[i][j] = fmaf(ar[i], br[j], accA[i][j]);
        }
        __syncthreads();
    }

    // Phase B: y_off inner product over state dim (reuse Ms as Cs, Xs as Ps)
    for (int n0 = 0; n0 < NST_; n0 += 16) {
        float4 c4 = *(const float4*)&g_conv[(size_t)(c * CH_ + l0 + lr) * CONVD_ +
                                            HID_ + NST_ + n0 + si4];
        Ms[(si4 + 0) * 64 + lr] = c4.x;
        Ms[(si4 + 1) * 64 + lr] = c4.y;
        Ms[(si4 + 2) * 64 + lr] = c4.z;
        Ms[(si4 + 3) * 64 + lr] = c4.w;
        const int pr = tid >> 2;        // 0..63
        float4 pv = *(const float4*)&g_prev[((size_t)(c * NH_ + h)) * HD_ * NST_ +
                                            (size_t)pr * NST_ + n0 + si4];
        Xs[(si4 + 0) * 64 + pr] = pv.x;
        Xs[(si4 + 1) * 64 + pr] = pv.y;
        Xs[(si4 + 2) * 64 + pr] = pv.z;
        Xs[(si4 + 3) * 64 + pr] = pv.w;
        __syncthreads();
#pragma unroll
        for (int k = 0; k < 16; k++) {
            float4 a4 = *(const float4*)&Ms[k * 64 + ty * 4];
            float4 b4 = *(const float4*)&Xs[k * 64 + tx * 4];
            float ar[4] = {a4.x, a4.y, a4.z, a4.w};
            float br[4] = {b4.x, b4.y, b4.z, b4.w};
#pragma unroll
            for (int i = 0; i < 4; i++)
#pragma unroll
                for (int j = 0; j < 4; j++)
                    acc2[i][j] = fmaf(ar[i], br[j], acc2[i][j]);
        }
        __syncthreads();
    }

    // Epilogue: combine + D skip term, write y
    const float dh = Dp[h];
#pragma unroll
    for (int i = 0; i < 4; i++) {
        const int l = l0 + ty * 4 + i;
        const int t = c * CH_ + l;
        const float el = expf(sdAc[l]);
        float4 x4 = *(const float4*)&g_conv[(size_t)t * CONVD_ + h * HD_ + tx * 4];
        float4 out;
        out.x = accA[i][0] + el * acc2[i][0] + x4.x * dh;
        out.y = accA[i][1] + el * acc2[i][1] + x4.y * dh;
        out.z = accA[i][2] + el * acc2[i][2] + x4.z * dh;
        out.w = accA[i][3] + el * acc2[i][3] + x4.w * dh;
        *(float4*)&g_y[(size_t)t * HID_ + h * HD_ + tx * 4] = out;
    }
}

// ---------------------------------------------------------------------------
// y = y * silu(z); RMSNorm(4096) * norm_w   (one block per row)
// ---------------------------------------------------------------------------
__global__ __launch_bounds__(256) void gatenorm_kernel(const float* __restrict__ nw)
{
    const int t = blockIdx.x;
    const int tid = threadIdx.x;
    float vals[16];
    float ss = 0.f;
#pragma unroll
    for (int k = 0; k < 16; k++) {
        const int i = tid + k * 256;
        const float yv = g_y[(size_t)t * HID_ + i];
        const float zv = g_zx[(size_t)t * D_IN_ + i];
        const float v = yv * (zv / (1.f + expf(-zv)));
        vals[k] = v;
        ss += v * v;
    }
    __shared__ float red[8];
#pragma unroll
    for (int o = 16; o > 0; o >>= 1) ss += __shfl_xor_sync(0xffffffffu, ss, o);
    if ((tid & 31) == 0) red[tid >> 5] = ss;
    __syncthreads();
    if (tid < 8) {
        float v = red[tid];
#pragma unroll
        for (int o = 4; o > 0; o >>= 1) v += __shfl_xor_sync(0xffu, v, o);
        if (tid == 0) red[0] = v;
    }
    __syncthreads();
    const float scale = rsqrtf(red[0] / (float)HID_ + 1e-5f);
#pragma unroll
    for (int k = 0; k < 16; k++) {
        const int i = tid + k * 256;
        g_y[(size_t)t * HID_ + i] = vals[k] * scale * nw[i];
    }
}

// ---------------------------------------------------------------------------
extern "C" void kernel_launch(void* const* d_in, const int* in_sizes, int n_in,
                              void* d_out, int out_size)
{
    const float* x       = (const float*)d_in[0];
    const float* in_w    = (const float*)d_in[1];
    const float* conv_w  = (const float*)d_in[2];
    const float* dt_bias = (const float*)d_in[3];
    const float* A_log   = (const float*)d_in[4];
    const float* Dp      = (const float*)d_in[5];
    const float* norm_w  = (const float*)d_in[6];
    const float* out_w   = (const float*)d_in[7];
    float* out = (float*)d_out;

    float *zx, *conv, *cb, *y;
    cudaGetSymbolAddress((void**)&zx, g_zx);
    cudaGetSymbolAddress((void**)&conv, g_conv);
    cudaGetSymbolAddress((void**)&cb, g_CB);
    cudaGetSymbolAddress((void**)&y, g_y);

    // 1) in_proj: [4096 x 8512] = x[4096x2048] @ in_w[8512x2048]^T
    gemm128<<<dim3((D_IN_ + 127) / 128, S_LEN / 128, 1), 256>>>(
        S_LEN, D_IN_, DIM_, x, DIM_, 0, in_w, DIM_, 0, zx, D_IN_, 0);

    // 2) causal conv1d + SiLU
    conv_silu_kernel<<<(S_LEN * CONVD_ + 255) / 256, 256>>>(conv_w);

    // 3) dt / dA
    dt_kernel<<<(S_LEN * NH_ + 255) / 256, 256>>>(dt_bias, A_log);

    // 4) per-chunk inclusive cumsum of dA
    cumsum_kernel<<<dim3(NC_, NH_), CH_>>>();

    // 5) CB[c][l][s] = C·B per chunk (batched via grid.z)
    gemm128<<<dim3(2, 2, NC_), 256>>>(
        CH_, CH_, NST_,
        conv + HID_ + NST_, CONVD_, CH_ * CONVD_,
        conv + HID_,        CONVD_, CH_ * CONVD_,
        cb, CH_, CH_ * CH_);

    // 6) per-chunk states
    states_kernel<<<dim3(NC_, NH_), 256>>>();

    // 7) inter-chunk scan
    chunkscan_kernel<<<(NH_ * HD_ * NST_) / 256, 256>>>();

    // 8) fused y_diag + y_off + D-skip
    ydiag_off_kernel<<<dim3(4, NC_, NH_), 256>>>(Dp);

    // 9) gate + RMSNorm
    gatenorm_kernel<<<S_LEN, 256>>>(norm_w);

    // 10) out_proj: [4096 x 2048] = y[4096x4096] @ out_w[2048x4096]^T
    gemm128<<<dim3(DIM_ / 128, S_LEN / 128, 1), 256>>>(
        S_LEN, DIM_, HID_, y, HID_, 0, out_w, HID_, 0, out, DIM_, 0);
}

// round 5
// speedup vs baseline: 3.2633x; 3.2633x over previous
#include <cuda_runtime.h>
#include <cuda_bf16.h>
#include <stdint.h>
#include <math.h>

// ---------------------------------------------------------------------------
// Mamba2-style SSD block. Round 5: big GEMMs on mma.sync bf16 split-precision
// (tcgen05 is rejected by the harness's ptxas target sm_103 — no 'a' suffix).
// ---------------------------------------------------------------------------

#define S_LEN   4096
#define DIM_    2048
#define HID_    4096
#define D_IN_   8512
#define D_INP_  8576      // padded to 128
#define CONVD_  4352
#define NH_     64
#define HD_     64
#define NST_    128
#define CH_     256
#define NC_     16

// Scratch (device globals; no allocation anywhere).
__device__ float g_zx[(size_t)S_LEN * D_IN_];
__device__ float g_conv[(size_t)S_LEN * CONVD_];
__device__ float g_dt[S_LEN * NH_];
__device__ float g_dAc[S_LEN * NH_];
__device__ float g_CB[NC_ * CH_ * CH_];
__device__ float g_states[NC_ * NH_ * HD_ * NST_];
__device__ float g_prev[NC_ * NH_ * HD_ * NST_];
__device__ float g_y[(size_t)S_LEN * HID_];

// bf16 split-precision operands
__device__ __nv_bfloat16 g_xhi[(size_t)S_LEN * DIM_];
__device__ __nv_bfloat16 g_xlo[(size_t)S_LEN * DIM_];
__device__ __nv_bfloat16 g_wihi[(size_t)D_INP_ * DIM_];
__device__ __nv_bfloat16 g_wilo[(size_t)D_INP_ * DIM_];
__device__ __nv_bfloat16 g_yhi[(size_t)S_LEN * HID_];
__device__ __nv_bfloat16 g_ylo[(size_t)S_LEN * HID_];
__device__ __nv_bfloat16 g_wohi[(size_t)DIM_ * HID_];
__device__ __nv_bfloat16 g_wolo[(size_t)DIM_ * HID_];

// ---------------------------------------------------------------------------
__device__ __forceinline__ uint32_t su32(const void* p) {
    uint32_t a;
    asm("{ .reg .u64 t; cvta.to.shared.u64 t, %1; cvt.u32.u64 %0, t; }"
        : "=r"(a) : "l"(p));
    return a;
}

__device__ __forceinline__ void cpasync16(uint32_t dst, const void* src) {
    asm volatile("cp.async.cg.shared.global [%0], [%1], 16;" :: "r"(dst), "l"(src));
}
#define CP_COMMIT() asm volatile("cp.async.commit_group;" ::: "memory")
#define CP_WAIT2()  asm volatile("cp.async.wait_group 2;" ::: "memory")

#define LDSM4(r, addr) \
    asm volatile("ldmatrix.sync.aligned.m8n8.x4.shared.b16 {%0,%1,%2,%3}, [%4];" \
        : "=r"((r)[0]), "=r"((r)[1]), "=r"((r)[2]), "=r"((r)[3]) : "r"(addr))

#define MMA16816(d, a, b0, b1) \
    asm volatile("mma.sync.aligned.m16n8k16.row.col.f32.bf16.bf16.f32 " \
        "{%0,%1,%2,%3}, {%4,%5,%6,%7}, {%8,%9}, {%0,%1,%2,%3};" \
        : "+f"((d)[0]), "+f"((d)[1]), "+f"((d)[2]), "+f"((d)[3]) \
        : "r"((a)[0]), "r"((a)[1]), "r"((a)[2]), "r"((a)[3]), "r"(b0), "r"(b1))

// ---------------------------------------------------------------------------
// mma.sync split-precision GEMM: C[M,N] = (Ahi+Alo)[M,K] @ (Bhi+Blo)[Npad,K]^T
// (lo*lo dropped). 128x128 CTA tile, BK=32, 3-stage cp.async, 256 threads.
// Warp layout 4(M) x 2(N): each warp 32x64.
// ---------------------------------------------------------------------------
#define PAD_K       40                      // bf16 elems per smem row (80 B)
#define SUB_BYTES   (128 * PAD_K * 2)       // 10240
#define STAGE_BYTES (4 * SUB_BYTES)         // 40960: Ahi, Alo, Bhi, Blo
#define GM_SMEM_TOTAL (3 * STAGE_BYTES)     // 122880

__global__ __launch_bounds__(256, 1) void gemm_mma(
    const __nv_bfloat16* __restrict__ Ahi, const __nv_bfloat16* __restrict__ Alo,
    const __nv_bfloat16* __restrict__ Bhi, const __nv_bfloat16* __restrict__ Blo,
    float* __restrict__ C, int N, int K)
{
    extern __shared__ char smem[];
    const uint32_t sb = su32(smem);
    const int tid = threadIdx.x;
    const int lane = tid & 31;
    const int warp = tid >> 5;
    const int warpM = warp & 3;          // 0..3 -> m offset *32
    const int warpN = warp >> 2;         // 0..1 -> n offset *64
    const int m0 = blockIdx.y * 128, n0 = blockIdx.x * 128;

    float acc[2][8][4];
#pragma unroll
    for (int i = 0; i < 2; i++)
#pragma unroll
        for (int j = 0; j < 8; j++)
#pragma unroll
            for (int v = 0; v < 4; v++) acc[i][j][v] = 0.f;

    auto load_chunk = [&](int i, int s) {
        const size_t k0 = (size_t)i * 32;
#pragma unroll
        for (int t = 0; t < 8; t++) {
            const int idx = t * 256 + tid;
            const int sub = idx >> 9;            // 0..3
            const int r = (idx >> 2) & 127;      // row 0..127
            const int cs = idx & 3;              // 16B segment
            const uint32_t d = sb + s * STAGE_BYTES + sub * SUB_BYTES
                             + (uint32_t)(r * PAD_K + cs * 8) * 2;
            const __nv_bfloat16* bp = (sub == 0) ? Ahi : (sub == 1) ? Alo
                                     : (sub == 2) ? Bhi : Blo;
            const int rg = (sub < 2) ? (m0 + r) : (n0 + r);
            cpasync16(d, bp + (size_t)rg * K + k0 + cs * 8);
        }
    };

    const int nch = K >> 5;
    load_chunk(0, 0); CP_COMMIT();
    load_chunk(1, 1); CP_COMMIT();
    load_chunk(2, 2); CP_COMMIT();

    const int lr = lane & 15;
    const int lc8 = (lane >> 4) * 8;

    for (int i = 0; i < nch; i++) {
        const int s = i % 3;
        CP_WAIT2();
        __syncthreads();

        const uint32_t aB = sb + s * STAGE_BYTES;
        const uint32_t bB = aB + 2 * SUB_BYTES;
#pragma unroll
        for (int k16 = 0; k16 < 2; k16++) {
            const int kof = k16 * 16 + lc8;
            uint32_t ah[2][4], al[2][4];
#pragma unroll
            for (int mt = 0; mt < 2; mt++) {
                const uint32_t ad = aB + (uint32_t)((warpM * 32 + mt * 16 + lr) * PAD_K + kof) * 2;
                LDSM4(ah[mt], ad);
                LDSM4(al[mt], ad + SUB_BYTES);
            }
            uint32_t bh[4][4], bl[4][4];
#pragma unroll
            for (int ng = 0; ng < 4; ng++) {
                const uint32_t bd = bB + (uint32_t)((warpN * 64 + ng * 16 + lr) * PAD_K + kof) * 2;
                LDSM4(bh[ng], bd);
                LDSM4(bl[ng], bd + SUB_BYTES);
            }
#pragma unroll
            for (int mt = 0; mt < 2; mt++)
#pragma unroll
                for (int nt = 0; nt < 8; nt++) {
                    const int ng = nt >> 1, sel = nt & 1;
                    MMA16816(acc[mt][nt], ah[mt], bh[ng][sel], bh[ng][sel + 2]);
                    MMA16816(acc[mt][nt], ah[mt], bl[ng][sel], bl[ng][sel + 2]);
                    MMA16816(acc[mt][nt], al[mt], bh[ng][sel], bh[ng][sel + 2]);
                }
        }
        __syncthreads();
        if (i + 3 < nch) load_chunk(i + 3, s);
        CP_COMMIT();
    }

    // epilogue
#pragma unroll
    for (int mt = 0; mt < 2; mt++) {
        const int row = m0 + warpM * 32 + mt * 16 + (lane >> 2);
#pragma unroll
        for (int nt = 0; nt < 8; nt++) {
            const int col = n0 + warpN * 64 + nt * 8 + (lane & 3) * 2;
            if (col < N) {
                *(float2*)&C[(size_t)row * N + col] =
                    make_float2(acc[mt][nt][0], acc[mt][nt][1]);
                *(float2*)&C[(size_t)(row + 8) * N + col] =
                    make_float2(acc[mt][nt][2], acc[mt][nt][3]);
            }
        }
    }
}

// ---------------------------------------------------------------------------
// fp32 -> (hi, lo) bf16 split; zero-pads rows beyond n4_src.
// ---------------------------------------------------------------------------
__global__ void split_kernel(const float* __restrict__ src,
                             __nv_bfloat16* __restrict__ hi,
                             __nv_bfloat16* __restrict__ lo,
                             int n4_src, int n4_tot)
{
    const int i = blockIdx.x * blockDim.x + threadIdx.x;
    if (i >= n4_tot) return;
    float4 v = make_float4(0.f, 0.f, 0.f, 0.f);
    if (i < n4_src) v = ((const float4*)src)[i];
    __nv_bfloat16 h0 = __float2bfloat16(v.x), h1 = __float2bfloat16(v.y);
    __nv_bfloat16 h2 = __float2bfloat16(v.z), h3 = __float2bfloat16(v.w);
    __nv_bfloat16 l0 = __float2bfloat16(v.x - __bfloat162float(h0));
    __nv_bfloat16 l1 = __float2bfloat16(v.y - __bfloat162float(h1));
    __nv_bfloat16 l2 = __float2bfloat16(v.z - __bfloat162float(h2));
    __nv_bfloat16 l3 = __float2bfloat16(v.w - __bfloat162float(h3));
    ((__nv_bfloat162*)hi)[2 * i]     = __halves2bfloat162(h0, h1);
    ((__nv_bfloat162*)hi)[2 * i + 1] = __halves2bfloat162(h2, h3);
    ((__nv_bfloat162*)lo)[2 * i]     = __halves2bfloat162(l0, l1);
    ((__nv_bfloat162*)lo)[2 * i + 1] = __halves2bfloat162(l2, l3);
}

// ---------------------------------------------------------------------------
// fp32 tiled SGEMM (kept for the small CB batch): C = A @ B^T
// ---------------------------------------------------------------------------
__global__ __launch_bounds__(256) void gemm128(
    int M, int N, int K,
    const float* __restrict__ A, int lda, int strideA,
    const float* __restrict__ B, int ldb, int strideB,
    float* __restrict__ C, int ldc, int strideC)
{
    __shared__ float As[8 * 128];
    __shared__ float Bs[8 * 128];
    const int bz = blockIdx.z;
    A += (size_t)bz * strideA;
    B += (size_t)bz * strideB;
    C += (size_t)bz * strideC;
    const int m0 = blockIdx.y * 128;
    const int n0 = blockIdx.x * 128;
    const int tid = threadIdx.x;
    const int lrow = tid >> 1;
    const int lseg = (tid & 1) * 4;
    const int ty = tid >> 4;
    const int tx = tid & 15;

    float acc[8][8];
#pragma unroll
    for (int i = 0; i < 8; i++)
#pragma unroll
        for (int j = 0; j < 8; j++) acc[i][j] = 0.f;

    const bool bok = (n0 + lrow) < N;
    const float* aptr = A + (size_t)(m0 + lrow) * lda + lseg;
    const float* bptr = B + (size_t)(bok ? (n0 + lrow) : 0) * ldb + lseg;

    for (int k0 = 0; k0 < K; k0 += 8) {
        float4 a4 = *(const float4*)(aptr + k0);
        float4 b4 = make_float4(0.f, 0.f, 0.f, 0.f);
        if (bok) b4 = *(const float4*)(bptr + k0);
        As[(lseg + 0) * 128 + lrow] = a4.x;
        As[(lseg + 1) * 128 + lrow] = a4.y;
        As[(lseg + 2) * 128 + lrow] = a4.z;
        As[(lseg + 3) * 128 + lrow] = a4.w;
        Bs[(lseg + 0) * 128 + lrow] = b4.x;
        Bs[(lseg + 1) * 128 + lrow] = b4.y;
        Bs[(lseg + 2) * 128 + lrow] = b4.z;
        Bs[(lseg + 3) * 128 + lrow] = b4.w;
        __syncthreads();
#pragma unroll
        for (int k = 0; k < 8; k++) {
            float ar[8], br[8];
            *(float4*)&ar[0] = *(const float4*)&As[k * 128 + ty * 8];
            *(float4*)&ar[4] = *(const float4*)&As[k * 128 + ty * 8 + 4];
            *(float4*)&br[0] = *(const float4*)&Bs[k * 128 + tx * 8];
            *(float4*)&br[4] = *(const float4*)&Bs[k * 128 + tx * 8 + 4];
#pragma unroll
            for (int i = 0; i < 8; i++)
#pragma unroll
                for (int j = 0; j < 8; j++)
                    acc[i][j] = fmaf(ar[i], br[j], acc[i][j]);
        }
        __syncthreads();
    }

#pragma unroll
    for (int i = 0; i < 8; i++) {
        const int m = m0 + ty * 8 + i;
#pragma unroll
        for (int j4 = 0; j4 < 8; j4 += 4) {
            const int n = n0 + tx * 8 + j4;
            if (n + 4 <= N) {
                *(float4*)(C + (size_t)m * ldc + n) =
                    make_float4(acc[i][j4], acc[i][j4 + 1], acc[i][j4 + 2], acc[i][j4 + 3]);
            } else {
#pragma unroll
                for (int j = 0; j < 4; j++)
                    if (n + j < N) C[(size_t)m * ldc + n + j] = acc[i][j4 + j];
            }
        }
    }
}

// ---------------------------------------------------------------------------
__global__ void conv_silu_kernel(const float* __restrict__ w)
{
    const int idx = blockIdx.x * blockDim.x + threadIdx.x;
    if (idx >= S_LEN * CONVD_) return;
    const int c = idx % CONVD_;
    const int t = idx / CONVD_;
    float s = 0.f;
#pragma unroll
    for (int i = 0; i < 4; i++) {
        const int tt = t - 3 + i;
        if (tt >= 0) s += g_zx[(size_t)tt * D_IN_ + HID_ + c] * w[c * 4 + i];
    }
    g_conv[idx] = s / (1.f + expf(-s));
}

__global__ void dt_kernel(const float* __restrict__ dt_bias,
                          const float* __restrict__ A_log)
{
    const int idx = blockIdx.x * blockDim.x + threadIdx.x;
    if (idx >= S_LEN * NH_) return;
    const int h = idx % NH_;
    const int t = idx / NH_;
    const float raw = g_zx[(size_t)t * D_IN_ + (HID_ + CONVD_) + h] + dt_bias[h];
    const float dt = (raw > 20.f) ? raw : log1pf(expf(raw));
    g_dt[idx] = dt;
    g_dAc[idx] = dt * (-expf(A_log[h]));
}

__global__ __launch_bounds__(CH_) void cumsum_kernel()
{
    const int c = blockIdx.x, h = blockIdx.y;
    const int l = threadIdx.x;
    __shared__ float sbuf[CH_];
    const int gi = (c * CH_ + l) * NH_ + h;
    sbuf[l] = g_dAc[gi];
    __syncthreads();
    for (int off = 1; off < CH_; off <<= 1) {
        const float add = (l >= off) ? sbuf[l - off] : 0.f;
        __syncthreads();
        sbuf[l] += add;
        __syncthreads();
    }
    g_dAc[gi] = sbuf[l];
}

__global__ __launch_bounds__(256) void states_kernel()
{
    const int c = blockIdx.x, h = blockIdx.y;
    __shared__ float sdecay[CH_];
    __shared__ float Xs[16 * 64];
    __shared__ float Bs[16 * 128];
    const int tid = threadIdx.x;
    const float dalast = g_dAc[(c * CH_ + CH_ - 1) * NH_ + h];
    {
        const int gi = (c * CH_ + tid) * NH_ + h;
        sdecay[tid] = g_dt[gi] * expf(dalast - g_dAc[gi]);
    }
    __syncthreads();
    const int ty = tid >> 4, tx = tid & 15;
    float acc[4][8];
#pragma unroll
    for (int i = 0; i < 4; i++)
#pragma unroll
        for (int j = 0; j < 8; j++) acc[i][j] = 0.f;

    const int sr = tid >> 4;
    const int p4 = (tid & 15) * 4;
    const int n8 = (tid & 15) * 8;

    for (int s0 = 0; s0 < CH_; s0 += 16) {
        const int t = c * CH_ + s0 + sr;
        const float sc = sdecay[s0 + sr];
        float4 x4 = *(const float4*)&g_conv[(size_t)t * CONVD_ + h * HD_ + p4];
        Xs[sr * 64 + p4 + 0] = x4.x * sc;
        Xs[sr * 64 + p4 + 1] = x4.y * sc;
        Xs[sr * 64 + p4 + 2] = x4.z * sc;
        Xs[sr * 64 + p4 + 3] = x4.w * sc;
        float4 b0 = *(const float4*)&g_conv[(size_t)t * CONVD_ + HID_ + n8];
        float4 b1 = *(const float4*)&g_conv[(size_t)t * CONVD_ + HID_ + n8 + 4];
        Bs[sr * 128 + n8 + 0] = b0.x; Bs[sr * 128 + n8 + 1] = b0.y;
        Bs[sr * 128 + n8 + 2] = b0.z; Bs[sr * 128 + n8 + 3] = b0.w;
        Bs[sr * 128 + n8 + 4] = b1.x; Bs[sr * 128 + n8 + 5] = b1.y;
        Bs[sr * 128 + n8 + 6] = b1.z; Bs[sr * 128 + n8 + 7] = b1.w;
        __syncthreads();
#pragma unroll
        for (int k = 0; k < 16; k++) {
            float ar[4], br[8];
            *(float4*)&ar[0] = *(const float4*)&Xs[k * 64 + ty * 4];
            *(float4*)&br[0] = *(const float4*)&Bs[k * 128 + tx * 8];
            *(float4*)&br[4] = *(const float4*)&Bs[k * 128 + tx * 8 + 4];
#pragma unroll
            for (int i = 0; i < 4; i++)
#pragma unroll
                for (int j = 0; j < 8; j++)
                    acc[i][j] = fmaf(ar[i], br[j], acc[i][j]);
        }
        __syncthreads();
    }
    const size_t base = ((size_t)(c * NH_ + h)) * HD_ * NST_;
#pragma unroll
    for (int i = 0; i < 4; i++) {
        const int p = ty * 4 + i;
        *(float4*)&g_states[base + (size_t)p * NST_ + tx * 8] =
            make_float4(acc[i][0], acc[i][1], acc[i][2], acc[i][3]);
        *(float4*)&g_states[base + (size_t)p * NST_ + tx * 8 + 4] =
            make_float4(acc[i][4], acc[i][5], acc[i][6], acc[i][7]);
    }
}

__global__ void chunkscan_kernel()
{
    const int idx = blockIdx.x * blockDim.x + threadIdx.x;
    if (idx >= NH_ * HD_ * NST_) return;
    const int h = idx / (HD_ * NST_);
    const int rem = idx % (HD_ * NST_);
    float carry = 0.f;
#pragma unroll
    for (int c = 0; c < NC_; c++) {
        const size_t off = ((size_t)(c * NH_ + h)) * HD_ * NST_ + rem;
        g_prev[off] = carry;
        const float dec = expf(g_dAc[(c * CH_ + CH_ - 1) * NH_ + h]);
        carry = carry * dec + g_states[off];
    }
}

__global__ __launch_bounds__(256) void ydiag_off_kernel(const float* __restrict__ Dp)
{
    const int lt = blockIdx.x, c = blockIdx.y, h = blockIdx.z;
    __shared__ float sdAc[CH_];
    __shared__ float sdt[CH_];
    __shared__ float Ms[16 * 64];
    __shared__ float Xs[16 * 64];
    const int tid = threadIdx.x;
    {
        const int gi = (c * CH_ + tid) * NH_ + h;
        sdAc[tid] = g_dAc[gi];
        sdt[tid] = g_dt[gi];
    }
    __syncthreads();
    const int ty = tid >> 4, tx = tid & 15;
    const int l0 = lt * 64;
    float accA[4][4], acc2[4][4];
#pragma unroll
    for (int i = 0; i < 4; i++)
#pragma unroll
        for (int j = 0; j < 4; j++) { accA[i][j] = 0.f; acc2[i][j] = 0.f; }

    const int lr = tid >> 2;
    const int si4 = (tid & 3) * 4;
    const int sr = tid >> 4;
    const int p4 = (tid & 15) * 4;

    const int smax = l0 + 64;
    for (int s0 = 0; s0 < smax; s0 += 16) {
        float4 cb4 = *(const float4*)&g_CB[c * (CH_ * CH_) + (l0 + lr) * CH_ + s0 + si4];
        const float dacl = sdAc[l0 + lr];
        float mv[4] = {cb4.x, cb4.y, cb4.z, cb4.w};
#pragma unroll
        for (int j = 0; j < 4; j++) {
            const int sj = s0 + si4 + j;
            float v = 0.f;
            if (sj <= l0 + lr) v = mv[j] * expf(dacl - sdAc[sj]);
            Ms[(si4 + j) * 64 + lr] = v;
        }
        const int t = c * CH_ + s0 + sr;
        const float dtv = sdt[s0 + sr];
        float4 x4 = *(const float4*)&g_conv[(size_t)t * CONVD_ + h * HD_ + p4];
        Xs[sr * 64 + p4 + 0] = x4.x * dtv;
        Xs[sr * 64 + p4 + 1] = x4.y * dtv;
        Xs[sr * 64 + p4 + 2] = x4.z * dtv;
        Xs[sr * 64 + p4 + 3] = x4.w * dtv;
        __syncthreads();
#pragma unroll
        for (int k = 0; k < 16; k++) {
            float4 a4 = *(const float4*)&Ms[k * 64 + ty * 4];
            float4 b4 = *(const float4*)&Xs[k * 64 + tx * 4];
            float ar[4] = {a4.x, a4.y, a4.z, a4.w};
            float br[4] = {b4.x, b4.y, b4.z, b4.w};
#pragma unroll
            for (int i = 0; i < 4; i++)
#pragma unroll
                for (int j = 0; j < 4; j++)
                    accA[i][j] = fmaf(ar[i], br[j], accA[i][j]);
        }
        __syncthreads();
    }

    for (int n0 = 0; n0 < NST_; n0 += 16) {
        float4 c4 = *(const float4*)&g_conv[(size_t)(c * CH_ + l0 + lr) * CONVD_ +
                                            HID_ + NST_ + n0 + si4];
        Ms[(si4 + 0) * 64 + lr] = c4.x;
        Ms[(si4 + 1) * 64 + lr] = c4.y;
        Ms[(si4 + 2) * 64 + lr] = c4.z;
        Ms[(si4 + 3) * 64 + lr] = c4.w;
        const int pr = tid >> 2;
        float4 pv = *(const float4*)&g_prev[((size_t)(c * NH_ + h)) * HD_ * NST_ +
                                            (size_t)pr * NST_ + n0 + si4];
        Xs[(si4 + 0) * 64 + pr] = pv.x;
        Xs[(si4 + 1) * 64 + pr] = pv.y;
        Xs[(si4 + 2) * 64 + pr] = pv.z;
        Xs[(si4 + 3) * 64 + pr] = pv.w;
        __syncthreads();
#pragma unroll
        for (int k = 0; k < 16; k++) {
            float4 a4 = *(const float4*)&Ms[k * 64 + ty * 4];
            float4 b4 = *(const float4*)&Xs[k * 64 + tx * 4];
            float ar[4] = {a4.x, a4.y, a4.z, a4.w};
            float br[4] = {b4.x, b4.y, b4.z, b4.w};
#pragma unroll
            for (int i = 0; i < 4; i++)
#pragma unroll
                for (int j = 0; j < 4; j++)
                    acc2[i][j] = fmaf(ar[i], br[j], acc2[i][j]);
        }
        __syncthreads();
    }

    const float dh = Dp[h];
#pragma unroll
    for (int i = 0; i < 4; i++) {
        const int l = l0 + ty * 4 + i;
        const int t = c * CH_ + l;
        const float el = expf(sdAc[l]);
        float4 x4 = *(const float4*)&g_conv[(size_t)t * CONVD_ + h * HD_ + tx * 4];
        float4 out;
        out.x = accA[i][0] + el * acc2[i][0] + x4.x * dh;
        out.y = accA[i][1] + el * acc2[i][1] + x4.y * dh;
        out.z = accA[i][2] + el * acc2[i][2] + x4.z * dh;
        out.w = accA[i][3] + el * acc2[i][3] + x4.w * dh;
        *(float4*)&g_y[(size_t)t * HID_ + h * HD_ + tx * 4] = out;
    }
}

__global__ __launch_bounds__(256) void gatenorm_kernel(const float* __restrict__ nw)
{
    const int t = blockIdx.x;
    const int tid = threadIdx.x;
    float vals[16];
    float ss = 0.f;
#pragma unroll
    for (int k = 0; k < 16; k++) {
        const int i = tid + k * 256;
        const float yv = g_y[(size_t)t * HID_ + i];
        const float zv = g_zx[(size_t)t * D_IN_ + i];
        const float v = yv * (zv / (1.f + expf(-zv)));
        vals[k] = v;
        ss += v * v;
    }
    __shared__ float red[8];
#pragma unroll
    for (int o = 16; o > 0; o >>= 1) ss += __shfl_xor_sync(0xffffffffu, ss, o);
    if ((tid & 31) == 0) red[tid >> 5] = ss;
    __syncthreads();
    if (tid < 8) {
        float v = red[tid];
#pragma unroll
        for (int o = 4; o > 0; o >>= 1) v += __shfl_xor_sync(0xffu, v, o);
        if (tid == 0) red[0] = v;
    }
    __syncthreads();
    const float scale = rsqrtf(red[0] / (float)HID_ + 1e-5f);
#pragma unroll
    for (int k = 0; k < 16; k++) {
        const int i = tid + k * 256;
        g_y[(size_t)t * HID_ + i] = vals[k] * scale * nw[i];
    }
}

// ---------------------------------------------------------------------------
extern "C" void kernel_launch(void* const* d_in, const int* in_sizes, int n_in,
                              void* d_out, int out_size)
{
    const float* x       = (const float*)d_in[0];
    const float* in_w    = (const float*)d_in[1];
    const float* conv_w  = (const float*)d_in[2];
    const float* dt_bias = (const float*)d_in[3];
    const float* A_log   = (const float*)d_in[4];
    const float* Dp      = (const float*)d_in[5];
    const float* norm_w  = (const float*)d_in[6];
    const float* out_w   = (const float*)d_in[7];
    float* out = (float*)d_out;

    float *zx, *conv, *cb, *y;
    __nv_bfloat16 *xhi, *xlo, *wihi, *wilo, *yhi, *ylo, *wohi, *wolo;
    cudaGetSymbolAddress((void**)&zx, g_zx);
    cudaGetSymbolAddress((void**)&conv, g_conv);
    cudaGetSymbolAddress((void**)&cb, g_CB);
    cudaGetSymbolAddress((void**)&y, g_y);
    cudaGetSymbolAddress((void**)&xhi, g_xhi);
    cudaGetSymbolAddress((void**)&xlo, g_xlo);
    cudaGetSymbolAddress((void**)&wihi, g_wihi);
    cudaGetSymbolAddress((void**)&wilo, g_wilo);
    cudaGetSymbolAddress((void**)&yhi, g_yhi);
    cudaGetSymbolAddress((void**)&ylo, g_ylo);
    cudaGetSymbolAddress((void**)&wohi, g_wohi);
    cudaGetSymbolAddress((void**)&wolo, g_wolo);

    cudaFuncSetAttribute(gemm_mma, cudaFuncAttributeMaxDynamicSharedMemorySize,
                         GM_SMEM_TOTAL);

    // 0) bf16 splits for in_proj operands
    {
        const int n4s = S_LEN * DIM_ / 4;
        split_kernel<<<(n4s + 255) / 256, 256>>>(x, xhi, xlo, n4s, n4s);
        const int n4w = D_IN_ * DIM_ / 4;
        const int n4wt = D_INP_ * DIM_ / 4;
        split_kernel<<<(n4wt + 255) / 256, 256>>>(in_w, wihi, wilo, n4w, n4wt);
    }

    // 1) in_proj: zx[4096 x 8512]
    gemm_mma<<<dim3(D_INP_ / 128, S_LEN / 128), 256, GM_SMEM_TOTAL>>>(
        xhi, xlo, wihi, wilo, zx, D_IN_, DIM_);

    // 2) causal conv1d + SiLU
    conv_silu_kernel<<<(S_LEN * CONVD_ + 255) / 256, 256>>>(conv_w);

    // 3) dt / dA
    dt_kernel<<<(S_LEN * NH_ + 255) / 256, 256>>>(dt_bias, A_log);

    // 4) per-chunk inclusive cumsum of dA
    cumsum_kernel<<<dim3(NC_, NH_), CH_>>>();

    // 5) CB per chunk
    gemm128<<<dim3(2, 2, NC_), 256>>>(
        CH_, CH_, NST_,
        conv + HID_ + NST_, CONVD_, CH_ * CONVD_,
        conv + HID_,        CONVD_, CH_ * CONVD_,
        cb, CH_, CH_ * CH_);

    // 6) per-chunk states
    states_kernel<<<dim3(NC_, NH_), 256>>>();

    // 7) inter-chunk scan
    chunkscan_kernel<<<(NH_ * HD_ * NST_) / 256, 256>>>();

    // 8) fused y_diag + y_off + D-skip
    ydiag_off_kernel<<<dim3(4, NC_, NH_), 256>>>(Dp);

    // 9) gate + RMSNorm
    gatenorm_kernel<<<S_LEN, 256>>>(norm_w);

    // 10) splits for out_proj operands, then out_proj
    {
        const int n4y = S_LEN * HID_ / 4;
        split_kernel<<<(n4y + 255) / 256, 256>>>(y, yhi, ylo, n4y, n4y);
        const int n4o = DIM_ * HID_ / 4;
        split_kernel<<<(n4o + 255) / 256, 256>>>(out_w, wohi, wolo, n4o, n4o);
    }
    gemm_mma<<<dim3(DIM_ / 128, S_LEN / 128), 256, GM_SMEM_TOTAL>>>(
        yhi, ylo, wohi, wolo, out, DIM_, HID_);
}

// round 7
// speedup vs baseline: 3.5872x; 1.0993x over previous
#include <cuda_runtime.h>
#include <cuda_bf16.h>
#include <stdint.h>
#include <math.h>

// ---------------------------------------------------------------------------
// Mamba2-style SSD block. Round 6: states + ydiag also on mma.sync bf16 split;
// y-split fused into gatenorm. Big GEMMs unchanged from Round 5 (2978us).
// ---------------------------------------------------------------------------

#define S_LEN   4096
#define DIM_    2048
#define HID_    4096
#define D_IN_   8512
#define D_INP_  8576
#define CONVD_  4352
#define NH_     64
#define HD_     64
#define NST_    128
#define CH_     256
#define NC_     16

__device__ float g_zx[(size_t)S_LEN * D_IN_];
__device__ float g_conv[(size_t)S_LEN * CONVD_];
__device__ float g_dt[S_LEN * NH_];
__device__ float g_dAc[S_LEN * NH_];
__device__ float g_CB[NC_ * CH_ * CH_];
__device__ float g_states[NC_ * NH_ * HD_ * NST_];
__device__ float g_prev[NC_ * NH_ * HD_ * NST_];
__device__ float g_y[(size_t)S_LEN * HID_];

__device__ __nv_bfloat16 g_xhi[(size_t)S_LEN * DIM_];
__device__ __nv_bfloat16 g_xlo[(size_t)S_LEN * DIM_];
__device__ __nv_bfloat16 g_wihi[(size_t)D_INP_ * DIM_];
__device__ __nv_bfloat16 g_wilo[(size_t)D_INP_ * DIM_];
__device__ __nv_bfloat16 g_yhi[(size_t)S_LEN * HID_];
__device__ __nv_bfloat16 g_ylo[(size_t)S_LEN * HID_];
__device__ __nv_bfloat16 g_wohi[(size_t)DIM_ * HID_];
__device__ __nv_bfloat16 g_wolo[(size_t)DIM_ * HID_];

// ---------------------------------------------------------------------------
__device__ __forceinline__ uint32_t su32(const void* p) {
    uint32_t a;
    asm("{ .reg .u64 t; cvta.to.shared.u64 t, %1; cvt.u32.u64 %0, t; }"
        : "=r"(a) : "l"(p));
    return a;
}

__device__ __forceinline__ void cpasync16(uint32_t dst, const void* src) {
    asm volatile("cp.async.cg.shared.global [%0], [%1], 16;" :: "r"(dst), "l"(src));
}
#define CP_COMMIT() asm volatile("cp.async.commit_group;" ::: "memory")
#define CP_WAIT2()  asm volatile("cp.async.wait_group 2;" ::: "memory")

#define LDSM4(r, addr) \
    asm volatile("ldmatrix.sync.aligned.m8n8.x4.shared.b16 {%0,%1,%2,%3}, [%4];" \
        : "=r"((r)[0]), "=r"((r)[1]), "=r"((r)[2]), "=r"((r)[3]) : "r"(addr))

#define LDSM4T(r, addr) \
    asm volatile("ldmatrix.sync.aligned.m8n8.x4.trans.shared.b16 {%0,%1,%2,%3}, [%4];" \
        : "=r"((r)[0]), "=r"((r)[1]), "=r"((r)[2]), "=r"((r)[3]) : "r"(addr))

#define MMA16816(d, a, b0, b1) \
    asm volatile("mma.sync.aligned.m16n8k16.row.col.f32.bf16.bf16.f32 " \
        "{%0,%1,%2,%3}, {%4,%5,%6,%7}, {%8,%9}, {%0,%1,%2,%3};" \
        : "+f"((d)[0]), "+f"((d)[1]), "+f"((d)[2]), "+f"((d)[3]) \
        : "r"((a)[0]), "r"((a)[1]), "r"((a)[2]), "r"((a)[3]), "r"(b0), "r"(b1))

// fp32x2 -> packed bf16x2 hi + lo
__device__ __forceinline__ void split2(float a, float b, uint32_t& hi, uint32_t& lo) {
    __nv_bfloat16 h0 = __float2bfloat16(a), h1 = __float2bfloat16(b);
    __nv_bfloat16 m0 = __float2bfloat16(a - __bfloat162float(h0));
    __nv_bfloat16 m1 = __float2bfloat16(b - __bfloat162float(h1));
    __nv_bfloat162 H = __halves2bfloat162(h0, h1), L = __halves2bfloat162(m0, m1);
    hi = *(uint32_t*)&H;
    lo = *(uint32_t*)&L;
}

// ---------------------------------------------------------------------------
// mma.sync split-precision GEMM: C = (Ahi+Alo) @ (Bhi+Blo)^T (lo*lo dropped).
// 128x128 CTA, BK=32, 3-stage cp.async, 256 threads, warps 4(M)x2(N).
// ---------------------------------------------------------------------------
#define PAD_K       40
#define SUB_BYTES   (128 * PAD_K * 2)
#define STAGE_BYTES (4 * SUB_BYTES)
#define GM_SMEM_TOTAL (3 * STAGE_BYTES)

__global__ __launch_bounds__(256, 1) void gemm_mma(
    const __nv_bfloat16* __restrict__ Ahi, const __nv_bfloat16* __restrict__ Alo,
    const __nv_bfloat16* __restrict__ Bhi, const __nv_bfloat16* __restrict__ Blo,
    float* __restrict__ C, int N, int K)
{
    extern __shared__ char smem[];
    const uint32_t sb = su32(smem);
    const int tid = threadIdx.x;
    const int lane = tid & 31;
    const int warp = tid >> 5;
    const int warpM = warp & 3;
    const int warpN = warp >> 2;
    const int m0 = blockIdx.y * 128, n0 = blockIdx.x * 128;

    float acc[2][8][4];
#pragma unroll
    for (int i = 0; i < 2; i++)
#pragma unroll
        for (int j = 0; j < 8; j++)
#pragma unroll
            for (int v = 0; v < 4; v++) acc[i][j][v] = 0.f;

    auto load_chunk = [&](int i, int s) {
        const size_t k0 = (size_t)i * 32;
#pragma unroll
        for (int t = 0; t < 8; t++) {
            const int idx = t * 256 + tid;
            const int sub = idx >> 9;
            const int r = (idx >> 2) & 127;
            const int cs = idx & 3;
            const uint32_t d = sb + s * STAGE_BYTES + sub * SUB_BYTES
                             + (uint32_t)(r * PAD_K + cs * 8) * 2;
            const __nv_bfloat16* bp = (sub == 0) ? Ahi : (sub == 1) ? Alo
                                     : (sub == 2) ? Bhi : Blo;
            const int rg = (sub < 2) ? (m0 + r) : (n0 + r);
            cpasync16(d, bp + (size_t)rg * K + k0 + cs * 8);
        }
    };

    const int nch = K >> 5;
    load_chunk(0, 0); CP_COMMIT();
    load_chunk(1, 1); CP_COMMIT();
    load_chunk(2, 2); CP_COMMIT();

    const int lr = lane & 15;
    const int lc8 = (lane >> 4) * 8;

    for (int i = 0; i < nch; i++) {
        const int s = i % 3;
        CP_WAIT2();
        __syncthreads();

        const uint32_t aB = sb + s * STAGE_BYTES;
        const uint32_t bB = aB + 2 * SUB_BYTES;
#pragma unroll
        for (int k16 = 0; k16 < 2; k16++) {
            const int kof = k16 * 16 + lc8;
            uint32_t ah[2][4], al[2][4];
#pragma unroll
            for (int mt = 0; mt < 2; mt++) {
                const uint32_t ad = aB + (uint32_t)((warpM * 32 + mt * 16 + lr) * PAD_K + kof) * 2;
                LDSM4(ah[mt], ad);
                LDSM4(al[mt], ad + SUB_BYTES);
            }
            uint32_t bh[4][4], bl[4][4];
#pragma unroll
            for (int ng = 0; ng < 4; ng++) {
                const uint32_t bd = bB + (uint32_t)((warpN * 64 + ng * 16 + lr) * PAD_K + kof) * 2;
                LDSM4(bh[ng], bd);
                LDSM4(bl[ng], bd + SUB_BYTES);
            }
#pragma unroll
            for (int mt = 0; mt < 2; mt++)
#pragma unroll
                for (int nt = 0; nt < 8; nt++) {
                    const int ng = nt >> 1, sel = nt & 1;
                    MMA16816(acc[mt][nt], ah[mt], bh[ng][sel], bh[ng][sel + 2]);
                    MMA16816(acc[mt][nt], ah[mt], bl[ng][sel], bl[ng][sel + 2]);
                    MMA16816(acc[mt][nt], al[mt], bh[ng][sel], bh[ng][sel + 2]);
                }
        }
        __syncthreads();
        if (i + 3 < nch) load_chunk(i + 3, s);
        CP_COMMIT();
    }

#pragma unroll
    for (int mt = 0; mt < 2; mt++) {
        const int row = m0 + warpM * 32 + mt * 16 + (lane >> 2);
#pragma unroll
        for (int nt = 0; nt < 8; nt++) {
            const int col = n0 + warpN * 64 + nt * 8 + (lane & 3) * 2;
            if (col < N) {
                *(float2*)&C[(size_t)row * N + col] =
                    make_float2(acc[mt][nt][0], acc[mt][nt][1]);
                *(float2*)&C[(size_t)(row + 8) * N + col] =
                    make_float2(acc[mt][nt][2], acc[mt][nt][3]);
            }
        }
    }
}

// ---------------------------------------------------------------------------
__global__ void split_kernel(const float* __restrict__ src,
                             __nv_bfloat16* __restrict__ hi,
                             __nv_bfloat16* __restrict__ lo,
                             int n4_src, int n4_tot)
{
    const int i = blockIdx.x * blockDim.x + threadIdx.x;
    if (i >= n4_tot) return;
    float4 v = make_float4(0.f, 0.f, 0.f, 0.f);
    if (i < n4_src) v = ((const float4*)src)[i];
    uint32_t h0, l0, h1, l1;
    split2(v.x, v.y, h0, l0);
    split2(v.z, v.w, h1, l1);
    ((uint32_t*)hi)[2 * i] = h0;     ((uint32_t*)hi)[2 * i + 1] = h1;
    ((uint32_t*)lo)[2 * i] = l0;     ((uint32_t*)lo)[2 * i + 1] = l1;
}

// ---------------------------------------------------------------------------
// fp32 tiled SGEMM (small CB batch only): C = A @ B^T
// ---------------------------------------------------------------------------
__global__ __launch_bounds__(256) void gemm128(
    int M, int N, int K,
    const float* __restrict__ A, int lda, int strideA,
    const float* __restrict__ B, int ldb, int strideB,
    float* __restrict__ C, int ldc, int strideC)
{
    __shared__ float As[8 * 128];
    __shared__ float Bs[8 * 128];
    const int bz = blockIdx.z;
    A += (size_t)bz * strideA;
    B += (size_t)bz * strideB;
    C += (size_t)bz * strideC;
    const int m0 = blockIdx.y * 128;
    const int n0 = blockIdx.x * 128;
    const int tid = threadIdx.x;
    const int lrow = tid >> 1;
    const int lseg = (tid & 1) * 4;
    const int ty = tid >> 4;
    const int tx = tid & 15;

    float acc[8][8];
#pragma unroll
    for (int i = 0; i < 8; i++)
#pragma unroll
        for (int j = 0; j < 8; j++) acc[i][j] = 0.f;

    const float* aptr = A + (size_t)(m0 + lrow) * lda + lseg;
    const float* bptr = B + (size_t)(n0 + lrow) * ldb + lseg;

    for (int k0 = 0; k0 < K; k0 += 8) {
        float4 a4 = *(const float4*)(aptr + k0);
        float4 b4 = *(const float4*)(bptr + k0);
        As[(lseg + 0) * 128 + lrow] = a4.x;
        As[(lseg + 1) * 128 + lrow] = a4.y;
        As[(lseg + 2) * 128 + lrow] = a4.z;
        As[(lseg + 3) * 128 + lrow] = a4.w;
        Bs[(lseg + 0) * 128 + lrow] = b4.x;
        Bs[(lseg + 1) * 128 + lrow] = b4.y;
        Bs[(lseg + 2) * 128 + lrow] = b4.z;
        Bs[(lseg + 3) * 128 + lrow] = b4.w;
        __syncthreads();
#pragma unroll
        for (int k = 0; k < 8; k++) {
            float ar[8], br[8];
            *(float4*)&ar[0] = *(const float4*)&As[k * 128 + ty * 8];
            *(float4*)&ar[4] = *(const float4*)&As[k * 128 + ty * 8 + 4];
            *(float4*)&br[0] = *(const float4*)&Bs[k * 128 + tx * 8];
            *(float4*)&br[4] = *(const float4*)&Bs[k * 128 + tx * 8 + 4];
#pragma unroll
            for (int i = 0; i < 8; i++)
#pragma unroll
                for (int j = 0; j < 8; j++)
                    acc[i][j] = fmaf(ar[i], br[j], acc[i][j]);
        }
        __syncthreads();
    }

#pragma unroll
    for (int i = 0; i < 8; i++) {
        const int m = m0 + ty * 8 + i;
#pragma unroll
        for (int j4 = 0; j4 < 8; j4 += 4) {
            const int n = n0 + tx * 8 + j4;
            *(float4*)(C + (size_t)m * ldc + n) =
                make_float4(acc[i][j4], acc[i][j4 + 1], acc[i][j4 + 2], acc[i][j4 + 3]);
        }
    }
}

// ---------------------------------------------------------------------------
__global__ void conv_silu_kernel(const float* __restrict__ w)
{
    const int idx = blockIdx.x * blockDim.x + threadIdx.x;
    if (idx >= S_LEN * CONVD_) return;
    const int c = idx % CONVD_;
    const int t = idx / CONVD_;
    float s = 0.f;
#pragma unroll
    for (int i = 0; i < 4; i++) {
        const int tt = t - 3 + i;
        if (tt >= 0) s += g_zx[(size_t)tt * D_IN_ + HID_ + c] * w[c * 4 + i];
    }
    g_conv[idx] = s / (1.f + expf(-s));
}

__global__ void dt_kernel(const float* __restrict__ dt_bias,
                          const float* __restrict__ A_log)
{
    const int idx = blockIdx.x * blockDim.x + threadIdx.x;
    if (idx >= S_LEN * NH_) return;
    const int h = idx % NH_;
    const int t = idx / NH_;
    const float raw = g_zx[(size_t)t * D_IN_ + (HID_ + CONVD_) + h] + dt_bias[h];
    const float dt = (raw > 20.f) ? raw : log1pf(expf(raw));
    g_dt[idx] = dt;
    g_dAc[idx] = dt * (-expf(A_log[h]));
}

__global__ __launch_bounds__(CH_) void cumsum_kernel()
{
    const int c = blockIdx.x, h = blockIdx.y;
    const int l = threadIdx.x;
    __shared__ float sbuf[CH_];
    const int gi = (c * CH_ + l) * NH_ + h;
    sbuf[l] = g_dAc[gi];
    __syncthreads();
    for (int off = 1; off < CH_; off <<= 1) {
        const float add = (l >= off) ? sbuf[l - off] : 0.f;
        __syncthreads();
        sbuf[l] += add;
        __syncthreads();
    }
    g_dAc[gi] = sbuf[l];
}

// ---------------------------------------------------------------------------
// states via mma.sync split bf16:
// states[c][h][p][n] = sum_l (x[l,p]*dt[l]*exp(dAlast-dAc[l])) * B[l,n]
// A[m=p][k=l] from smem [l][p] via ldmatrix.trans; B[n][k=l] from [l][n] trans.
// ---------------------------------------------------------------------------
__global__ __launch_bounds__(256) void states_mma()
{
    const int c = blockIdx.x, h = blockIdx.y;
    __shared__ float sdec[CH_];
    __shared__ __nv_bfloat16 sA[2][32 * 72];    // [l][p], pad 8
    __shared__ __nv_bfloat16 sB[2][32 * 136];   // [l][n], pad 8
    const int tid = threadIdx.x;
    const int lane = tid & 31, warp = tid >> 5;
    const int warpM = warp & 1, warpN = warp >> 1;   // 2(M=p:32) x 4(N=n:32)

    {
        const float dalast = g_dAc[(c * CH_ + CH_ - 1) * NH_ + h];
        const int gi = (c * CH_ + tid) * NH_ + h;
        sdec[tid] = g_dt[gi] * expf(dalast - g_dAc[gi]);
    }
    __syncthreads();

    float acc[2][4][4];
#pragma unroll
    for (int i = 0; i < 2; i++)
#pragma unroll
        for (int j = 0; j < 4; j++)
#pragma unroll
            for (int v = 0; v < 4; v++) acc[i][j][v] = 0.f;

    const int krA = (lane & 7) | ((lane >> 4) << 3);          // A trans k-row
    const int mbA = ((lane >> 3) & 1) * 8;                    // A trans m-offset bit
    const int krB = (lane & 7) | (((lane >> 3) & 1) << 3);    // B trans k-row
    const int nbB = (lane >> 4) * 8;                          // B trans n-offset bit

    for (int s0 = 0; s0 < CH_; s0 += 32) {
        // A: x * w, 32 rows x 64 p
#pragma unroll
        for (int t = 0; t < 2; t++) {
            const int gi = t * 256 + tid;
            const int row = gi >> 4, p4 = (gi & 15) * 4;
            const float wv = sdec[s0 + row];
            float4 v = *(const float4*)&g_conv[(size_t)(c * CH_ + s0 + row) * CONVD_ + h * HD_ + p4];
            uint32_t h0, l0, h1, l1;
            split2(v.x * wv, v.y * wv, h0, l0);
            split2(v.z * wv, v.w * wv, h1, l1);
            uint32_t* dh_ = (uint32_t*)&sA[0][row * 72 + p4];
            uint32_t* dl_ = (uint32_t*)&sA[1][row * 72 + p4];
            dh_[0] = h0; dh_[1] = h1; dl_[0] = l0; dl_[1] = l1;
        }
        // B: 32 rows x 128 n
#pragma unroll
        for (int t = 0; t < 4; t++) {
            const int gi = t * 256 + tid;
            const int row = gi >> 5, n4 = (gi & 31) * 4;
            float4 v = *(const float4*)&g_conv[(size_t)(c * CH_ + s0 + row) * CONVD_ + HID_ + n4];
            uint32_t h0, l0, h1, l1;
            split2(v.x, v.y, h0, l0);
            split2(v.z, v.w, h1, l1);
            uint32_t* dh_ = (uint32_t*)&sB[0][row * 136 + n4];
            uint32_t* dl_ = (uint32_t*)&sB[1][row * 136 + n4];
            dh_[0] = h0; dh_[1] = h1; dl_[0] = l0; dl_[1] = l1;
        }
        __syncthreads();
#pragma unroll
        for (int k16 = 0; k16 < 2; k16++) {
            uint32_t ah[2][4], al[2][4];
#pragma unroll
            for (int mt = 0; mt < 2; mt++) {
                const int mc = warpM * 32 + mt * 16 + mbA;
                const uint32_t ad = su32(&sA[0][(k16 * 16 + krA) * 72 + mc]);
                LDSM4T(ah[mt], ad);
                LDSM4T(al[mt], ad + 32 * 72 * 2);
            }
            uint32_t bh[4][2], bl[4][2];
#pragma unroll
            for (int nh2 = 0; nh2 < 2; nh2++) {
                const int nc = warpN * 32 + nh2 * 16 + nbB;
                uint32_t r[4];
                const uint32_t bd = su32(&sB[0][(k16 * 16 + krB) * 136 + nc]);
                LDSM4T(r, bd);
                bh[nh2 * 2][0] = r[0]; bh[nh2 * 2][1] = r[1];
                bh[nh2 * 2 + 1][0] = r[2]; bh[nh2 * 2 + 1][1] = r[3];
                LDSM4T(r, bd + 32 * 136 * 2);
                bl[nh2 * 2][0] = r[0]; bl[nh2 * 2][1] = r[1];
                bl[nh2 * 2 + 1][0] = r[2]; bl[nh2 * 2 + 1][1] = r[3];
            }
#pragma unroll
            for (int mt = 0; mt < 2; mt++)
#pragma unroll
                for (int ng = 0; ng < 4; ng++) {
                    MMA16816(acc[mt][ng], ah[mt], bh[ng][0], bh[ng][1]);
                    MMA16816(acc[mt][ng], ah[mt], bl[ng][0], bl[ng][1]);
                    MMA16816(acc[mt][ng], al[mt], bh[ng][0], bh[ng][1]);
                }
        }
        __syncthreads();
    }

    const size_t base = ((size_t)(c * NH_ + h)) * HD_ * NST_;
#pragma unroll
    for (int mt = 0; mt < 2; mt++) {
        const int row = warpM * 32 + mt * 16 + (lane >> 2);
#pragma unroll
        for (int ng = 0; ng < 4; ng++) {
            const int col = warpN * 32 + ng * 8 + (lane & 3) * 2;
            *(float2*)&g_states[base + (size_t)row * NST_ + col] =
                make_float2(acc[mt][ng][0], acc[mt][ng][1]);
            *(float2*)&g_states[base + (size_t)(row + 8) * NST_ + col] =
                make_float2(acc[mt][ng][2], acc[mt][ng][3]);
        }
    }
}

__global__ void chunkscan_kernel()
{
    const int idx = blockIdx.x * blockDim.x + threadIdx.x;
    if (idx >= NH_ * HD_ * NST_) return;
    const int h = idx / (HD_ * NST_);
    const int rem = idx % (HD_ * NST_);
    float carry = 0.f;
#pragma unroll
    for (int c = 0; c < NC_; c++) {
        const size_t off = ((size_t)(c * NH_ + h)) * HD_ * NST_ + rem;
        g_prev[off] = carry;
        const float dec = expf(g_dAc[(c * CH_ + CH_ - 1) * NH_ + h]);
        carry = carry * dec + g_states[off];
    }
}

// ---------------------------------------------------------------------------
// ydiag via mma.sync split bf16, two phases:
//  A: C1[l,p] = sum_s M[l,s]*xdt[s,p],  M = mask*exp(dacl-dacs)*CB
//  B: C2[l,p] = sum_n C[l,n]*prev[p,n]; y = C1 + exp(dacl)*C2 + D*x
// ---------------------------------------------------------------------------
// smem elem offsets in sbuf (bf16):
#define YD_MH 0
#define YD_ML 2560          // 64*40
#define YD_XH 5120
#define YD_XL 7424          // +32*72
#define YD_CH 0
#define YD_CL 4608          // 64*72
#define YD_PH 9216
#define YD_PL 13824

__global__ __launch_bounds__(256) void ydiag_mma(const float* __restrict__ Dp)
{
    const int lt = blockIdx.x, c = blockIdx.y, h = blockIdx.z;
    __shared__ float sdAc[CH_], sdtv[CH_];
    __shared__ __nv_bfloat16 sbuf[18432];
    const int tid = threadIdx.x;
    const int lane = tid & 31, warp = tid >> 5;
    const int warpM = warp & 1, warpN = warp >> 1;    // 2(M=l:32) x 4(N=p:16)
    const int l0 = lt * 64;

    {
        const int gi = (c * CH_ + tid) * NH_ + h;
        sdAc[tid] = g_dAc[gi];
        sdtv[tid] = g_dt[gi];
    }
    __syncthreads();

    float accA[2][2][4], acc2[2][2][4];
#pragma unroll
    for (int i = 0; i < 2; i++)
#pragma unroll
        for (int j = 0; j < 2; j++)
#pragma unroll
            for (int v = 0; v < 4; v++) { accA[i][j][v] = 0.f; acc2[i][j][v] = 0.f; }

    const int lr = lane & 15;
    const int lc8 = (lane >> 4) * 8;
    const int krB = (lane & 7) | (((lane >> 3) & 1) << 3);
    const int nbB = (lane >> 4) * 8;

    // ---- Phase A ----
    const int smax = l0 + 64;
    for (int s0 = 0; s0 < smax; s0 += 32) {
        // build M [64 l][32 s]
        {
            const int lrow = tid >> 2;
            const int sseg = (tid & 3) * 8;
            const float dacl = sdAc[l0 + lrow];
            const float* cbp = &g_CB[c * (CH_ * CH_) + (l0 + lrow) * CH_ + s0 + sseg];
            float4 cb0 = *(const float4*)cbp;
            float4 cb1 = *(const float4*)(cbp + 4);
            float cbv[8] = {cb0.x, cb0.y, cb0.z, cb0.w, cb1.x, cb1.y, cb1.z, cb1.w};
#pragma unroll
            for (int j = 0; j < 8; j++) {
                const int s = s0 + sseg + j;
                float v = 0.f;
                if (s <= l0 + lrow) v = cbv[j] * expf(dacl - sdAc[s]);
                const __nv_bfloat16 hv = __float2bfloat16(v);
                sbuf[YD_MH + lrow * 40 + sseg + j] = hv;
                sbuf[YD_ML + lrow * 40 + sseg + j] =
                    __float2bfloat16(v - __bfloat162float(hv));
            }
        }
        // load X*dt [32 s][64 p]
#pragma unroll
        for (int t = 0; t < 2; t++) {
            const int gi = t * 256 + tid;
            const int row = gi >> 4, p4 = (gi & 15) * 4;
            const float wv = sdtv[s0 + row];
            float4 v = *(const float4*)&g_conv[(size_t)(c * CH_ + s0 + row) * CONVD_ + h * HD_ + p4];
            uint32_t h0, lo0, h1, lo1;
            split2(v.x * wv, v.y * wv, h0, lo0);
            split2(v.z * wv, v.w * wv, h1, lo1);
            uint32_t* dh_ = (uint32_t*)&sbuf[YD_XH + row * 72 + p4];
            uint32_t* dl_ = (uint32_t*)&sbuf[YD_XL + row * 72 + p4];
            dh_[0] = h0; dh_[1] = h1; dl_[0] = lo0; dl_[1] = lo1;
        }
        __syncthreads();
#pragma unroll
        for (int k16 = 0; k16 < 2; k16++) {
            uint32_t ah[2][4], al[2][4];
#pragma unroll
            for (int mt = 0; mt < 2; mt++) {
                const uint32_t ad = su32(
                    &sbuf[YD_MH + (warpM * 32 + mt * 16 + lr) * 40 + k16 * 16 + lc8]);
                LDSM4(ah[mt], ad);
                LDSM4(al[mt], ad + YD_ML * 2);
            }
            uint32_t bh[2][2], bl[2][2];
            {
                const int nc = warpN * 16 + nbB;
                uint32_t r[4];
                const uint32_t bd = su32(&sbuf[YD_XH + (k16 * 16 + krB) * 72 + nc]);
                LDSM4T(r, bd);
                bh[0][0] = r[0]; bh[0][1] = r[1]; bh[1][0] = r[2]; bh[1][1] = r[3];
                LDSM4T(r, bd + (YD_XL - YD_XH) * 2);
                bl[0][0] = r[0]; bl[0][1] = r[1]; bl[1][0] = r[2]; bl[1][1] = r[3];
            }
#pragma unroll
            for (int mt = 0; mt < 2; mt++)
#pragma unroll
                for (int ng = 0; ng < 2; ng++) {
                    MMA16816(accA[mt][ng], ah[mt], bh[ng][0], bh[ng][1]);
                    MMA16816(accA[mt][ng], ah[mt], bl[ng][0], bl[ng][1]);
                    MMA16816(accA[mt][ng], al[mt], bh[ng][0], bh[ng][1]);
                }
        }
        __syncthreads();
    }

    // ---- Phase B ----
    const size_t pbase = ((size_t)(c * NH_ + h)) * HD_ * NST_;
    for (int n0c = 0; n0c < NST_; n0c += 64) {
        // C tile [64 l][64 n] and prev tile [64 p][64 n]
#pragma unroll
        for (int t = 0; t < 4; t++) {
            const int gi = t * 256 + tid;
            const int row = gi >> 4, n4 = (gi & 15) * 4;
            float4 v = *(const float4*)&g_conv[(size_t)(c * CH_ + l0 + row) * CONVD_ +
                                               HID_ + NST_ + n0c + n4];
            uint32_t h0, lo0, h1, lo1;
            split2(v.x, v.y, h0, lo0);
            split2(v.z, v.w, h1, lo1);
            uint32_t* dh_ = (uint32_t*)&sbuf[YD_CH + row * 72 + n4];
            uint32_t* dl_ = (uint32_t*)&sbuf[YD_CL + row * 72 + n4];
            dh_[0] = h0; dh_[1] = h1; dl_[0] = lo0; dl_[1] = lo1;

            float4 p = *(const float4*)&g_prev[pbase + (size_t)row * NST_ + n0c + n4];
            split2(p.x, p.y, h0, lo0);
            split2(p.z, p.w, h1, lo1);
            uint32_t* ph_ = (uint32_t*)&sbuf[YD_PH + row * 72 + n4];
            uint32_t* pl_ = (uint32_t*)&sbuf[YD_PL + row * 72 + n4];
            ph_[0] = h0; ph_[1] = h1; pl_[0] = lo0; pl_[1] = lo1;
        }
        __syncthreads();
#pragma unroll
        for (int k16 = 0; k16 < 4; k16++) {
            uint32_t ah[2][4], al[2][4];
#pragma unroll
            for (int mt = 0; mt < 2; mt++) {
                const uint32_t ad = su32(
                    &sbuf[YD_CH + (warpM * 32 + mt * 16 + lr) * 72 + k16 * 16 + lc8]);
                LDSM4(ah[mt], ad);
                LDSM4(al[mt], ad + YD_CL * 2);
            }
            uint32_t bh[4], bl[4];
            {
                const uint32_t bd = su32(
                    &sbuf[YD_PH + (warpN * 16 + lr) * 72 + k16 * 16 + lc8]);
                LDSM4(bh, bd);
                LDSM4(bl, bd + (YD_PL - YD_PH) * 2);
            }
#pragma unroll
            for (int mt = 0; mt < 2; mt++)
#pragma unroll
                for (int ng = 0; ng < 2; ng++) {
                    MMA16816(acc2[mt][ng], ah[mt], bh[ng], bh[ng + 2]);
                    MMA16816(acc2[mt][ng], ah[mt], bl[ng], bl[ng + 2]);
                    MMA16816(acc2[mt][ng], al[mt], bh[ng], bh[ng + 2]);
                }
        }
        __syncthreads();
    }

    // ---- epilogue ----
    const float dh = Dp[h];
#pragma unroll
    for (int mt = 0; mt < 2; mt++) {
        const int lrow = warpM * 32 + mt * 16 + (lane >> 2);
#pragma unroll
        for (int ng = 0; ng < 2; ng++) {
            const int col = warpN * 16 + ng * 8 + (lane & 3) * 2;
#pragma unroll
            for (int half = 0; half < 2; half++) {
                const int l = l0 + lrow + half * 8;
                const int t = c * CH_ + l;
                const float el = expf(sdAc[l]);
                const float2 x2 = *(const float2*)&g_conv[(size_t)t * CONVD_ + h * HD_ + col];
                float2 o;
                o.x = accA[mt][ng][half * 2]     + el * acc2[mt][ng][half * 2]     + x2.x * dh;
                o.y = accA[mt][ng][half * 2 + 1] + el * acc2[mt][ng][half * 2 + 1] + x2.y * dh;
                *(float2*)&g_y[(size_t)t * HID_ + h * HD_ + col] = o;
            }
        }
    }
}

// ---------------------------------------------------------------------------
// gate + RMSNorm, fused bf16 hi/lo split output for out_proj
// ---------------------------------------------------------------------------
__global__ __launch_bounds__(256) void gatenorm_kernel(const float* __restrict__ nw)
{
    const int t = blockIdx.x;
    const int tid = threadIdx.x;
    float vals[16];
    float ss = 0.f;
#pragma unroll
    for (int k = 0; k < 16; k++) {
        const int i = tid + k * 256;
        const float yv = g_y[(size_t)t * HID_ + i];
        const float zv = g_zx[(size_t)t * D_IN_ + i];
        const float v = yv * (zv / (1.f + expf(-zv)));
        vals[k] = v;
        ss += v * v;
    }
    __shared__ float red[8];
#pragma unroll
    for (int o = 16; o > 0; o >>= 1) ss += __shfl_xor_sync(0xffffffffu, ss, o);
    if ((tid & 31) == 0) red[tid >> 5] = ss;
    __syncthreads();
    if (tid < 8) {
        float v = red[tid];
#pragma unroll
        for (int o = 4; o > 0; o >>= 1) v += __shfl_xor_sync(0xffu, v, o);
        if (tid == 0) red[0] = v;
    }
    __syncthreads();
    const float scale = rsqrtf(red[0] / (float)HID_ + 1e-5f);
#pragma unroll
    for (int k = 0; k < 16; k++) {
        const int i = tid + k * 256;
        const float v = vals[k] * scale * nw[i];
        const __nv_bfloat16 hv = __float2bfloat16(v);
        g_yhi[(size_t)t * HID_ + i] = hv;
        g_ylo[(size_t)t * HID_ + i] = __float2bfloat16(v - __bfloat162float(hv));
    }
}

// ---------------------------------------------------------------------------
extern "C" void kernel_launch(void* const* d_in, const int* in_sizes, int n_in,
                              void* d_out, int out_size)
{
    const float* x       = (const float*)d_in[0];
    const float* in_w    = (const float*)d_in[1];
    const float* conv_w  = (const float*)d_in[2];
    const float* dt_bias = (const float*)d_in[3];
    const float* A_log   = (const float*)d_in[4];
    const float* Dp      = (const float*)d_in[5];
    const float* norm_w  = (const float*)d_in[6];
    const float* out_w   = (const float*)d_in[7];
    float* out = (float*)d_out;

    float *zx, *conv, *cb;
    __nv_bfloat16 *xhi, *xlo, *wihi, *wilo, *yhi, *ylo, *wohi, *wolo;
    cudaGetSymbolAddress((void**)&zx, g_zx);
    cudaGetSymbolAddress((void**)&conv, g_conv);
    cudaGetSymbolAddress((void**)&cb, g_CB);
    cudaGetSymbolAddress((void**)&xhi, g_xhi);
    cudaGetSymbolAddress((void**)&xlo, g_xlo);
    cudaGetSymbolAddress((void**)&wihi, g_wihi);
    cudaGetSymbolAddress((void**)&wilo, g_wilo);
    cudaGetSymbolAddress((void**)&yhi, g_yhi);
    cudaGetSymbolAddress((void**)&ylo, g_ylo);
    cudaGetSymbolAddress((void**)&wohi, g_wohi);
    cudaGetSymbolAddress((void**)&wolo, g_wolo);

    cudaFuncSetAttribute(gemm_mma, cudaFuncAttributeMaxDynamicSharedMemorySize,
                         GM_SMEM_TOTAL);

    // 0) bf16 splits for in_proj operands
    {
        const int n4s = S_LEN * DIM_ / 4;
        split_kernel<<<(n4s + 255) / 256, 256>>>(x, xhi, xlo, n4s, n4s);
        const int n4w = D_IN_ * DIM_ / 4;
        const int n4wt = D_INP_ * DIM_ / 4;
        split_kernel<<<(n4wt + 255) / 256, 256>>>(in_w, wihi, wilo, n4w, n4wt);
    }

    // 1) in_proj
    gemm_mma<<<dim3(D_INP_ / 128, S_LEN / 128), 256, GM_SMEM_TOTAL>>>(
        xhi, xlo, wihi, wilo, zx, D_IN_, DIM_);

    // 2) conv1d + SiLU
    conv_silu_kernel<<<(S_LEN * CONVD_ + 255) / 256, 256>>>(conv_w);

    // 3) dt / dA
    dt_kernel<<<(S_LEN * NH_ + 255) / 256, 256>>>(dt_bias, A_log);

    // 4) cumsum
    cumsum_kernel<<<dim3(NC_, NH_), CH_>>>();

    // 5) CB per chunk
    gemm128<<<dim3(2, 2, NC_), 256>>>(
        CH_, CH_, NST_,
        conv + HID_ + NST_, CONVD_, CH_ * CONVD_,
        conv + HID_,        CONVD_, CH_ * CONVD_,
        cb, CH_, CH_ * CH_);

    // 6) states (mma)
    states_mma<<<dim3(NC_, NH_), 256>>>();

    // 7) inter-chunk scan
    chunkscan_kernel<<<(NH_ * HD_ * NST_) / 256, 256>>>();

    // 8) y_diag + y_off + D-skip (mma)
    ydiag_mma<<<dim3(4, NC_, NH_), 256>>>(Dp);

    // 9) gate + RMSNorm (+ fused y split)
    gatenorm_kernel<<<S_LEN, 256>>>(norm_w);

    // 10) out_proj (weight split + gemm)
    {
        const int n4o = DIM_ * HID_ / 4;
        split_kernel<<<(n4o + 255) / 256, 256>>>(out_w, wohi, wolo, n4o, n4o);
    }
    gemm_mma<<<dim3(DIM_ / 128, S_LEN / 128), 256, GM_SMEM_TOTAL>>>(
        yhi, ylo, wohi, wolo, out, DIM_, HID_);
}

// round 8
// speedup vs baseline: 4.7362x; 1.3203x over previous
#include <cuda_runtime.h>
#include <cuda_bf16.h>
#include <cuda_fp16.h>
#include <stdint.h>
#include <math.h>

// ---------------------------------------------------------------------------
// Mamba2-style SSD block. Round 7: big GEMMs switch to 2-pass fp16 split
// (A = hi+lo fp16, B rounded to fp16) — cuts smem-crossbar traffic ~1.45x.
// Fast-math __expf in mid-section. states/ydiag stay bf16 3-pass (R6).
// ---------------------------------------------------------------------------

#define S_LEN   4096
#define DIM_    2048
#define HID_    4096
#define D_IN_   8512
#define D_INP_  8576
#define CONVD_  4352
#define NH_     64
#define HD_     64
#define NST_    128
#define CH_     256
#define NC_     16

__device__ float g_zx[(size_t)S_LEN * D_IN_];
__device__ float g_conv[(size_t)S_LEN * CONVD_];
__device__ float g_dt[S_LEN * NH_];
__device__ float g_dAc[S_LEN * NH_];
__device__ float g_CB[NC_ * CH_ * CH_];
__device__ float g_states[NC_ * NH_ * HD_ * NST_];
__device__ float g_prev[NC_ * NH_ * HD_ * NST_];
__device__ float g_y[(size_t)S_LEN * HID_];

// fp16 split-precision operands
__device__ __half g_xhi[(size_t)S_LEN * DIM_];
__device__ __half g_xlo[(size_t)S_LEN * DIM_];
__device__ __half g_wih[(size_t)D_INP_ * DIM_];
__device__ __half g_yhi[(size_t)S_LEN * HID_];
__device__ __half g_ylo[(size_t)S_LEN * HID_];
__device__ __half g_woh[(size_t)DIM_ * HID_];

// ---------------------------------------------------------------------------
__device__ __forceinline__ uint32_t su32(const void* p) {
    uint32_t a;
    asm("{ .reg .u64 t; cvta.to.shared.u64 t, %1; cvt.u32.u64 %0, t; }"
        : "=r"(a) : "l"(p));
    return a;
}

__device__ __forceinline__ void cpasync16(uint32_t dst, const void* src) {
    asm volatile("cp.async.cg.shared.global [%0], [%1], 16;" :: "r"(dst), "l"(src));
}
#define CP_COMMIT() asm volatile("cp.async.commit_group;" ::: "memory")
#define CP_WAIT2()  asm volatile("cp.async.wait_group 2;" ::: "memory")

#define LDSM4(r, addr) \
    asm volatile("ldmatrix.sync.aligned.m8n8.x4.shared.b16 {%0,%1,%2,%3}, [%4];" \
        : "=r"((r)[0]), "=r"((r)[1]), "=r"((r)[2]), "=r"((r)[3]) : "r"(addr))

#define LDSM4T(r, addr) \
    asm volatile("ldmatrix.sync.aligned.m8n8.x4.trans.shared.b16 {%0,%1,%2,%3}, [%4];" \
        : "=r"((r)[0]), "=r"((r)[1]), "=r"((r)[2]), "=r"((r)[3]) : "r"(addr))

// bf16 mma (mid-section kernels)
#define MMA16816(d, a, b0, b1) \
    asm volatile("mma.sync.aligned.m16n8k16.row.col.f32.bf16.bf16.f32 " \
        "{%0,%1,%2,%3}, {%4,%5,%6,%7}, {%8,%9}, {%0,%1,%2,%3};" \
        : "+f"((d)[0]), "+f"((d)[1]), "+f"((d)[2]), "+f"((d)[3]) \
        : "r"((a)[0]), "r"((a)[1]), "r"((a)[2]), "r"((a)[3]), "r"(b0), "r"(b1))

// fp16 mma (big GEMMs)
#define MMA16816H(d, a, b0, b1) \
    asm volatile("mma.sync.aligned.m16n8k16.row.col.f32.f16.f16.f32 " \
        "{%0,%1,%2,%3}, {%4,%5,%6,%7}, {%8,%9}, {%0,%1,%2,%3};" \
        : "+f"((d)[0]), "+f"((d)[1]), "+f"((d)[2]), "+f"((d)[3]) \
        : "r"((a)[0]), "r"((a)[1]), "r"((a)[2]), "r"((a)[3]), "r"(b0), "r"(b1))

// fp32x2 -> packed bf16x2 hi + lo (mid-section)
__device__ __forceinline__ void split2(float a, float b, uint32_t& hi, uint32_t& lo) {
    __nv_bfloat16 h0 = __float2bfloat16(a), h1 = __float2bfloat16(b);
    __nv_bfloat16 m0 = __float2bfloat16(a - __bfloat162float(h0));
    __nv_bfloat16 m1 = __float2bfloat16(b - __bfloat162float(h1));
    __nv_bfloat162 H = __halves2bfloat162(h0, h1), L = __halves2bfloat162(m0, m1);
    hi = *(uint32_t*)&H;
    lo = *(uint32_t*)&L;
}

// fp32x2 -> packed fp16x2 hi + lo
__device__ __forceinline__ void split2h(float a, float b, uint32_t& hi, uint32_t& lo) {
    __half h0 = __float2half_rn(a), h1 = __float2half_rn(b);
    __half m0 = __float2half_rn(a - __half2float(h0));
    __half m1 = __float2half_rn(b - __half2float(h1));
    __half2 H = __halves2half2(h0, h1), L = __halves2half2(m0, m1);
    hi = *(uint32_t*)&H;
    lo = *(uint32_t*)&L;
}

// ---------------------------------------------------------------------------
// fp16 2-pass split GEMM: C[M,N] = (Ahi+Alo)[M,K] @ Bh[Npad,K]^T
// 128x128 CTA, BK=32, 3-stage cp.async, 256 threads, warps 4(M)x2(N).
// ---------------------------------------------------------------------------
#define PAD_K       40
#define SUB_BYTES   (128 * PAD_K * 2)       // 10240
#define STAGE_BYTES (3 * SUB_BYTES)         // 30720: Ahi, Alo, Bh
#define GM_SMEM_TOTAL (3 * STAGE_BYTES)     // 92160

__global__ __launch_bounds__(256, 1) void gemm_mma(
    const __half* __restrict__ Ahi, const __half* __restrict__ Alo,
    const __half* __restrict__ Bh,
    float* __restrict__ C, int N, int K)
{
    extern __shared__ char smem[];
    const uint32_t sb = su32(smem);
    const int tid = threadIdx.x;
    const int lane = tid & 31;
    const int warp = tid >> 5;
    const int warpM = warp & 3;
    const int warpN = warp >> 2;
    const int m0 = blockIdx.y * 128, n0 = blockIdx.x * 128;

    float acc[2][8][4];
#pragma unroll
    for (int i = 0; i < 2; i++)
#pragma unroll
        for (int j = 0; j < 8; j++)
#pragma unroll
            for (int v = 0; v < 4; v++) acc[i][j][v] = 0.f;

    auto load_chunk = [&](int i, int s) {
        const size_t k0 = (size_t)i * 32;
#pragma unroll
        for (int t = 0; t < 6; t++) {
            const int idx = t * 256 + tid;        // 0..1535
            const int sub = idx >> 9;             // 0..2
            const int r = (idx >> 2) & 127;
            const int cs = idx & 3;
            const uint32_t d = sb + s * STAGE_BYTES + sub * SUB_BYTES
                             + (uint32_t)(r * PAD_K + cs * 8) * 2;
            const __half* bp = (sub == 0) ? Ahi : (sub == 1) ? Alo : Bh;
            const int rg = (sub < 2) ? (m0 + r) : (n0 + r);
            cpasync16(d, bp + (size_t)rg * K + k0 + cs * 8);
        }
    };

    const int nch = K >> 5;
    load_chunk(0, 0); CP_COMMIT();
    load_chunk(1, 1); CP_COMMIT();
    load_chunk(2, 2); CP_COMMIT();

    const int lr = lane & 15;
    const int lc8 = (lane >> 4) * 8;

    for (int i = 0; i < nch; i++) {
        const int s = i % 3;
        CP_WAIT2();
        __syncthreads();

        const uint32_t aB = sb + s * STAGE_BYTES;
        const uint32_t bB = aB + 2 * SUB_BYTES;
#pragma unroll
        for (int k16 = 0; k16 < 2; k16++) {
            const int kof = k16 * 16 + lc8;
            uint32_t ah[2][4], al[2][4];
#pragma unroll
            for (int mt = 0; mt < 2; mt++) {
                const uint32_t ad = aB + (uint32_t)((warpM * 32 + mt * 16 + lr) * PAD_K + kof) * 2;
                LDSM4(ah[mt], ad);
                LDSM4(al[mt], ad + SUB_BYTES);
            }
            uint32_t b[4][4];
#pragma unroll
            for (int ng = 0; ng < 4; ng++) {
                const uint32_t bd = bB + (uint32_t)((warpN * 64 + ng * 16 + lr) * PAD_K + kof) * 2;
                LDSM4(b[ng], bd);
            }
#pragma unroll
            for (int mt = 0; mt < 2; mt++)
#pragma unroll
                for (int nt = 0; nt < 8; nt++) {
                    const int ng = nt >> 1, sel = nt & 1;
                    MMA16816H(acc[mt][nt], ah[mt], b[ng][sel], b[ng][sel + 2]);
                    MMA16816H(acc[mt][nt], al[mt], b[ng][sel], b[ng][sel + 2]);
                }
        }
        __syncthreads();
        if (i + 3 < nch) load_chunk(i + 3, s);
        CP_COMMIT();
    }

#pragma unroll
    for (int mt = 0; mt < 2; mt++) {
        const int row = m0 + warpM * 32 + mt * 16 + (lane >> 2);
#pragma unroll
        for (int nt = 0; nt < 8; nt++) {
            const int col = n0 + warpN * 64 + nt * 8 + (lane & 3) * 2;
            if (col < N) {
                *(float2*)&C[(size_t)row * N + col] =
                    make_float2(acc[mt][nt][0], acc[mt][nt][1]);
                *(float2*)&C[(size_t)(row + 8) * N + col] =
                    make_float2(acc[mt][nt][2], acc[mt][nt][3]);
            }
        }
    }
}

// ---------------------------------------------------------------------------
// fp32 -> fp16 hi/lo split (activations)
// ---------------------------------------------------------------------------
__global__ void split_f16(const float* __restrict__ src,
                          __half* __restrict__ hi, __half* __restrict__ lo,
                          int n4)
{
    const int i = blockIdx.x * blockDim.x + threadIdx.x;
    if (i >= n4) return;
    float4 v = ((const float4*)src)[i];
    uint32_t h0, l0, h1, l1;
    split2h(v.x, v.y, h0, l0);
    split2h(v.z, v.w, h1, l1);
    ((uint32_t*)hi)[2 * i] = h0;     ((uint32_t*)hi)[2 * i + 1] = h1;
    ((uint32_t*)lo)[2 * i] = l0;     ((uint32_t*)lo)[2 * i + 1] = l1;
}

// fp32 -> fp16 single round (weights); zero-pads beyond n4_src
__global__ void round_f16(const float* __restrict__ src,
                          __half* __restrict__ hi, int n4_src, int n4_tot)
{
    const int i = blockIdx.x * blockDim.x + threadIdx.x;
    if (i >= n4_tot) return;
    float4 v = make_float4(0.f, 0.f, 0.f, 0.f);
    if (i < n4_src) v = ((const float4*)src)[i];
    __half2 a = __halves2half2(__float2half_rn(v.x), __float2half_rn(v.y));
    __half2 b = __halves2half2(__float2half_rn(v.z), __float2half_rn(v.w));
    ((uint32_t*)hi)[2 * i] = *(uint32_t*)&a;
    ((uint32_t*)hi)[2 * i + 1] = *(uint32_t*)&b;
}

// ---------------------------------------------------------------------------
// fp32 tiled SGEMM (small CB batch only): C = A @ B^T
// ---------------------------------------------------------------------------
__global__ __launch_bounds__(256) void gemm128(
    int M, int N, int K,
    const float* __restrict__ A, int lda, int strideA,
    const float* __restrict__ B, int ldb, int strideB,
    float* __restrict__ C, int ldc, int strideC)
{
    __shared__ float As[8 * 128];
    __shared__ float Bs[8 * 128];
    const int bz = blockIdx.z;
    A += (size_t)bz * strideA;
    B += (size_t)bz * strideB;
    C += (size_t)bz * strideC;
    const int m0 = blockIdx.y * 128;
    const int n0 = blockIdx.x * 128;
    const int tid = threadIdx.x;
    const int lrow = tid >> 1;
    const int lseg = (tid & 1) * 4;
    const int ty = tid >> 4;
    const int tx = tid & 15;

    float acc[8][8];
#pragma unroll
    for (int i = 0; i < 8; i++)
#pragma unroll
        for (int j = 0; j < 8; j++) acc[i][j] = 0.f;

    const float* aptr = A + (size_t)(m0 + lrow) * lda + lseg;
    const float* bptr = B + (size_t)(n0 + lrow) * ldb + lseg;

    for (int k0 = 0; k0 < K; k0 += 8) {
        float4 a4 = *(const float4*)(aptr + k0);
        float4 b4 = *(const float4*)(bptr + k0);
        As[(lseg + 0) * 128 + lrow] = a4.x;
        As[(lseg + 1) * 128 + lrow] = a4.y;
        As[(lseg + 2) * 128 + lrow] = a4.z;
        As[(lseg + 3) * 128 + lrow] = a4.w;
        Bs[(lseg + 0) * 128 + lrow] = b4.x;
        Bs[(lseg + 1) * 128 + lrow] = b4.y;
        Bs[(lseg + 2) * 128 + lrow] = b4.z;
        Bs[(lseg + 3) * 128 + lrow] = b4.w;
        __syncthreads();
#pragma unroll
        for (int k = 0; k < 8; k++) {
            float ar[8], br[8];
            *(float4*)&ar[0] = *(const float4*)&As[k * 128 + ty * 8];
            *(float4*)&ar[4] = *(const float4*)&As[k * 128 + ty * 8 + 4];
            *(float4*)&br[0] = *(const float4*)&Bs[k * 128 + tx * 8];
            *(float4*)&br[4] = *(const float4*)&Bs[k * 128 + tx * 8 + 4];
#pragma unroll
            for (int i = 0; i < 8; i++)
#pragma unroll
                for (int j = 0; j < 8; j++)
                    acc[i][j] = fmaf(ar[i], br[j], acc[i][j]);
        }
        __syncthreads();
    }

#pragma unroll
    for (int i = 0; i < 8; i++) {
        const int m = m0 + ty * 8 + i;
#pragma unroll
        for (int j4 = 0; j4 < 8; j4 += 4) {
            const int n = n0 + tx * 8 + j4;
            *(float4*)(C + (size_t)m * ldc + n) =
                make_float4(acc[i][j4], acc[i][j4 + 1], acc[i][j4 + 2], acc[i][j4 + 3]);
        }
    }
}

// ---------------------------------------------------------------------------
__global__ void conv_silu_kernel(const float* __restrict__ w)
{
    const int idx = blockIdx.x * blockDim.x + threadIdx.x;
    if (idx >= S_LEN * CONVD_) return;
    const int c = idx % CONVD_;
    const int t = idx / CONVD_;
    float s = 0.f;
#pragma unroll
    for (int i = 0; i < 4; i++) {
        const int tt = t - 3 + i;
        if (tt >= 0) s += g_zx[(size_t)tt * D_IN_ + HID_ + c] * w[c * 4 + i];
    }
    g_conv[idx] = s / (1.f + __expf(-s));
}

__global__ void dt_kernel(const float* __restrict__ dt_bias,
                          const float* __restrict__ A_log)
{
    const int idx = blockIdx.x * blockDim.x + threadIdx.x;
    if (idx >= S_LEN * NH_) return;
    const int h = idx % NH_;
    const int t = idx / NH_;
    const float raw = g_zx[(size_t)t * D_IN_ + (HID_ + CONVD_) + h] + dt_bias[h];
    const float dt = (raw > 20.f) ? raw : log1pf(__expf(raw));
    g_dt[idx] = dt;
    g_dAc[idx] = dt * (-__expf(A_log[h]));
}

__global__ __launch_bounds__(CH_) void cumsum_kernel()
{
    const int c = blockIdx.x, h = blockIdx.y;
    const int l = threadIdx.x;
    __shared__ float sbuf[CH_];
    const int gi = (c * CH_ + l) * NH_ + h;
    sbuf[l] = g_dAc[gi];
    __syncthreads();
    for (int off = 1; off < CH_; off <<= 1) {
        const float add = (l >= off) ? sbuf[l - off] : 0.f;
        __syncthreads();
        sbuf[l] += add;
        __syncthreads();
    }
    g_dAc[gi] = sbuf[l];
}

// ---------------------------------------------------------------------------
// states via mma.sync split bf16 (unchanged from R6)
// ---------------------------------------------------------------------------
__global__ __launch_bounds__(256) void states_mma()
{
    const int c = blockIdx.x, h = blockIdx.y;
    __shared__ float sdec[CH_];
    __shared__ __nv_bfloat16 sA[2][32 * 72];
    __shared__ __nv_bfloat16 sB[2][32 * 136];
    const int tid = threadIdx.x;
    const int lane = tid & 31, warp = tid >> 5;
    const int warpM = warp & 1, warpN = warp >> 1;

    {
        const float dalast = g_dAc[(c * CH_ + CH_ - 1) * NH_ + h];
        const int gi = (c * CH_ + tid) * NH_ + h;
        sdec[tid] = g_dt[gi] * __expf(dalast - g_dAc[gi]);
    }
    __syncthreads();

    float acc[2][4][4];
#pragma unroll
    for (int i = 0; i < 2; i++)
#pragma unroll
        for (int j = 0; j < 4; j++)
#pragma unroll
            for (int v = 0; v < 4; v++) acc[i][j][v] = 0.f;

    const int krA = (lane & 7) | ((lane >> 4) << 3);
    const int mbA = ((lane >> 3) & 1) * 8;
    const int krB = (lane & 7) | (((lane >> 3) & 1) << 3);
    const int nbB = (lane >> 4) * 8;

    for (int s0 = 0; s0 < CH_; s0 += 32) {
#pragma unroll
        for (int t = 0; t < 2; t++) {
            const int gi = t * 256 + tid;
            const int row = gi >> 4, p4 = (gi & 15) * 4;
            const float wv = sdec[s0 + row];
            float4 v = *(const float4*)&g_conv[(size_t)(c * CH_ + s0 + row) * CONVD_ + h * HD_ + p4];
            uint32_t h0, l0, h1, l1;
            split2(v.x * wv, v.y * wv, h0, l0);
            split2(v.z * wv, v.w * wv, h1, l1);
            uint32_t* dh_ = (uint32_t*)&sA[0][row * 72 + p4];
            uint32_t* dl_ = (uint32_t*)&sA[1][row * 72 + p4];
            dh_[0] = h0; dh_[1] = h1; dl_[0] = l0; dl_[1] = l1;
        }
#pragma unroll
        for (int t = 0; t < 4; t++) {
            const int gi = t * 256 + tid;
            const int row = gi >> 5, n4 = (gi & 31) * 4;
            float4 v = *(const float4*)&g_conv[(size_t)(c * CH_ + s0 + row) * CONVD_ + HID_ + n4];
            uint32_t h0, l0, h1, l1;
            split2(v.x, v.y, h0, l0);
            split2(v.z, v.w, h1, l1);
            uint32_t* dh_ = (uint32_t*)&sB[0][row * 136 + n4];
            uint32_t* dl_ = (uint32_t*)&sB[1][row * 136 + n4];
            dh_[0] = h0; dh_[1] = h1; dl_[0] = l0; dl_[1] = l1;
        }
        __syncthreads();
#pragma unroll
        for (int k16 = 0; k16 < 2; k16++) {
            uint32_t ah[2][4], al[2][4];
#pragma unroll
            for (int mt = 0; mt < 2; mt++) {
                const int mc = warpM * 32 + mt * 16 + mbA;
                const uint32_t ad = su32(&sA[0][(k16 * 16 + krA) * 72 + mc]);
                LDSM4T(ah[mt], ad);
                LDSM4T(al[mt], ad + 32 * 72 * 2);
            }
            uint32_t bh[4][2], bl[4][2];
#pragma unroll
            for (int nh2 = 0; nh2 < 2; nh2++) {
                const int nc = warpN * 32 + nh2 * 16 + nbB;
                uint32_t r[4];
                const uint32_t bd = su32(&sB[0][(k16 * 16 + krB) * 136 + nc]);
                LDSM4T(r, bd);
                bh[nh2 * 2][0] = r[0]; bh[nh2 * 2][1] = r[1];
                bh[nh2 * 2 + 1][0] = r[2]; bh[nh2 * 2 + 1][1] = r[3];
                LDSM4T(r, bd + 32 * 136 * 2);
                bl[nh2 * 2][0] = r[0]; bl[nh2 * 2][1] = r[1];
                bl[nh2 * 2 + 1][0] = r[2]; bl[nh2 * 2 + 1][1] = r[3];
            }
#pragma unroll
            for (int mt = 0; mt < 2; mt++)
#pragma unroll
                for (int ng = 0; ng < 4; ng++) {
                    MMA16816(acc[mt][ng], ah[mt], bh[ng][0], bh[ng][1]);
                    MMA16816(acc[mt][ng], ah[mt], bl[ng][0], bl[ng][1]);
                    MMA16816(acc[mt][ng], al[mt], bh[ng][0], bh[ng][1]);
                }
        }
        __syncthreads();
    }

    const size_t base = ((size_t)(c * NH_ + h)) * HD_ * NST_;
#pragma unroll
    for (int mt = 0; mt < 2; mt++) {
        const int row = warpM * 32 + mt * 16 + (lane >> 2);
#pragma unroll
        for (int ng = 0; ng < 4; ng++) {
            const int col = warpN * 32 + ng * 8 + (lane & 3) * 2;
            *(float2*)&g_states[base + (size_t)row * NST_ + col] =
                make_float2(acc[mt][ng][0], acc[mt][ng][1]);
            *(float2*)&g_states[base + (size_t)(row + 8) * NST_ + col] =
                make_float2(acc[mt][ng][2], acc[mt][ng][3]);
        }
    }
}

__global__ void chunkscan_kernel()
{
    const int idx = blockIdx.x * blockDim.x + threadIdx.x;
    if (idx >= NH_ * HD_ * NST_) return;
    const int h = idx / (HD_ * NST_);
    const int rem = idx % (HD_ * NST_);
    float carry = 0.f;
#pragma unroll
    for (int c = 0; c < NC_; c++) {
        const size_t off = ((size_t)(c * NH_ + h)) * HD_ * NST_ + rem;
        g_prev[off] = carry;
        const float dec = __expf(g_dAc[(c * CH_ + CH_ - 1) * NH_ + h]);
        carry = carry * dec + g_states[off];
    }
}

// ---------------------------------------------------------------------------
// ydiag via mma.sync split bf16 (unchanged from R6 aside from __expf)
// ---------------------------------------------------------------------------
#define YD_MH 0
#define YD_ML 2560
#define YD_XH 5120
#define YD_XL 7424
#define YD_CH 0
#define YD_CL 4608
#define YD_PH 9216
#define YD_PL 13824

__global__ __launch_bounds__(256) void ydiag_mma(const float* __restrict__ Dp)
{
    const int lt = blockIdx.x, c = blockIdx.y, h = blockIdx.z;
    __shared__ float sdAc[CH_], sdtv[CH_];
    __shared__ __nv_bfloat16 sbuf[18432];
    const int tid = threadIdx.x;
    const int lane = tid & 31, warp = tid >> 5;
    const int warpM = warp & 1, warpN = warp >> 1;
    const int l0 = lt * 64;

    {
        const int gi = (c * CH_ + tid) * NH_ + h;
        sdAc[tid] = g_dAc[gi];
        sdtv[tid] = g_dt[gi];
    }
    __syncthreads();

    float accA[2][2][4], acc2[2][2][4];
#pragma unroll
    for (int i = 0; i < 2; i++)
#pragma unroll
        for (int j = 0; j < 2; j++)
#pragma unroll
            for (int v = 0; v < 4; v++) { accA[i][j][v] = 0.f; acc2[i][j][v] = 0.f; }

    const int lr = lane & 15;
    const int lc8 = (lane >> 4) * 8;
    const int krB = (lane & 7) | (((lane >> 3) & 1) << 3);
    const int nbB = (lane >> 4) * 8;

    const int smax = l0 + 64;
    for (int s0 = 0; s0 < smax; s0 += 32) {
        {
            const int lrow = tid >> 2;
            const int sseg = (tid & 3) * 8;
            const float dacl = sdAc[l0 + lrow];
            const float* cbp = &g_CB[c * (CH_ * CH_) + (l0 + lrow) * CH_ + s0 + sseg];
            float4 cb0 = *(const float4*)cbp;
            float4 cb1 = *(const float4*)(cbp + 4);
            float cbv[8] = {cb0.x, cb0.y, cb0.z, cb0.w, cb1.x, cb1.y, cb1.z, cb1.w};
#pragma unroll
            for (int j = 0; j < 8; j++) {
                const int s = s0 + sseg + j;
                float v = 0.f;
                if (s <= l0 + lrow) v = cbv[j] * __expf(dacl - sdAc[s]);
                const __nv_bfloat16 hv = __float2bfloat16(v);
                sbuf[YD_MH + lrow * 40 + sseg + j] = hv;
                sbuf[YD_ML + lrow * 40 + sseg + j] =
                    __float2bfloat16(v - __bfloat162float(hv));
            }
        }
#pragma unroll
        for (int t = 0; t < 2; t++) {
            const int gi = t * 256 + tid;
            const int row = gi >> 4, p4 = (gi & 15) * 4;
            const float wv = sdtv[s0 + row];
            float4 v = *(const float4*)&g_conv[(size_t)(c * CH_ + s0 + row) * CONVD_ + h * HD_ + p4];
            uint32_t h0, lo0, h1, lo1;
            split2(v.x * wv, v.y * wv, h0, lo0);
            split2(v.z * wv, v.w * wv, h1, lo1);
            uint32_t* dh_ = (uint32_t*)&sbuf[YD_XH + row * 72 + p4];
            uint32_t* dl_ = (uint32_t*)&sbuf[YD_XL + row * 72 + p4];
            dh_[0] = h0; dh_[1] = h1; dl_[0] = lo0; dl_[1] = lo1;
        }
        __syncthreads();
#pragma unroll
        for (int k16 = 0; k16 < 2; k16++) {
            uint32_t ah[2][4], al[2][4];
#pragma unroll
            for (int mt = 0; mt < 2; mt++) {
                const uint32_t ad = su32(
                    &sbuf[YD_MH + (warpM * 32 + mt * 16 + lr) * 40 + k16 * 16 + lc8]);
                LDSM4(ah[mt], ad);
                LDSM4(al[mt], ad + YD_ML * 2);
            }
            uint32_t bh[2][2], bl[2][2];
            {
                const int nc = warpN * 16 + nbB;
                uint32_t r[4];
                const uint32_t bd = su32(&sbuf[YD_XH + (k16 * 16 + krB) * 72 + nc]);
                LDSM4T(r, bd);
                bh[0][0] = r[0]; bh[0][1] = r[1]; bh[1][0] = r[2]; bh[1][1] = r[3];
                LDSM4T(r, bd + (YD_XL - YD_XH) * 2);
                bl[0][0] = r[0]; bl[0][1] = r[1]; bl[1][0] = r[2]; bl[1][1] = r[3];
            }
#pragma unroll
            for (int mt = 0; mt < 2; mt++)
#pragma unroll
                for (int ng = 0; ng < 2; ng++) {
                    MMA16816(accA[mt][ng], ah[mt], bh[ng][0], bh[ng][1]);
                    MMA16816(accA[mt][ng], ah[mt], bl[ng][0], bl[ng][1]);
                    MMA16816(accA[mt][ng], al[mt], bh[ng][0], bh[ng][1]);
                }
        }
        __syncthreads();
    }

    const size_t pbase = ((size_t)(c * NH_ + h)) * HD_ * NST_;
    for (int n0c = 0; n0c < NST_; n0c += 64) {
#pragma unroll
        for (int t = 0; t < 4; t++) {
            const int gi = t * 256 + tid;
            const int row = gi >> 4, n4 = (gi & 15) * 4;
            float4 v = *(const float4*)&g_conv[(size_t)(c * CH_ + l0 + row) * CONVD_ +
                                               HID_ + NST_ + n0c + n4];
            uint32_t h0, lo0, h1, lo1;
            split2(v.x, v.y, h0, lo0);
            split2(v.z, v.w, h1, lo1);
            uint32_t* dh_ = (uint32_t*)&sbuf[YD_CH + row * 72 + n4];
            uint32_t* dl_ = (uint32_t*)&sbuf[YD_CL + row * 72 + n4];
            dh_[0] = h0; dh_[1] = h1; dl_[0] = lo0; dl_[1] = lo1;

            float4 p = *(const float4*)&g_prev[pbase + (size_t)row * NST_ + n0c + n4];
            split2(p.x, p.y, h0, lo0);
            split2(p.z, p.w, h1, lo1);
            uint32_t* ph_ = (uint32_t*)&sbuf[YD_PH + row * 72 + n4];
            uint32_t* pl_ = (uint32_t*)&sbuf[YD_PL + row * 72 + n4];
            ph_[0] = h0; ph_[1] = h1; pl_[0] = lo0; pl_[1] = lo1;
        }
        __syncthreads();
#pragma unroll
        for (int k16 = 0; k16 < 4; k16++) {
            uint32_t ah[2][4], al[2][4];
#pragma unroll
            for (int mt = 0; mt < 2; mt++) {
                const uint32_t ad = su32(
                    &sbuf[YD_CH + (warpM * 32 + mt * 16 + lr) * 72 + k16 * 16 + lc8]);
                LDSM4(ah[mt], ad);
                LDSM4(al[mt], ad + YD_CL * 2);
            }
            uint32_t bh[4], bl[4];
            {
                const uint32_t bd = su32(
                    &sbuf[YD_PH + (warpN * 16 + lr) * 72 + k16 * 16 + lc8]);
                LDSM4(bh, bd);
                LDSM4(bl, bd + (YD_PL - YD_PH) * 2);
            }
#pragma unroll
            for (int mt = 0; mt < 2; mt++)
#pragma unroll
                for (int ng = 0; ng < 2; ng++) {
                    MMA16816(acc2[mt][ng], ah[mt], bh[ng], bh[ng + 2]);
                    MMA16816(acc2[mt][ng], ah[mt], bl[ng], bl[ng + 2]);
                    MMA16816(acc2[mt][ng], al[mt], bh[ng], bh[ng + 2]);
                }
        }
        __syncthreads();
    }

    const float dh = Dp[h];
#pragma unroll
    for (int mt = 0; mt < 2; mt++) {
        const int lrow = warpM * 32 + mt * 16 + (lane >> 2);
#pragma unroll
        for (int ng = 0; ng < 2; ng++) {
            const int col = warpN * 16 + ng * 8 + (lane & 3) * 2;
#pragma unroll
            for (int half = 0; half < 2; half++) {
                const int l = l0 + lrow + half * 8;
                const int t = c * CH_ + l;
                const float el = __expf(sdAc[l]);
                const float2 x2 = *(const float2*)&g_conv[(size_t)t * CONVD_ + h * HD_ + col];
                float2 o;
                o.x = accA[mt][ng][half * 2]     + el * acc2[mt][ng][half * 2]     + x2.x * dh;
                o.y = accA[mt][ng][half * 2 + 1] + el * acc2[mt][ng][half * 2 + 1] + x2.y * dh;
                *(float2*)&g_y[(size_t)t * HID_ + h * HD_ + col] = o;
            }
        }
    }
}

// ---------------------------------------------------------------------------
// gate + RMSNorm, fused fp16 hi/lo split output for out_proj
// ---------------------------------------------------------------------------
__global__ __launch_bounds__(256) void gatenorm_kernel(const float* __restrict__ nw)
{
    const int t = blockIdx.x;
    const int tid = threadIdx.x;
    float vals[16];
    float ss = 0.f;
#pragma unroll
    for (int k = 0; k < 16; k++) {
        const int i = tid + k * 256;
        const float yv = g_y[(size_t)t * HID_ + i];
        const float zv = g_zx[(size_t)t * D_IN_ + i];
        const float v = yv * (zv / (1.f + __expf(-zv)));
        vals[k] = v;
        ss += v * v;
    }
    __shared__ float red[8];
#pragma unroll
    for (int o = 16; o > 0; o >>= 1) ss += __shfl_xor_sync(0xffffffffu, ss, o);
    if ((tid & 31) == 0) red[tid >> 5] = ss;
    __syncthreads();
    if (tid < 8) {
        float v = red[tid];
#pragma unroll
        for (int o = 4; o > 0; o >>= 1) v += __shfl_xor_sync(0xffu, v, o);
        if (tid == 0) red[0] = v;
    }
    __syncthreads();
    const float scale = rsqrtf(red[0] / (float)HID_ + 1e-5f);
#pragma unroll
    for (int k = 0; k < 16; k++) {
        const int i = tid + k * 256;
        const float v = vals[k] * scale * nw[i];
        const __half hv = __float2half_rn(v);
        g_yhi[(size_t)t * HID_ + i] = hv;
        g_ylo[(size_t)t * HID_ + i] = __float2half_rn(v - __half2float(hv));
    }
}

// ---------------------------------------------------------------------------
extern "C" void kernel_launch(void* const* d_in, const int* in_sizes, int n_in,
                              void* d_out, int out_size)
{
    const float* x       = (const float*)d_in[0];
    const float* in_w    = (const float*)d_in[1];
    const float* conv_w  = (const float*)d_in[2];
    const float* dt_bias = (const float*)d_in[3];
    const float* A_log   = (const float*)d_in[4];
    const float* Dp      = (const float*)d_in[5];
    const float* norm_w  = (const float*)d_in[6];
    const float* out_w   = (const float*)d_in[7];
    float* out = (float*)d_out;

    float *zx, *conv, *cb;
    __half *xhi, *xlo, *wih, *yhi, *ylo, *woh;
    cudaGetSymbolAddress((void**)&zx, g_zx);
    cudaGetSymbolAddress((void**)&conv, g_conv);
    cudaGetSymbolAddress((void**)&cb, g_CB);
    cudaGetSymbolAddress((void**)&xhi, g_xhi);
    cudaGetSymbolAddress((void**)&xlo, g_xlo);
    cudaGetSymbolAddress((void**)&wih, g_wih);
    cudaGetSymbolAddress((void**)&yhi, g_yhi);
    cudaGetSymbolAddress((void**)&ylo, g_ylo);
    cudaGetSymbolAddress((void**)&woh, g_woh);

    cudaFuncSetAttribute(gemm_mma, cudaFuncAttributeMaxDynamicSharedMemorySize,
                         GM_SMEM_TOTAL);

    // 0) fp16 splits for in_proj operands
    {
        const int n4s = S_LEN * DIM_ / 4;
        split_f16<<<(n4s + 255) / 256, 256>>>(x, xhi, xlo, n4s);
        const int n4w = D_IN_ * DIM_ / 4;
        const int n4wt = D_INP_ * DIM_ / 4;
        round_f16<<<(n4wt + 255) / 256, 256>>>(in_w, wih, n4w, n4wt);
    }

    // 1) in_proj
    gemm_mma<<<dim3(D_INP_ / 128, S_LEN / 128), 256, GM_SMEM_TOTAL>>>(
        xhi, xlo, wih, zx, D_IN_, DIM_);

    // 2) conv1d + SiLU
    conv_silu_kernel<<<(S_LEN * CONVD_ + 255) / 256, 256>>>(conv_w);

    // 3) dt / dA
    dt_kernel<<<(S_LEN * NH_ + 255) / 256, 256>>>(dt_bias, A_log);

    // 4) cumsum
    cumsum_kernel<<<dim3(NC_, NH_), CH_>>>();

    // 5) CB per chunk
    gemm128<<<dim3(2, 2, NC_), 256>>>(
        CH_, CH_, NST_,
        conv + HID_ + NST_, CONVD_, CH_ * CONVD_,
        conv + HID_,        CONVD_, CH_ * CONVD_,
        cb, CH_, CH_ * CH_);

    // 6) states (mma)
    states_mma<<<dim3(NC_, NH_), 256>>>();

    // 7) inter-chunk scan
    chunkscan_kernel<<<(NH_ * HD_ * NST_) / 256, 256>>>();

    // 8) y_diag + y_off + D-skip (mma)
    ydiag_mma<<<dim3(4, NC_, NH_), 256>>>(Dp);

    // 9) gate + RMSNorm (+ fused fp16 y split)
    gatenorm_kernel<<<S_LEN, 256>>>(norm_w);

    // 10) out_proj (weight round + gemm)
    {
        const int n4o = DIM_ * HID_ / 4;
        round_f16<<<(n4o + 255) / 256, 256>>>(out_w, woh, n4o, n4o);
    }
    gemm_mma<<<dim3(DIM_ / 128, S_LEN / 128), 256, GM_SMEM_TOTAL>>>(
        yhi, ylo, woh, out, DIM_, HID_);
}

// round 9
// speedup vs baseline: 7.8415x; 1.6557x over previous
#include <cuda_runtime.h>
#include <cuda_bf16.h>
#include <cuda_fp16.h>
#include <stdint.h>
#include <math.h>

// ---------------------------------------------------------------------------
// Mamba2-style SSD block. Round 8: big GEMMs single-pass fp16 (both operands
// rounded). conv_silu vectorized x4. states/ydiag stay bf16 3-pass.
// ---------------------------------------------------------------------------

#define S_LEN   4096
#define DIM_    2048
#define HID_    4096
#define D_IN_   8512
#define D_INP_  8576
#define CONVD_  4352
#define NH_     64
#define HD_     64
#define NST_    128
#define CH_     256
#define NC_     16

__device__ float g_zx[(size_t)S_LEN * D_IN_];
__device__ float g_conv[(size_t)S_LEN * CONVD_];
__device__ float g_dt[S_LEN * NH_];
__device__ float g_dAc[S_LEN * NH_];
__device__ float g_CB[NC_ * CH_ * CH_];
__device__ float g_states[NC_ * NH_ * HD_ * NST_];
__device__ float g_prev[NC_ * NH_ * HD_ * NST_];
__device__ float g_y[(size_t)S_LEN * HID_];

// fp16 operands (single precision pass)
__device__ __half g_xh[(size_t)S_LEN * DIM_];
__device__ __half g_wih[(size_t)D_INP_ * DIM_];
__device__ __half g_yh[(size_t)S_LEN * HID_];
__device__ __half g_woh[(size_t)DIM_ * HID_];

// ---------------------------------------------------------------------------
__device__ __forceinline__ uint32_t su32(const void* p) {
    uint32_t a;
    asm("{ .reg .u64 t; cvta.to.shared.u64 t, %1; cvt.u32.u64 %0, t; }"
        : "=r"(a) : "l"(p));
    return a;
}

__device__ __forceinline__ void cpasync16(uint32_t dst, const void* src) {
    asm volatile("cp.async.cg.shared.global [%0], [%1], 16;" :: "r"(dst), "l"(src));
}
#define CP_COMMIT() asm volatile("cp.async.commit_group;" ::: "memory")
#define CP_WAIT2()  asm volatile("cp.async.wait_group 2;" ::: "memory")

#define LDSM4(r, addr) \
    asm volatile("ldmatrix.sync.aligned.m8n8.x4.shared.b16 {%0,%1,%2,%3}, [%4];" \
        : "=r"((r)[0]), "=r"((r)[1]), "=r"((r)[2]), "=r"((r)[3]) : "r"(addr))

#define LDSM4T(r, addr) \
    asm volatile("ldmatrix.sync.aligned.m8n8.x4.trans.shared.b16 {%0,%1,%2,%3}, [%4];" \
        : "=r"((r)[0]), "=r"((r)[1]), "=r"((r)[2]), "=r"((r)[3]) : "r"(addr))

// bf16 mma (mid-section kernels)
#define MMA16816(d, a, b0, b1) \
    asm volatile("mma.sync.aligned.m16n8k16.row.col.f32.bf16.bf16.f32 " \
        "{%0,%1,%2,%3}, {%4,%5,%6,%7}, {%8,%9}, {%0,%1,%2,%3};" \
        : "+f"((d)[0]), "+f"((d)[1]), "+f"((d)[2]), "+f"((d)[3]) \
        : "r"((a)[0]), "r"((a)[1]), "r"((a)[2]), "r"((a)[3]), "r"(b0), "r"(b1))

// fp16 mma (big GEMMs)
#define MMA16816H(d, a, b0, b1) \
    asm volatile("mma.sync.aligned.m16n8k16.row.col.f32.f16.f16.f32 " \
        "{%0,%1,%2,%3}, {%4,%5,%6,%7}, {%8,%9}, {%0,%1,%2,%3};" \
        : "+f"((d)[0]), "+f"((d)[1]), "+f"((d)[2]), "+f"((d)[3]) \
        : "r"((a)[0]), "r"((a)[1]), "r"((a)[2]), "r"((a)[3]), "r"(b0), "r"(b1))

// fp32x2 -> packed bf16x2 hi + lo (mid-section)
__device__ __forceinline__ void split2(float a, float b, uint32_t& hi, uint32_t& lo) {
    __nv_bfloat16 h0 = __float2bfloat16(a), h1 = __float2bfloat16(b);
    __nv_bfloat16 m0 = __float2bfloat16(a - __bfloat162float(h0));
    __nv_bfloat16 m1 = __float2bfloat16(b - __bfloat162float(h1));
    __nv_bfloat162 H = __halves2bfloat162(h0, h1), L = __halves2bfloat162(m0, m1);
    hi = *(uint32_t*)&H;
    lo = *(uint32_t*)&L;
}

// ---------------------------------------------------------------------------
// fp16 single-pass GEMM: C[M,N] = Ah[M,K] @ Bh[Npad,K]^T
// 128x128 CTA, BK=32, 3-stage cp.async, 256 threads, warps 4(M)x2(N).
// ---------------------------------------------------------------------------
#define PAD_K       40
#define SUB_BYTES   (128 * PAD_K * 2)       // 10240
#define STAGE_BYTES (2 * SUB_BYTES)         // 20480: Ah, Bh
#define GM_SMEM_TOTAL (3 * STAGE_BYTES)     // 61440

__global__ __launch_bounds__(256, 1) void gemm_mma(
    const __half* __restrict__ Ah, const __half* __restrict__ Bh,
    float* __restrict__ C, int N, int K)
{
    extern __shared__ char smem[];
    const uint32_t sb = su32(smem);
    const int tid = threadIdx.x;
    const int lane = tid & 31;
    const int warp = tid >> 5;
    const int warpM = warp & 3;
    const int warpN = warp >> 2;
    const int m0 = blockIdx.y * 128, n0 = blockIdx.x * 128;

    float acc[2][8][4];
#pragma unroll
    for (int i = 0; i < 2; i++)
#pragma unroll
        for (int j = 0; j < 8; j++)
#pragma unroll
            for (int v = 0; v < 4; v++) acc[i][j][v] = 0.f;

    auto load_chunk = [&](int i, int s) {
        const size_t k0 = (size_t)i * 32;
#pragma unroll
        for (int t = 0; t < 4; t++) {
            const int idx = t * 256 + tid;        // 0..1023
            const int sub = idx >> 9;             // 0..1
            const int r = (idx >> 2) & 127;
            const int cs = idx & 3;
            const uint32_t d = sb + s * STAGE_BYTES + sub * SUB_BYTES
                             + (uint32_t)(r * PAD_K + cs * 8) * 2;
            const __half* bp = (sub == 0) ? Ah : Bh;
            const int rg = (sub == 0) ? (m0 + r) : (n0 + r);
            cpasync16(d, bp + (size_t)rg * K + k0 + cs * 8);
        }
    };

    const int nch = K >> 5;
    load_chunk(0, 0); CP_COMMIT();
    load_chunk(1, 1); CP_COMMIT();
    load_chunk(2, 2); CP_COMMIT();

    const int lr = lane & 15;
    const int lc8 = (lane >> 4) * 8;

    for (int i = 0; i < nch; i++) {
        const int s = i % 3;
        CP_WAIT2();
        __syncthreads();

        const uint32_t aB = sb + s * STAGE_BYTES;
        const uint32_t bB = aB + SUB_BYTES;
#pragma unroll
        for (int k16 = 0; k16 < 2; k16++) {
            const int kof = k16 * 16 + lc8;
            uint32_t a[2][4];
#pragma unroll
            for (int mt = 0; mt < 2; mt++) {
                const uint32_t ad = aB + (uint32_t)((warpM * 32 + mt * 16 + lr) * PAD_K + kof) * 2;
                LDSM4(a[mt], ad);
            }
            uint32_t b[4][4];
#pragma unroll
            for (int ng = 0; ng < 4; ng++) {
                const uint32_t bd = bB + (uint32_t)((warpN * 64 + ng * 16 + lr) * PAD_K + kof) * 2;
                LDSM4(b[ng], bd);
            }
#pragma unroll
            for (int mt = 0; mt < 2; mt++)
#pragma unroll
                for (int nt = 0; nt < 8; nt++) {
                    const int ng = nt >> 1, sel = nt & 1;
                    MMA16816H(acc[mt][nt], a[mt], b[ng][sel], b[ng][sel + 2]);
                }
        }
        __syncthreads();
        if (i + 3 < nch) load_chunk(i + 3, s);
        CP_COMMIT();
    }

#pragma unroll
    for (int mt = 0; mt < 2; mt++) {
        const int row = m0 + warpM * 32 + mt * 16 + (lane >> 2);
#pragma unroll
        for (int nt = 0; nt < 8; nt++) {
            const int col = n0 + warpN * 64 + nt * 8 + (lane & 3) * 2;
            if (col < N) {
                *(float2*)&C[(size_t)row * N + col] =
                    make_float2(acc[mt][nt][0], acc[mt][nt][1]);
                *(float2*)&C[(size_t)(row + 8) * N + col] =
                    make_float2(acc[mt][nt][2], acc[mt][nt][3]);
            }
        }
    }
}

// fp32 -> fp16 single round; zero-pads beyond n4_src
__global__ void round_f16(const float* __restrict__ src,
                          __half* __restrict__ hi, int n4_src, int n4_tot)
{
    const int i = blockIdx.x * blockDim.x + threadIdx.x;
    if (i >= n4_tot) return;
    float4 v = make_float4(0.f, 0.f, 0.f, 0.f);
    if (i < n4_src) v = ((const float4*)src)[i];
    __half2 a = __halves2half2(__float2half_rn(v.x), __float2half_rn(v.y));
    __half2 b = __halves2half2(__float2half_rn(v.z), __float2half_rn(v.w));
    ((uint32_t*)hi)[2 * i] = *(uint32_t*)&a;
    ((uint32_t*)hi)[2 * i + 1] = *(uint32_t*)&b;
}

// ---------------------------------------------------------------------------
// fp32 tiled SGEMM (small CB batch only): C = A @ B^T
// ---------------------------------------------------------------------------
__global__ __launch_bounds__(256) void gemm128(
    int M, int N, int K,
    const float* __restrict__ A, int lda, int strideA,
    const float* __restrict__ B, int ldb, int strideB,
    float* __restrict__ C, int ldc, int strideC)
{
    __shared__ float As[8 * 128];
    __shared__ float Bs[8 * 128];
    const int bz = blockIdx.z;
    A += (size_t)bz * strideA;
    B += (size_t)bz * strideB;
    C += (size_t)bz * strideC;
    const int m0 = blockIdx.y * 128;
    const int n0 = blockIdx.x * 128;
    const int tid = threadIdx.x;
    const int lrow = tid >> 1;
    const int lseg = (tid & 1) * 4;
    const int ty = tid >> 4;
    const int tx = tid & 15;

    float acc[8][8];
#pragma unroll
    for (int i = 0; i < 8; i++)
#pragma unroll
        for (int j = 0; j < 8; j++) acc[i][j] = 0.f;

    const float* aptr = A + (size_t)(m0 + lrow) * lda + lseg;
    const float* bptr = B + (size_t)(n0 + lrow) * ldb + lseg;

    for (int k0 = 0; k0 < K; k0 += 8) {
        float4 a4 = *(const float4*)(aptr + k0);
        float4 b4 = *(const float4*)(bptr + k0);
        As[(lseg + 0) * 128 + lrow] = a4.x;
        As[(lseg + 1) * 128 + lrow] = a4.y;
        As[(lseg + 2) * 128 + lrow] = a4.z;
        As[(lseg + 3) * 128 + lrow] = a4.w;
        Bs[(lseg + 0) * 128 + lrow] = b4.x;
        Bs[(lseg + 1) * 128 + lrow] = b4.y;
        Bs[(lseg + 2) * 128 + lrow] = b4.z;
        Bs[(lseg + 3) * 128 + lrow] = b4.w;
        __syncthreads();
#pragma unroll
        for (int k = 0; k < 8; k++) {
            float ar[8], br[8];
            *(float4*)&ar[0] = *(const float4*)&As[k * 128 + ty * 8];
            *(float4*)&ar[4] = *(const float4*)&As[k * 128 + ty * 8 + 4];
            *(float4*)&br[0] = *(const float4*)&Bs[k * 128 + tx * 8];
            *(float4*)&br[4] = *(const float4*)&Bs[k * 128 + tx * 8 + 4];
#pragma unroll
            for (int i = 0; i < 8; i++)
#pragma unroll
                for (int j = 0; j < 8; j++)
                    acc[i][j] = fmaf(ar[i], br[j], acc[i][j]);
        }
        __syncthreads();
    }

#pragma unroll
    for (int i = 0; i < 8; i++) {
        const int m = m0 + ty * 8 + i;
#pragma unroll
        for (int j4 = 0; j4 < 8; j4 += 4) {
            const int n = n0 + tx * 8 + j4;
            *(float4*)(C + (size_t)m * ldc + n) =
                make_float4(acc[i][j4], acc[i][j4 + 1], acc[i][j4 + 2], acc[i][j4 + 3]);
        }
    }
}

// ---------------------------------------------------------------------------
// conv1d + SiLU, 4 channels per thread (float4)
// ---------------------------------------------------------------------------
__global__ void conv_silu_kernel(const float* __restrict__ w)
{
    const int idx = blockIdx.x * blockDim.x + threadIdx.x;
    const int NQ = CONVD_ / 4;
    if (idx >= S_LEN * NQ) return;
    const int c4 = idx % NQ;
    const int t = idx / NQ;
    float4 acc = make_float4(0.f, 0.f, 0.f, 0.f);
#pragma unroll
    for (int i = 0; i < 4; i++) {
        const int tt = t - 3 + i;
        if (tt >= 0) {
            float4 xv = *(const float4*)&g_zx[(size_t)tt * D_IN_ + HID_ + c4 * 4];
            acc.x += xv.x * w[(c4 * 4 + 0) * 4 + i];
            acc.y += xv.y * w[(c4 * 4 + 1) * 4 + i];
            acc.z += xv.z * w[(c4 * 4 + 2) * 4 + i];
            acc.w += xv.w * w[(c4 * 4 + 3) * 4 + i];
        }
    }
    float4 o;
    o.x = acc.x / (1.f + __expf(-acc.x));
    o.y = acc.y / (1.f + __expf(-acc.y));
    o.z = acc.z / (1.f + __expf(-acc.z));
    o.w = acc.w / (1.f + __expf(-acc.w));
    *(float4*)&g_conv[(size_t)t * CONVD_ + c4 * 4] = o;
}

__global__ void dt_kernel(const float* __restrict__ dt_bias,
                          const float* __restrict__ A_log)
{
    const int idx = blockIdx.x * blockDim.x + threadIdx.x;
    if (idx >= S_LEN * NH_) return;
    const int h = idx % NH_;
    const int t = idx / NH_;
    const float raw = g_zx[(size_t)t * D_IN_ + (HID_ + CONVD_) + h] + dt_bias[h];
    const float dt = (raw > 20.f) ? raw : log1pf(__expf(raw));
    g_dt[idx] = dt;
    g_dAc[idx] = dt * (-__expf(A_log[h]));
}

__global__ __launch_bounds__(CH_) void cumsum_kernel()
{
    const int c = blockIdx.x, h = blockIdx.y;
    const int l = threadIdx.x;
    __shared__ float sbuf[CH_];
    const int gi = (c * CH_ + l) * NH_ + h;
    sbuf[l] = g_dAc[gi];
    __syncthreads();
    for (int off = 1; off < CH_; off <<= 1) {
        const float add = (l >= off) ? sbuf[l - off] : 0.f;
        __syncthreads();
        sbuf[l] += add;
        __syncthreads();
    }
    g_dAc[gi] = sbuf[l];
}

// ---------------------------------------------------------------------------
// states via mma.sync split bf16 (unchanged)
// ---------------------------------------------------------------------------
__global__ __launch_bounds__(256) void states_mma()
{
    const int c = blockIdx.x, h = blockIdx.y;
    __shared__ float sdec[CH_];
    __shared__ __nv_bfloat16 sA[2][32 * 72];
    __shared__ __nv_bfloat16 sB[2][32 * 136];
    const int tid = threadIdx.x;
    const int lane = tid & 31, warp = tid >> 5;
    const int warpM = warp & 1, warpN = warp >> 1;

    {
        const float dalast = g_dAc[(c * CH_ + CH_ - 1) * NH_ + h];
        const int gi = (c * CH_ + tid) * NH_ + h;
        sdec[tid] = g_dt[gi] * __expf(dalast - g_dAc[gi]);
    }
    __syncthreads();

    float acc[2][4][4];
#pragma unroll
    for (int i = 0; i < 2; i++)
#pragma unroll
        for (int j = 0; j < 4; j++)
#pragma unroll
            for (int v = 0; v < 4; v++) acc[i][j][v] = 0.f;

    const int krA = (lane & 7) | ((lane >> 4) << 3);
    const int mbA = ((lane >> 3) & 1) * 8;
    const int krB = (lane & 7) | (((lane >> 3) & 1) << 3);
    const int nbB = (lane >> 4) * 8;

    for (int s0 = 0; s0 < CH_; s0 += 32) {
#pragma unroll
        for (int t = 0; t < 2; t++) {
            const int gi = t * 256 + tid;
            const int row = gi >> 4, p4 = (gi & 15) * 4;
            const float wv = sdec[s0 + row];
            float4 v = *(const float4*)&g_conv[(size_t)(c * CH_ + s0 + row) * CONVD_ + h * HD_ + p4];
            uint32_t h0, l0, h1, l1;
            split2(v.x * wv, v.y * wv, h0, l0);
            split2(v.z * wv, v.w * wv, h1, l1);
            uint32_t* dh_ = (uint32_t*)&sA[0][row * 72 + p4];
            uint32_t* dl_ = (uint32_t*)&sA[1][row * 72 + p4];
            dh_[0] = h0; dh_[1] = h1; dl_[0] = l0; dl_[1] = l1;
        }
#pragma unroll
        for (int t = 0; t < 4; t++) {
            const int gi = t * 256 + tid;
            const int row = gi >> 5, n4 = (gi & 31) * 4;
            float4 v = *(const float4*)&g_conv[(size_t)(c * CH_ + s0 + row) * CONVD_ + HID_ + n4];
            uint32_t h0, l0, h1, l1;
            split2(v.x, v.y, h0, l0);
            split2(v.z, v.w, h1, l1);
            uint32_t* dh_ = (uint32_t*)&sB[0][row * 136 + n4];
            uint32_t* dl_ = (uint32_t*)&sB[1][row * 136 + n4];
            dh_[0] = h0; dh_[1] = h1; dl_[0] = l0; dl_[1] = l1;
        }
        __syncthreads();
#pragma unroll
        for (int k16 = 0; k16 < 2; k16++) {
            uint32_t ah[2][4], al[2][4];
#pragma unroll
            for (int mt = 0; mt < 2; mt++) {
                const int mc = warpM * 32 + mt * 16 + mbA;
                const uint32_t ad = su32(&sA[0][(k16 * 16 + krA) * 72 + mc]);
                LDSM4T(ah[mt], ad);
                LDSM4T(al[mt], ad + 32 * 72 * 2);
            }
            uint32_t bh[4][2], bl[4][2];
#pragma unroll
            for (int nh2 = 0; nh2 < 2; nh2++) {
                const int nc = warpN * 32 + nh2 * 16 + nbB;
                uint32_t r[4];
                const uint32_t bd = su32(&sB[0][(k16 * 16 + krB) * 136 + nc]);
                LDSM4T(r, bd);
                bh[nh2 * 2][0] = r[0]; bh[nh2 * 2][1] = r[1];
                bh[nh2 * 2 + 1][0] = r[2]; bh[nh2 * 2 + 1][1] = r[3];
                LDSM4T(r, bd + 32 * 136 * 2);
                bl[nh2 * 2][0] = r[0]; bl[nh2 * 2][1] = r[1];
                bl[nh2 * 2 + 1][0] = r[2]; bl[nh2 * 2 + 1][1] = r[3];
            }
#pragma unroll
            for (int mt = 0; mt < 2; mt++)
#pragma unroll
                for (int ng = 0; ng < 4; ng++) {
                    MMA16816(acc[mt][ng], ah[mt], bh[ng][0], bh[ng][1]);
                    MMA16816(acc[mt][ng], ah[mt], bl[ng][0], bl[ng][1]);
                    MMA16816(acc[mt][ng], al[mt], bh[ng][0], bh[ng][1]);
                }
        }
        __syncthreads();
    }

    const size_t base = ((size_t)(c * NH_ + h)) * HD_ * NST_;
#pragma unroll
    for (int mt = 0; mt < 2; mt++) {
        const int row = warpM * 32 + mt * 16 + (lane >> 2);
#pragma unroll
        for (int ng = 0; ng < 4; ng++) {
            const int col = warpN * 32 + ng * 8 + (lane & 3) * 2;
            *(float2*)&g_states[base + (size_t)row * NST_ + col] =
                make_float2(acc[mt][ng][0], acc[mt][ng][1]);
            *(float2*)&g_states[base + (size_t)(row + 8) * NST_ + col] =
                make_float2(acc[mt][ng][2], acc[mt][ng][3]);
        }
    }
}

__global__ void chunkscan_kernel()
{
    const int idx = blockIdx.x * blockDim.x + threadIdx.x;
    if (idx >= NH_ * HD_ * NST_) return;
    const int h = idx / (HD_ * NST_);
    const int rem = idx % (HD_ * NST_);
    float carry = 0.f;
#pragma unroll
    for (int c = 0; c < NC_; c++) {
        const size_t off = ((size_t)(c * NH_ + h)) * HD_ * NST_ + rem;
        g_prev[off] = carry;
        const float dec = __expf(g_dAc[(c * CH_ + CH_ - 1) * NH_ + h]);
        carry = carry * dec + g_states[off];
    }
}

// ---------------------------------------------------------------------------
// ydiag via mma.sync split bf16 (unchanged)
// ---------------------------------------------------------------------------
#define YD_MH 0
#define YD_ML 2560
#define YD_XH 5120
#define YD_XL 7424
#define YD_CH 0
#define YD_CL 4608
#define YD_PH 9216
#define YD_PL 13824

__global__ __launch_bounds__(256) void ydiag_mma(const float* __restrict__ Dp)
{
    const int lt = blockIdx.x, c = blockIdx.y, h = blockIdx.z;
    __shared__ float sdAc[CH_], sdtv[CH_];
    __shared__ __nv_bfloat16 sbuf[18432];
    const int tid = threadIdx.x;
    const int lane = tid & 31, warp = tid >> 5;
    const int warpM = warp & 1, warpN = warp >> 1;
    const int l0 = lt * 64;

    {
        const int gi = (c * CH_ + tid) * NH_ + h;
        sdAc[tid] = g_dAc[gi];
        sdtv[tid] = g_dt[gi];
    }
    __syncthreads();

    float accA[2][2][4], acc2[2][2][4];
#pragma unroll
    for (int i = 0; i < 2; i++)
#pragma unroll
        for (int j = 0; j < 2; j++)
#pragma unroll
            for (int v = 0; v < 4; v++) { accA[i][j][v] = 0.f; acc2[i][j][v] = 0.f; }

    const int lr = lane & 15;
    const int lc8 = (lane >> 4) * 8;
    const int krB = (lane & 7) | (((lane >> 3) & 1) << 3);
    const int nbB = (lane >> 4) * 8;

    const int smax = l0 + 64;
    for (int s0 = 0; s0 < smax; s0 += 32) {
        {
            const int lrow = tid >> 2;
            const int sseg = (tid & 3) * 8;
            const float dacl = sdAc[l0 + lrow];
            const float* cbp = &g_CB[c * (CH_ * CH_) + (l0 + lrow) * CH_ + s0 + sseg];
            float4 cb0 = *(const float4*)cbp;
            float4 cb1 = *(const float4*)(cbp + 4);
            float cbv[8] = {cb0.x, cb0.y, cb0.z, cb0.w, cb1.x, cb1.y, cb1.z, cb1.w};
#pragma unroll
            for (int j = 0; j < 8; j++) {
                const int s = s0 + sseg + j;
                float v = 0.f;
                if (s <= l0 + lrow) v = cbv[j] * __expf(dacl - sdAc[s]);
                const __nv_bfloat16 hv = __float2bfloat16(v);
                sbuf[YD_MH + lrow * 40 + sseg + j] = hv;
                sbuf[YD_ML + lrow * 40 + sseg + j] =
                    __float2bfloat16(v - __bfloat162float(hv));
            }
        }
#pragma unroll
        for (int t = 0; t < 2; t++) {
            const int gi = t * 256 + tid;
            const int row = gi >> 4, p4 = (gi & 15) * 4;
            const float wv = sdtv[s0 + row];
            float4 v = *(const float4*)&g_conv[(size_t)(c * CH_ + s0 + row) * CONVD_ + h * HD_ + p4];
            uint32_t h0, lo0, h1, lo1;
            split2(v.x * wv, v.y * wv, h0, lo0);
            split2(v.z * wv, v.w * wv, h1, lo1);
            uint32_t* dh_ = (uint32_t*)&sbuf[YD_XH + row * 72 + p4];
            uint32_t* dl_ = (uint32_t*)&sbuf[YD_XL + row * 72 + p4];
            dh_[0] = h0; dh_[1] = h1; dl_[0] = lo0; dl_[1] = lo1;
        }
        __syncthreads();
#pragma unroll
        for (int k16 = 0; k16 < 2; k16++) {
            uint32_t ah[2][4], al[2][4];
#pragma unroll
            for (int mt = 0; mt < 2; mt++) {
                const uint32_t ad = su32(
                    &sbuf[YD_MH + (warpM * 32 + mt * 16 + lr) * 40 + k16 * 16 + lc8]);
                LDSM4(ah[mt], ad);
                LDSM4(al[mt], ad + YD_ML * 2);
            }
            uint32_t bh[2][2], bl[2][2];
            {
                const int nc = warpN * 16 + nbB;
                uint32_t r[4];
                const uint32_t bd = su32(&sbuf[YD_XH + (k16 * 16 + krB) * 72 + nc]);
                LDSM4T(r, bd);
                bh[0][0] = r[0]; bh[0][1] = r[1]; bh[1][0] = r[2]; bh[1][1] = r[3];
                LDSM4T(r, bd + (YD_XL - YD_XH) * 2);
                bl[0][0] = r[0]; bl[0][1] = r[1]; bl[1][0] = r[2]; bl[1][1] = r[3];
            }
#pragma unroll
            for (int mt = 0; mt < 2; mt++)
#pragma unroll
                for (int ng = 0; ng < 2; ng++) {
                    MMA16816(accA[mt][ng], ah[mt], bh[ng][0], bh[ng][1]);
                    MMA16816(accA[mt][ng], ah[mt], bl[ng][0], bl[ng][1]);
                    MMA16816(accA[mt][ng], al[mt], bh[ng][0], bh[ng][1]);
                }
        }
        __syncthreads();
    }

    const size_t pbase = ((size_t)(c * NH_ + h)) * HD_ * NST_;
    for (int n0c = 0; n0c < NST_; n0c += 64) {
#pragma unroll
        for (int t = 0; t < 4; t++) {
            const int gi = t * 256 + tid;
            const int row = gi >> 4, n4 = (gi & 15) * 4;
            float4 v = *(const float4*)&g_conv[(size_t)(c * CH_ + l0 + row) * CONVD_ +
                                               HID_ + NST_ + n0c + n4];
            uint32_t h0, lo0, h1, lo1;
            split2(v.x, v.y, h0, lo0);
            split2(v.z, v.w, h1, lo1);
            uint32_t* dh_ = (uint32_t*)&sbuf[YD_CH + row * 72 + n4];
            uint32_t* dl_ = (uint32_t*)&sbuf[YD_CL + row * 72 + n4];
            dh_[0] = h0; dh_[1] = h1; dl_[0] = lo0; dl_[1] = lo1;

            float4 p = *(const float4*)&g_prev[pbase + (size_t)row * NST_ + n0c + n4];
            split2(p.x, p.y, h0, lo0);
            split2(p.z, p.w, h1, lo1);
            uint32_t* ph_ = (uint32_t*)&sbuf[YD_PH + row * 72 + n4];
            uint32_t* pl_ = (uint32_t*)&sbuf[YD_PL + row * 72 + n4];
            ph_[0] = h0; ph_[1] = h1; pl_[0] = lo0; pl_[1] = lo1;
        }
        __syncthreads();
#pragma unroll
        for (int k16 = 0; k16 < 4; k16++) {
            uint32_t ah[2][4], al[2][4];
#pragma unroll
            for (int mt = 0; mt < 2; mt++) {
                const uint32_t ad = su32(
                    &sbuf[YD_CH + (warpM * 32 + mt * 16 + lr) * 72 + k16 * 16 + lc8]);
                LDSM4(ah[mt], ad);
                LDSM4(al[mt], ad + YD_CL * 2);
            }
            uint32_t bh[4], bl[4];
            {
                const uint32_t bd = su32(
                    &sbuf[YD_PH + (warpN * 16 + lr) * 72 + k16 * 16 + lc8]);
                LDSM4(bh, bd);
                LDSM4(bl, bd + (YD_PL - YD_PH) * 2);
            }
#pragma unroll
            for (int mt = 0; mt < 2; mt++)
#pragma unroll
                for (int ng = 0; ng < 2; ng++) {
                    MMA16816(acc2[mt][ng], ah[mt], bh[ng], bh[ng + 2]);
                    MMA16816(acc2[mt][ng], ah[mt], bl[ng], bl[ng + 2]);
                    MMA16816(acc2[mt][ng], al[mt], bh[ng], bh[ng + 2]);
                }
        }
        __syncthreads();
    }

    const float dh = Dp[h];
#pragma unroll
    for (int mt = 0; mt < 2; mt++) {
        const int lrow = warpM * 32 + mt * 16 + (lane >> 2);
#pragma unroll
        for (int ng = 0; ng < 2; ng++) {
            const int col = warpN * 16 + ng * 8 + (lane & 3) * 2;
#pragma unroll
            for (int half = 0; half < 2; half++) {
                const int l = l0 + lrow + half * 8;
                const int t = c * CH_ + l;
                const float el = __expf(sdAc[l]);
                const float2 x2 = *(const float2*)&g_conv[(size_t)t * CONVD_ + h * HD_ + col];
                float2 o;
                o.x = accA[mt][ng][half * 2]     + el * acc2[mt][ng][half * 2]     + x2.x * dh;
                o.y = accA[mt][ng][half * 2 + 1] + el * acc2[mt][ng][half * 2 + 1] + x2.y * dh;
                *(float2*)&g_y[(size_t)t * HID_ + h * HD_ + col] = o;
            }
        }
    }
}

// ---------------------------------------------------------------------------
// gate + RMSNorm, fused fp16 output for out_proj
// ---------------------------------------------------------------------------
__global__ __launch_bounds__(256) void gatenorm_kernel(const float* __restrict__ nw)
{
    const int t = blockIdx.x;
    const int tid = threadIdx.x;
    float vals[16];
    float ss = 0.f;
#pragma unroll
    for (int k = 0; k < 16; k++) {
        const int i = tid + k * 256;
        const float yv = g_y[(size_t)t * HID_ + i];
        const float zv = g_zx[(size_t)t * D_IN_ + i];
        const float v = yv * (zv / (1.f + __expf(-zv)));
        vals[k] = v;
        ss += v * v;
    }
    __shared__ float red[8];
#pragma unroll
    for (int o = 16; o > 0; o >>= 1) ss += __shfl_xor_sync(0xffffffffu, ss, o);
    if ((tid & 31) == 0) red[tid >> 5] = ss;
    __syncthreads();
    if (tid < 8) {
        float v = red[tid];
#pragma unroll
        for (int o = 4; o > 0; o >>= 1) v += __shfl_xor_sync(0xffu, v, o);
        if (tid == 0) red[0] = v;
    }
    __syncthreads();
    const float scale = rsqrtf(red[0] / (float)HID_ + 1e-5f);
#pragma unroll
    for (int k = 0; k < 16; k++) {
        const int i = tid + k * 256;
        g_yh[(size_t)t * HID_ + i] = __float2half_rn(vals[k] * scale * nw[i]);
    }
}

// ---------------------------------------------------------------------------
extern "C" void kernel_launch(void* const* d_in, const int* in_sizes, int n_in,
                              void* d_out, int out_size)
{
    const float* x       = (const float*)d_in[0];
    const float* in_w    = (const float*)d_in[1];
    const float* conv_w  = (const float*)d_in[2];
    const float* dt_bias = (const float*)d_in[3];
    const float* A_log   = (const float*)d_in[4];
    const float* Dp      = (const float*)d_in[5];
    const float* norm_w  = (const float*)d_in[6];
    const float* out_w   = (const float*)d_in[7];
    float* out = (float*)d_out;

    float *zx, *conv, *cb;
    __half *xh, *wih, *yh, *woh;
    cudaGetSymbolAddress((void**)&zx, g_zx);
    cudaGetSymbolAddress((void**)&conv, g_conv);
    cudaGetSymbolAddress((void**)&cb, g_CB);
    cudaGetSymbolAddress((void**)&xh, g_xh);
    cudaGetSymbolAddress((void**)&wih, g_wih);
    cudaGetSymbolAddress((void**)&yh, g_yh);
    cudaGetSymbolAddress((void**)&woh, g_woh);

    cudaFuncSetAttribute(gemm_mma, cudaFuncAttributeMaxDynamicSharedMemorySize,
                         GM_SMEM_TOTAL);

    // 0) fp16 rounds for in_proj operands
    {
        const int n4s = S_LEN * DIM_ / 4;
        round_f16<<<(n4s + 255) / 256, 256>>>(x, xh, n4s, n4s);
        const int n4w = D_IN_ * DIM_ / 4;
        const int n4wt = D_INP_ * DIM_ / 4;
        round_f16<<<(n4wt + 255) / 256, 256>>>(in_w, wih, n4w, n4wt);
    }

    // 1) in_proj
    gemm_mma<<<dim3(D_INP_ / 128, S_LEN / 128), 256, GM_SMEM_TOTAL>>>(
        xh, wih, zx, D_IN_, DIM_);

    // 2) conv1d + SiLU (vectorized)
    conv_silu_kernel<<<(S_LEN * (CONVD_ / 4) + 255) / 256, 256>>>(conv_w);

    // 3) dt / dA
    dt_kernel<<<(S_LEN * NH_ + 255) / 256, 256>>>(dt_bias, A_log);

    // 4) cumsum
    cumsum_kernel<<<dim3(NC_, NH_), CH_>>>();

    // 5) CB per chunk
    gemm128<<<dim3(2, 2, NC_), 256>>>(
        CH_, CH_, NST_,
        conv + HID_ + NST_, CONVD_, CH_ * CONVD_,
        conv + HID_,        CONVD_, CH_ * CONVD_,
        cb, CH_, CH_ * CH_);

    // 6) states (mma)
    states_mma<<<dim3(NC_, NH_), 256>>>();

    // 7) inter-chunk scan
    chunkscan_kernel<<<(NH_ * HD_ * NST_) / 256, 256>>>();

    // 8) y_diag + y_off + D-skip (mma)
    ydiag_mma<<<dim3(4, NC_, NH_), 256>>>(Dp);

    // 9) gate + RMSNorm (+ fused fp16 round)
    gatenorm_kernel<<<S_LEN, 256>>>(norm_w);

    // 10) out_proj
    {
        const int n4o = DIM_ * HID_ / 4;
        round_f16<<<(n4o + 255) / 256, 256>>>(out_w, woh, n4o, n4o);
    }
    gemm_mma<<<dim3(DIM_ / 128, S_LEN / 128), 256, GM_SMEM_TOTAL>>>(
        yh, woh, out, DIM_, HID_);
}

// round 11
// speedup vs baseline: 8.5362x; 1.0886x over previous
#include <cuda_runtime.h>
#include <cuda_bf16.h>
#include <cuda_fp16.h>
#include <stdint.h>
#include <math.h>

// ---------------------------------------------------------------------------
// Mamba2-style SSD block. Round 9: conv_silu weight-load coalescing fix
// (float4 taps), GEMM BK=64 double-buffer (half the syncs). Rest = R8.
// ---------------------------------------------------------------------------

#define S_LEN   4096
#define DIM_    2048
#define HID_    4096
#define D_IN_   8512
#define D_INP_  8576
#define CONVD_  4352
#define NH_     64
#define HD_     64
#define NST_    128
#define CH_     256
#define NC_     16

__device__ float g_zx[(size_t)S_LEN * D_IN_];
__device__ float g_conv[(size_t)S_LEN * CONVD_];
__device__ float g_dt[S_LEN * NH_];
__device__ float g_dAc[S_LEN * NH_];
__device__ float g_CB[NC_ * CH_ * CH_];
__device__ float g_states[NC_ * NH_ * HD_ * NST_];
__device__ float g_prev[NC_ * NH_ * HD_ * NST_];
__device__ float g_y[(size_t)S_LEN * HID_];

// fp16 operands (single precision pass)
__device__ __half g_xh[(size_t)S_LEN * DIM_];
__device__ __half g_wih[(size_t)D_INP_ * DIM_];
__device__ __half g_yh[(size_t)S_LEN * HID_];
__device__ __half g_woh[(size_t)DIM_ * HID_];

// ---------------------------------------------------------------------------
__device__ __forceinline__ uint32_t su32(const void* p) {
    uint32_t a;
    asm("{ .reg .u64 t; cvta.to.shared.u64 t, %1; cvt.u32.u64 %0, t; }"
        : "=r"(a) : "l"(p));
    return a;
}

__device__ __forceinline__ void cpasync16(uint32_t dst, const void* src) {
    asm volatile("cp.async.cg.shared.global [%0], [%1], 16;" :: "r"(dst), "l"(src));
}
#define CP_COMMIT() asm volatile("cp.async.commit_group;" ::: "memory")
#define CP_WAIT1()  asm volatile("cp.async.wait_group 1;" ::: "memory")

#define LDSM4(r, addr) \
    asm volatile("ldmatrix.sync.aligned.m8n8.x4.shared.b16 {%0,%1,%2,%3}, [%4];" \
        : "=r"((r)[0]), "=r"((r)[1]), "=r"((r)[2]), "=r"((r)[3]) : "r"(addr))

#define LDSM4T(r, addr) \
    asm volatile("ldmatrix.sync.aligned.m8n8.x4.trans.shared.b16 {%0,%1,%2,%3}, [%4];" \
        : "=r"((r)[0]), "=r"((r)[1]), "=r"((r)[2]), "=r"((r)[3]) : "r"(addr))

// bf16 mma (mid-section kernels)
#define MMA16816(d, a, b0, b1) \
    asm volatile("mma.sync.aligned.m16n8k16.row.col.f32.bf16.bf16.f32 " \
        "{%0,%1,%2,%3}, {%4,%5,%6,%7}, {%8,%9}, {%0,%1,%2,%3};" \
        : "+f"((d)[0]), "+f"((d)[1]), "+f"((d)[2]), "+f"((d)[3]) \
        : "r"((a)[0]), "r"((a)[1]), "r"((a)[2]), "r"((a)[3]), "r"(b0), "r"(b1))

// fp16 mma (big GEMMs)
#define MMA16816H(d, a, b0, b1) \
    asm volatile("mma.sync.aligned.m16n8k16.row.col.f32.f16.f16.f32 " \
        "{%0,%1,%2,%3}, {%4,%5,%6,%7}, {%8,%9}, {%0,%1,%2,%3};" \
        : "+f"((d)[0]), "+f"((d)[1]), "+f"((d)[2]), "+f"((d)[3]) \
        : "r"((a)[0]), "r"((a)[1]), "r"((a)[2]), "r"((a)[3]), "r"(b0), "r"(b1))

// fp32x2 -> packed bf16x2 hi + lo (mid-section)
__device__ __forceinline__ void split2(float a, float b, uint32_t& hi, uint32_t& lo) {
    __nv_bfloat16 h0 = __float2bfloat16(a), h1 = __float2bfloat16(b);
    __nv_bfloat16 m0 = __float2bfloat16(a - __bfloat162float(h0));
    __nv_bfloat16 m1 = __float2bfloat16(b - __bfloat162float(h1));
    __nv_bfloat162 H = __halves2bfloat162(h0, h1), L = __halves2bfloat162(m0, m1);
    hi = *(uint32_t*)&H;
    lo = *(uint32_t*)&L;
}

// ---------------------------------------------------------------------------
// fp16 single-pass GEMM: C[M,N] = Ah[M,K] @ Bh[Npad,K]^T
// 128x128 CTA, BK=64, 2-stage double buffer, 256 threads, warps 4(M)x2(N).
// ---------------------------------------------------------------------------
#define PAD_K       72                      // 64 + 8 pad, elems per smem row
#define SUB_BYTES   (128 * PAD_K * 2)       // 18432
#define STAGE_BYTES (2 * SUB_BYTES)         // 36864: Ah, Bh
#define GM_SMEM_TOTAL (2 * STAGE_BYTES)     // 73728

__global__ __launch_bounds__(256, 1) void gemm_mma(
    const __half* __restrict__ Ah, const __half* __restrict__ Bh,
    float* __restrict__ C, int N, int K)
{
    extern __shared__ char smem[];
    const uint32_t sb = su32(smem);
    const int tid = threadIdx.x;
    const int lane = tid & 31;
    const int warp = tid >> 5;
    const int warpM = warp & 3;
    const int warpN = warp >> 2;
    const int m0 = blockIdx.y * 128, n0 = blockIdx.x * 128;

    float acc[2][8][4];
#pragma unroll
    for (int i = 0; i < 2; i++)
#pragma unroll
        for (int j = 0; j < 8; j++)
#pragma unroll
            for (int v = 0; v < 4; v++) acc[i][j][v] = 0.f;

    auto load_chunk = [&](int i, int s) {
        const size_t k0 = (size_t)i * 64;
#pragma unroll
        for (int t = 0; t < 8; t++) {
            const int idx = t * 256 + tid;        // 0..2047
            const int sub = idx >> 10;            // 0..1
            const int r = (idx >> 3) & 127;
            const int cs = idx & 7;
            const uint32_t d = sb + s * STAGE_BYTES + sub * SUB_BYTES
                             + (uint32_t)(r * PAD_K + cs * 8) * 2;
            const __half* bp = (sub == 0) ? Ah : Bh;
            const int rg = (sub == 0) ? (m0 + r) : (n0 + r);
            cpasync16(d, bp + (size_t)rg * K + k0 + cs * 8);
        }
    };

    const int nch = K >> 6;
    load_chunk(0, 0); CP_COMMIT();
    load_chunk(1, 1); CP_COMMIT();

    const int lr = lane & 15;
    const int lc8 = (lane >> 4) * 8;

    for (int i = 0; i < nch; i++) {
        const int s = i & 1;
        CP_WAIT1();
        __syncthreads();

        const uint32_t aB = sb + s * STAGE_BYTES;
        const uint32_t bB = aB + SUB_BYTES;
#pragma unroll
        for (int k16 = 0; k16 < 4; k16++) {
            const int kof = k16 * 16 + lc8;
            uint32_t a[2][4];
#pragma unroll
            for (int mt = 0; mt < 2; mt++) {
                const uint32_t ad = aB + (uint32_t)((warpM * 32 + mt * 16 + lr) * PAD_K + kof) * 2;
                LDSM4(a[mt], ad);
            }
            uint32_t b[4][4];
#pragma unroll
            for (int ng = 0; ng < 4; ng++) {
                const uint32_t bd = bB + (uint32_t)((warpN * 64 + ng * 16 + lr) * PAD_K + kof) * 2;
                LDSM4(b[ng], bd);
            }
#pragma unroll
            for (int mt = 0; mt < 2; mt++)
#pragma unroll
                for (int nt = 0; nt < 8; nt++) {
                    const int ng = nt >> 1, sel = nt & 1;
                    MMA16816H(acc[mt][nt], a[mt], b[ng][sel], b[ng][sel + 2]);
                }
        }
        __syncthreads();
        if (i + 2 < nch) load_chunk(i + 2, s);
        CP_COMMIT();
    }

#pragma unroll
    for (int mt = 0; mt < 2; mt++) {
        const int row = m0 + warpM * 32 + mt * 16 + (lane >> 2);
#pragma unroll
        for (int nt = 0; nt < 8; nt++) {
            const int col = n0 + warpN * 64 + nt * 8 + (lane & 3) * 2;
            if (col < N) {
                *(float2*)&C[(size_t)row * N + col] =
                    make_float2(acc[mt][nt][0], acc[mt][nt][1]);
                *(float2*)&C[(size_t)(row + 8) * N + col] =
                    make_float2(acc[mt][nt][2], acc[mt][nt][3]);
            }
        }
    }
}

// fp32 -> fp16 single round; zero-pads beyond n4_src
__global__ void round_f16(const float* __restrict__ src,
                          __half* __restrict__ hi, int n4_src, int n4_tot)
{
    const int i = blockIdx.x * blockDim.x + threadIdx.x;
    if (i >= n4_tot) return;
    float4 v = make_float4(0.f, 0.f, 0.f, 0.f);
    if (i < n4_src) v = ((const float4*)src)[i];
    __half2 a = __halves2half2(__float2half_rn(v.x), __float2half_rn(v.y));
    __half2 b = __halves2half2(__float2half_rn(v.z), __float2half_rn(v.w));
    ((uint32_t*)hi)[2 * i] = *(uint32_t*)&a;
    ((uint32_t*)hi)[2 * i + 1] = *(uint32_t*)&b;
}

// ---------------------------------------------------------------------------
// fp32 tiled SGEMM (small CB batch only): C = A @ B^T
// ---------------------------------------------------------------------------
__global__ __launch_bounds__(256) void gemm128(
    int M, int N, int K,
    const float* __restrict__ A, int lda, int strideA,
    const float* __restrict__ B, int ldb, int strideB,
    float* __restrict__ C, int ldc, int strideC)
{
    __shared__ float As[8 * 128];
    __shared__ float Bs[8 * 128];
    const int bz = blockIdx.z;
    A += (size_t)bz * strideA;
    B += (size_t)bz * strideB;
    C += (size_t)bz * strideC;
    const int m0 = blockIdx.y * 128;
    const int n0 = blockIdx.x * 128;
    const int tid = threadIdx.x;
    const int lrow = tid >> 1;
    const int lseg = (tid & 1) * 4;
    const int ty = tid >> 4;
    const int tx = tid & 15;

    float acc[8][8];
#pragma unroll
    for (int i = 0; i < 8; i++)
#pragma unroll
        for (int j = 0; j < 8; j++) acc[i][j] = 0.f;

    const float* aptr = A + (size_t)(m0 + lrow) * lda + lseg;
    const float* bptr = B + (size_t)(n0 + lrow) * ldb + lseg;

    for (int k0 = 0; k0 < K; k0 += 8) {
        float4 a4 = *(const float4*)(aptr + k0);
        float4 b4 = *(const float4*)(bptr + k0);
        As[(lseg + 0) * 128 + lrow] = a4.x;
        As[(lseg + 1) * 128 + lrow] = a4.y;
        As[(lseg + 2) * 128 + lrow] = a4.z;
        As[(lseg + 3) * 128 + lrow] = a4.w;
        Bs[(lseg + 0) * 128 + lrow] = b4.x;
        Bs[(lseg + 1) * 128 + lrow] = b4.y;
        Bs[(lseg + 2) * 128 + lrow] = b4.z;
        Bs[(lseg + 3) * 128 + lrow] = b4.w;
        __syncthreads();
#pragma unroll
        for (int k = 0; k < 8; k++) {
            float ar[8], br[8];
            *(float4*)&ar[0] = *(const float4*)&As[k * 128 + ty * 8];
            *(float4*)&ar[4] = *(const float4*)&As[k * 128 + ty * 8 + 4];
            *(float4*)&br[0] = *(const float4*)&Bs[k * 128 + tx * 8];
            *(float4*)&br[4] = *(const float4*)&Bs[k * 128 + tx * 8 + 4];
#pragma unroll
            for (int i = 0; i < 8; i++)
#pragma unroll
                for (int j = 0; j < 8; j++)
                    acc[i][j] = fmaf(ar[i], br[j], acc[i][j]);
        }
        __syncthreads();
    }

#pragma unroll
    for (int i = 0; i < 8; i++) {
        const int m = m0 + ty * 8 + i;
#pragma unroll
        for (int j4 = 0; j4 < 8; j4 += 4) {
            const int n = n0 + tx * 8 + j4;
            *(float4*)(C + (size_t)m * ldc + n) =
                make_float4(acc[i][j4], acc[i][j4 + 1], acc[i][j4 + 2], acc[i][j4 + 3]);
        }
    }
}

// ---------------------------------------------------------------------------
// conv1d + SiLU, 4 channels per thread, coalesced float4 weight loads
// ---------------------------------------------------------------------------
__global__ void conv_silu_kernel(const float* __restrict__ w)
{
    const int idx = blockIdx.x * blockDim.x + threadIdx.x;
    const int NQ = CONVD_ / 4;
    if (idx >= S_LEN * NQ) return;
    const int c4 = idx % NQ;
    const int t = idx / NQ;

    const float4 w0 = *(const float4*)&w[(c4 * 4 + 0) * 4];
    const float4 w1 = *(const float4*)&w[(c4 * 4 + 1) * 4];
    const float4 w2 = *(const float4*)&w[(c4 * 4 + 2) * 4];
    const float4 w3 = *(const float4*)&w[(c4 * 4 + 3) * 4];
    const float wa[4][4] = {{w0.x, w0.y, w0.z, w0.w},
                            {w1.x, w1.y, w1.z, w1.w},
                            {w2.x, w2.y, w2.z, w2.w},
                            {w3.x, w3.y, w3.z, w3.w}};

    float4 acc = make_float4(0.f, 0.f, 0.f, 0.f);
#pragma unroll
    for (int i = 0; i < 4; i++) {
        const int tt = t - 3 + i;
        if (tt >= 0) {
            float4 xv = *(const float4*)&g_zx[(size_t)tt * D_IN_ + HID_ + c4 * 4];
            acc.x += xv.x * wa[0][i];
            acc.y += xv.y * wa[1][i];
            acc.z += xv.z * wa[2][i];
            acc.w += xv.w * wa[3][i];
        }
    }
    float4 o;
    o.x = acc.x / (1.f + __expf(-acc.x));
    o.y = acc.y / (1.f + __expf(-acc.y));
    o.z = acc.z / (1.f + __expf(-acc.z));
    o.w = acc.w / (1.f + __expf(-acc.w));
    *(float4*)&g_conv[(size_t)t * CONVD_ + c4 * 4] = o;
}

__global__ void dt_kernel(const float* __restrict__ dt_bias,
                          const float* __restrict__ A_log)
{
    const int idx = blockIdx.x * blockDim.x + threadIdx.x;
    if (idx >= S_LEN * NH_) return;
    const int h = idx % NH_;
    const int t = idx / NH_;
    const float raw = g_zx[(size_t)t * D_IN_ + (HID_ + CONVD_) + h] + dt_bias[h];
    const float dt = (raw > 20.f) ? raw : log1pf(__expf(raw));
    g_dt[idx] = dt;
    g_dAc[idx] = dt * (-__expf(A_log[h]));
}

__global__ __launch_bounds__(CH_) void cumsum_kernel()
{
    const int c = blockIdx.x, h = blockIdx.y;
    const int l = threadIdx.x;
    __shared__ float sbuf[CH_];
    const int gi = (c * CH_ + l) * NH_ + h;
    sbuf[l] = g_dAc[gi];
    __syncthreads();
    for (int off = 1; off < CH_; off <<= 1) {
        const float add = (l >= off) ? sbuf[l - off] : 0.f;
        __syncthreads();
        sbuf[l] += add;
        __syncthreads();
    }
    g_dAc[gi] = sbuf[l];
}

// ---------------------------------------------------------------------------
// states via mma.sync split bf16 (unchanged)
// ---------------------------------------------------------------------------
__global__ __launch_bounds__(256) void states_mma()
{
    const int c = blockIdx.x, h = blockIdx.y;
    __shared__ float sdec[CH_];
    __shared__ __nv_bfloat16 sA[2][32 * 72];
    __shared__ __nv_bfloat16 sB[2][32 * 136];
    const int tid = threadIdx.x;
    const int lane = tid & 31, warp = tid >> 5;
    const int warpM = warp & 1, warpN = warp >> 1;

    {
        const float dalast = g_dAc[(c * CH_ + CH_ - 1) * NH_ + h];
        const int gi = (c * CH_ + tid) * NH_ + h;
        sdec[tid] = g_dt[gi] * __expf(dalast - g_dAc[gi]);
    }
    __syncthreads();

    float acc[2][4][4];
#pragma unroll
    for (int i = 0; i < 2; i++)
#pragma unroll
        for (int j = 0; j < 4; j++)
#pragma unroll
            for (int v = 0; v < 4; v++) acc[i][j][v] = 0.f;

    const int krA = (lane & 7) | ((lane >> 4) << 3);
    const int mbA = ((lane >> 3) & 1) * 8;
    const int krB = (lane & 7) | (((lane >> 3) & 1) << 3);
    const int nbB = (lane >> 4) * 8;

    for (int s0 = 0; s0 < CH_; s0 += 32) {
#pragma unroll
        for (int t = 0; t < 2; t++) {
            const int gi = t * 256 + tid;
            const int row = gi >> 4, p4 = (gi & 15) * 4;
            const float wv = sdec[s0 + row];
            float4 v = *(const float4*)&g_conv[(size_t)(c * CH_ + s0 + row) * CONVD_ + h * HD_ + p4];
            uint32_t h0, l0, h1, l1;
            split2(v.x * wv, v.y * wv, h0, l0);
            split2(v.z * wv, v.w * wv, h1, l1);
            uint32_t* dh_ = (uint32_t*)&sA[0][row * 72 + p4];
            uint32_t* dl_ = (uint32_t*)&sA[1][row * 72 + p4];
            dh_[0] = h0; dh_[1] = h1; dl_[0] = l0; dl_[1] = l1;
        }
#pragma unroll
        for (int t = 0; t < 4; t++) {
            const int gi = t * 256 + tid;
            const int row = gi >> 5, n4 = (gi & 31) * 4;
            float4 v = *(const float4*)&g_conv[(size_t)(c * CH_ + s0 + row) * CONVD_ + HID_ + n4];
            uint32_t h0, l0, h1, l1;
            split2(v.x, v.y, h0, l0);
            split2(v.z, v.w, h1, l1);
            uint32_t* dh_ = (uint32_t*)&sB[0][row * 136 + n4];
            uint32_t* dl_ = (uint32_t*)&sB[1][row * 136 + n4];
            dh_[0] = h0; dh_[1] = h1; dl_[0] = l0; dl_[1] = l1;
        }
        __syncthreads();
#pragma unroll
        for (int k16 = 0; k16 < 2; k16++) {
            uint32_t ah[2][4], al[2][4];
#pragma unroll
            for (int mt = 0; mt < 2; mt++) {
                const int mc = warpM * 32 + mt * 16 + mbA;
                const uint32_t ad = su32(&sA[0][(k16 * 16 + krA) * 72 + mc]);
                LDSM4T(ah[mt], ad);
                LDSM4T(al[mt], ad + 32 * 72 * 2);
            }
            uint32_t bh[4][2], bl[4][2];
#pragma unroll
            for (int nh2 = 0; nh2 < 2; nh2++) {
                const int nc = warpN * 32 + nh2 * 16 + nbB;
                uint32_t r[4];
                const uint32_t bd = su32(&sB[0][(k16 * 16 + krB) * 136 + nc]);
                LDSM4T(r, bd);
                bh[nh2 * 2][0] = r[0]; bh[nh2 * 2][1] = r[1];
                bh[nh2 * 2 + 1][0] = r[2]; bh[nh2 * 2 + 1][1] = r[3];
                LDSM4T(r, bd + 32 * 136 * 2);
                bl[nh2 * 2][0] = r[0]; bl[nh2 * 2][1] = r[1];
                bl[nh2 * 2 + 1][0] = r[2]; bl[nh2 * 2 + 1][1] = r[3];
            }
#pragma unroll
            for (int mt = 0; mt < 2; mt++)
#pragma unroll
                for (int ng = 0; ng < 4; ng++) {
                    MMA16816(acc[mt][ng], ah[mt], bh[ng][0], bh[ng][1]);
                    MMA16816(acc[mt][ng], ah[mt], bl[ng][0], bl[ng][1]);
                    MMA16816(acc[mt][ng], al[mt], bh[ng][0], bh[ng][1]);
                }
        }
        __syncthreads();
    }

    const size_t base = ((size_t)(c * NH_ + h)) * HD_ * NST_;
#pragma unroll
    for (int mt = 0; mt < 2; mt++) {
        const int row = warpM * 32 + mt * 16 + (lane >> 2);
#pragma unroll
        for (int ng = 0; ng < 4; ng++) {
            const int col = warpN * 32 + ng * 8 + (lane & 3) * 2;
            *(float2*)&g_states[base + (size_t)row * NST_ + col] =
                make_float2(acc[mt][ng][0], acc[mt][ng][1]);
            *(float2*)&g_states[base + (size_t)(row + 8) * NST_ + col] =
                make_float2(acc[mt][ng][2], acc[mt][ng][3]);
        }
    }
}

__global__ void chunkscan_kernel()
{
    const int idx = blockIdx.x * blockDim.x + threadIdx.x;
    if (idx >= NH_ * HD_ * NST_) return;
    const int h = idx / (HD_ * NST_);
    const int rem = idx % (HD_ * NST_);
    float carry = 0.f;
#pragma unroll
    for (int c = 0; c < NC_; c++) {
        const size_t off = ((size_t)(c * NH_ + h)) * HD_ * NST_ + rem;
        g_prev[off] = carry;
        const float dec = __expf(g_dAc[(c * CH_ + CH_ - 1) * NH_ + h]);
        carry = carry * dec + g_states[off];
    }
}

// ---------------------------------------------------------------------------
// ydiag via mma.sync split bf16 (unchanged)
// ---------------------------------------------------------------------------
#define YD_MH 0
#define YD_ML 2560
#define YD_XH 5120
#define YD_XL 7424
#define YD_CH 0
#define YD_CL 4608
#define YD_PH 9216
#define YD_PL 13824

__global__ __launch_bounds__(256) void ydiag_mma(const float* __restrict__ Dp)
{
    const int lt = blockIdx.x, c = blockIdx.y, h = blockIdx.z;
    __shared__ float sdAc[CH_], sdtv[CH_];
    __shared__ __nv_bfloat16 sbuf[18432];
    const int tid = threadIdx.x;
    const int lane = tid & 31, warp = tid >> 5;
    const int warpM = warp & 1, warpN = warp >> 1;
    const int l0 = lt * 64;

    {
        const int gi = (c * CH_ + tid) * NH_ + h;
        sdAc[tid] = g_dAc[gi];
        sdtv[tid] = g_dt[gi];
    }
    __syncthreads();

    float accA[2][2][4], acc2[2][2][4];
#pragma unroll
    for (int i = 0; i < 2; i++)
#pragma unroll
        for (int j = 0; j < 2; j++)
#pragma unroll
            for (int v = 0; v < 4; v++) { accA[i][j][v] = 0.f; acc2[i][j][v] = 0.f; }

    const int lr = lane & 15;
    const int lc8 = (lane >> 4) * 8;
    const int krB = (lane & 7) | (((lane >> 3) & 1) << 3);
    const int nbB = (lane >> 4) * 8;

    const int smax = l0 + 64;
    for (int s0 = 0; s0 < smax; s0 += 32) {
        {
            const int lrow = tid >> 2;
            const int sseg = (tid & 3) * 8;
            const float dacl = sdAc[l0 + lrow];
            const float* cbp = &g_CB[c * (CH_ * CH_) + (l0 + lrow) * CH_ + s0 + sseg];
            float4 cb0 = *(const float4*)cbp;
            float4 cb1 = *(const float4*)(cbp + 4);
            float cbv[8] = {cb0.x, cb0.y, cb0.z, cb0.w, cb1.x, cb1.y, cb1.z, cb1.w};
#pragma unroll
            for (int j = 0; j < 8; j++) {
                const int s = s0 + sseg + j;
                float v = 0.f;
                if (s <= l0 + lrow) v = cbv[j] * __expf(dacl - sdAc[s]);
                const __nv_bfloat16 hv = __float2bfloat16(v);
                sbuf[YD_MH + lrow * 40 + sseg + j] = hv;
                sbuf[YD_ML + lrow * 40 + sseg + j] =
                    __float2bfloat16(v - __bfloat162float(hv));
            }
        }
#pragma unroll
        for (int t = 0; t < 2; t++) {
            const int gi = t * 256 + tid;
            const int row = gi >> 4, p4 = (gi & 15) * 4;
            const float wv = sdtv[s0 + row];
            float4 v = *(const float4*)&g_conv[(size_t)(c * CH_ + s0 + row) * CONVD_ + h * HD_ + p4];
            uint32_t h0, lo0, h1, lo1;
            split2(v.x * wv, v.y * wv, h0, lo0);
            split2(v.z * wv, v.w * wv, h1, lo1);
            uint32_t* dh_ = (uint32_t*)&sbuf[YD_XH + row * 72 + p4];
            uint32_t* dl_ = (uint32_t*)&sbuf[YD_XL + row * 72 + p4];
            dh_[0] = h0; dh_[1] = h1; dl_[0] = lo0; dl_[1] = lo1;
        }
        __syncthreads();
#pragma unroll
        for (int k16 = 0; k16 < 2; k16++) {
            uint32_t ah[2][4], al[2][4];
#pragma unroll
            for (int mt = 0; mt < 2; mt++) {
                const uint32_t ad = su32(
                    &sbuf[YD_MH + (warpM * 32 + mt * 16 + lr) * 40 + k16 * 16 + lc8]);
                LDSM4(ah[mt], ad);
                LDSM4(al[mt], ad + YD_ML * 2);
            }
            uint32_t bh[2][2], bl[2][2];
            {
                const int nc = warpN * 16 + nbB;
                uint32_t r[4];
                const uint32_t bd = su32(&sbuf[YD_XH + (k16 * 16 + krB) * 72 + nc]);
                LDSM4T(r, bd);
                bh[0][0] = r[0]; bh[0][1] = r[1]; bh[1][0] = r[2]; bh[1][1] = r[3];
                LDSM4T(r, bd + (YD_XL - YD_XH) * 2);
                bl[0][0] = r[0]; bl[0][1] = r[1]; bl[1][0] = r[2]; bl[1][1] = r[3];
            }
#pragma unroll
            for (int mt = 0; mt < 2; mt++)
#pragma unroll
                for (int ng = 0; ng < 2; ng++) {
                    MMA16816(accA[mt][ng], ah[mt], bh[ng][0], bh[ng][1]);
                    MMA16816(accA[mt][ng], ah[mt], bl[ng][0], bl[ng][1]);
                    MMA16816(accA[mt][ng], al[mt], bh[ng][0], bh[ng][1]);
                }
        }
        __syncthreads();
    }

    const size_t pbase = ((size_t)(c * NH_ + h)) * HD_ * NST_;
    for (int n0c = 0; n0c < NST_; n0c += 64) {
#pragma unroll
        for (int t = 0; t < 4; t++) {
            const int gi = t * 256 + tid;
            const int row = gi >> 4, n4 = (gi & 15) * 4;
            float4 v = *(const float4*)&g_conv[(size_t)(c * CH_ + l0 + row) * CONVD_ +
                                               HID_ + NST_ + n0c + n4];
            uint32_t h0, lo0, h1, lo1;
            split2(v.x, v.y, h0, lo0);
            split2(v.z, v.w, h1, lo1);
            uint32_t* dh_ = (uint32_t*)&sbuf[YD_CH + row * 72 + n4];
            uint32_t* dl_ = (uint32_t*)&sbuf[YD_CL + row * 72 + n4];
            dh_[0] = h0; dh_[1] = h1; dl_[0] = lo0; dl_[1] = lo1;

            float4 p = *(const float4*)&g_prev[pbase + (size_t)row * NST_ + n0c + n4];
            split2(p.x, p.y, h0, lo0);
            split2(p.z, p.w, h1, lo1);
            uint32_t* ph_ = (uint32_t*)&sbuf[YD_PH + row * 72 + n4];
            uint32_t* pl_ = (uint32_t*)&sbuf[YD_PL + row * 72 + n4];
            ph_[0] = h0; ph_[1] = h1; pl_[0] = lo0; pl_[1] = lo1;
        }
        __syncthreads();
#pragma unroll
        for (int k16 = 0; k16 < 4; k16++) {
            uint32_t ah[2][4], al[2][4];
#pragma unroll
            for (int mt = 0; mt < 2; mt++) {
                const uint32_t ad = su32(
                    &sbuf[YD_CH + (warpM * 32 + mt * 16 + lr) * 72 + k16 * 16 + lc8]);
                LDSM4(ah[mt], ad);
                LDSM4(al[mt], ad + YD_CL * 2);
            }
            uint32_t bh[4], bl[4];
            {
                const uint32_t bd = su32(
                    &sbuf[YD_PH + (warpN * 16 + lr) * 72 + k16 * 16 + lc8]);
                LDSM4(bh, bd);
                LDSM4(bl, bd + (YD_PL - YD_PH) * 2);
            }
#pragma unroll
            for (int mt = 0; mt < 2; mt++)
#pragma unroll
                for (int ng = 0; ng < 2; ng++) {
                    MMA16816(acc2[mt][ng], ah[mt], bh[ng], bh[ng + 2]);
                    MMA16816(acc2[mt][ng], ah[mt], bl[ng], bl[ng + 2]);
                    MMA16816(acc2[mt][ng], al[mt], bh[ng], bh[ng + 2]);
                }
        }
        __syncthreads();
    }

    const float dh = Dp[h];
#pragma unroll
    for (int mt = 0; mt < 2; mt++) {
        const int lrow = warpM * 32 + mt * 16 + (lane >> 2);
#pragma unroll
        for (int ng = 0; ng < 2; ng++) {
            const int col = warpN * 16 + ng * 8 + (lane & 3) * 2;
#pragma unroll
            for (int half = 0; half < 2; half++) {
                const int l = l0 + lrow + half * 8;
                const int t = c * CH_ + l;
                const float el = __expf(sdAc[l]);
                const float2 x2 = *(const float2*)&g_conv[(size_t)t * CONVD_ + h * HD_ + col];
                float2 o;
                o.x = accA[mt][ng][half * 2]     + el * acc2[mt][ng][half * 2]     + x2.x * dh;
                o.y = accA[mt][ng][half * 2 + 1] + el * acc2[mt][ng][half * 2 + 1] + x2.y * dh;
                *(float2*)&g_y[(size_t)t * HID_ + h * HD_ + col] = o;
            }
        }
    }
}

// ---------------------------------------------------------------------------
// gate + RMSNorm, fused fp16 output for out_proj
// ---------------------------------------------------------------------------
__global__ __launch_bounds__(256) void gatenorm_kernel(const float* __restrict__ nw)
{
    const int t = blockIdx.x;
    const int tid = threadIdx.x;
    float vals[16];
    float ss = 0.f;
#pragma unroll
    for (int k = 0; k < 16; k++) {
        const int i = tid + k * 256;
        const float yv = g_y[(size_t)t * HID_ + i];
        const float zv = g_zx[(size_t)t * D_IN_ + i];
        const float v = yv * (zv / (1.f + __expf(-zv)));
        vals[k] = v;
        ss += v * v;
    }
    __shared__ float red[8];
#pragma unroll
    for (int o = 16; o > 0; o >>= 1) ss += __shfl_xor_sync(0xffffffffu, ss, o);
    if ((tid & 31) == 0) red[tid >> 5] = ss;
    __syncthreads();
    if (tid < 8) {
        float v = red[tid];
#pragma unroll
        for (int o = 4; o > 0; o >>= 1) v += __shfl_xor_sync(0xffu, v, o);
        if (tid == 0) red[0] = v;
    }
    __syncthreads();
    const float scale = rsqrtf(red[0] / (float)HID_ + 1e-5f);
#pragma unroll
    for (int k = 0; k < 16; k++) {
        const int i = tid + k * 256;
        g_yh[(size_t)t * HID_ + i] = __float2half_rn(vals[k] * scale * nw[i]);
    }
}

// ---------------------------------------------------------------------------
extern "C" void kernel_launch(void* const* d_in, const int* in_sizes, int n_in,
                              void* d_out, int out_size)
{
    const float* x       = (const float*)d_in[0];
    const float* in_w    = (const float*)d_in[1];
    const float* conv_w  = (const float*)d_in[2];
    const float* dt_bias = (const float*)d_in[3];
    const float* A_log   = (const float*)d_in[4];
    const float* Dp      = (const float*)d_in[5];
    const float* norm_w  = (const float*)d_in[6];
    const float* out_w   = (const float*)d_in[7];
    float* out = (float*)d_out;

    float *zx, *conv, *cb;
    __half *xh, *wih, *yh, *woh;
    cudaGetSymbolAddress((void**)&zx, g_zx);
    cudaGetSymbolAddress((void**)&conv, g_conv);
    cudaGetSymbolAddress((void**)&cb, g_CB);
    cudaGetSymbolAddress((void**)&xh, g_xh);
    cudaGetSymbolAddress((void**)&wih, g_wih);
    cudaGetSymbolAddress((void**)&yh, g_yh);
    cudaGetSymbolAddress((void**)&woh, g_woh);

    cudaFuncSetAttribute(gemm_mma, cudaFuncAttributeMaxDynamicSharedMemorySize,
                         GM_SMEM_TOTAL);

    // 0) fp16 rounds for in_proj operands
    {
        const int n4s = S_LEN * DIM_ / 4;
        round_f16<<<(n4s + 255) / 256, 256>>>(x, xh, n4s, n4s);
        const int n4w = D_IN_ * DIM_ / 4;
        const int n4wt = D_INP_ * DIM_ / 4;
        round_f16<<<(n4wt + 255) / 256, 256>>>(in_w, wih, n4w, n4wt);
    }

    // 1) in_proj
    gemm_mma<<<dim3(D_INP_ / 128, S_LEN / 128), 256, GM_SMEM_TOTAL>>>(
        xh, wih, zx, D_IN_, DIM_);

    // 2) conv1d + SiLU
    conv_silu_kernel<<<(S_LEN * (CONVD_ / 4) + 255) / 256, 256>>>(conv_w);

    // 3) dt / dA
    dt_kernel<<<(S_LEN * NH_ + 255) / 256, 256>>>(dt_bias, A_log);

    // 4) cumsum
    cumsum_kernel<<<dim3(NC_, NH_), CH_>>>();

    // 5) CB per chunk
    gemm128<<<dim3(2, 2, NC_), 256>>>(
        CH_, CH_, NST_,
        conv + HID_ + NST_, CONVD_, CH_ * CONVD_,
        conv + HID_,        CONVD_, CH_ * CONVD_,
        cb, CH_, CH_ * CH_);

    // 6) states (mma)
    states_mma<<<dim3(NC_, NH_), 256>>>();

    // 7) inter-chunk scan
    chunkscan_kernel<<<(NH_ * HD_ * NST_) / 256, 256>>>();

    // 8) y_diag + y_off + D-skip (mma)
    ydiag_mma<<<dim3(4, NC_, NH_), 256>>>(Dp);

    // 9) gate + RMSNorm (+ fused fp16 round)
    gatenorm_kernel<<<S_LEN, 256>>>(norm_w);

    // 10) out_proj
    {
        const int n4o = DIM_ * HID_ / 4;
        round_f16<<<(n4o + 255) / 256, 256>>>(out_w, woh, n4o, n4o);
    }
    gemm_mma<<<dim3(DIM_ / 128, S_LEN / 128), 256, GM_SMEM_TOTAL>>>(
        yh, woh, out, DIM_, HID_);
}

// round 13
// speedup vs baseline: 8.9980x; 1.0541x over previous
#include <cuda_runtime.h>
#include <cuda_bf16.h>
#include <cuda_fp16.h>
#include <stdint.h>
#include <math.h>

// ---------------------------------------------------------------------------
// Mamba2-style SSD block. Round 10: states/ydiag switch to single-pass fp16
// mma (was bf16 3-pass); conv_silu time-tiled (8 t per thread, rolling window).
// GEMMs/rest unchanged from R9 (1138us).
// ---------------------------------------------------------------------------

#define S_LEN   4096
#define DIM_    2048
#define HID_    4096
#define D_IN_   8512
#define D_INP_  8576
#define CONVD_  4352
#define NH_     64
#define HD_     64
#define NST_    128
#define CH_     256
#define NC_     16

__device__ float g_zx[(size_t)S_LEN * D_IN_];
__device__ float g_conv[(size_t)S_LEN * CONVD_];
__device__ float g_dt[S_LEN * NH_];
__device__ float g_dAc[S_LEN * NH_];
__device__ float g_CB[NC_ * CH_ * CH_];
__device__ float g_states[NC_ * NH_ * HD_ * NST_];
__device__ float g_prev[NC_ * NH_ * HD_ * NST_];
__device__ float g_y[(size_t)S_LEN * HID_];

__device__ __half g_xh[(size_t)S_LEN * DIM_];
__device__ __half g_wih[(size_t)D_INP_ * DIM_];
__device__ __half g_yh[(size_t)S_LEN * HID_];
__device__ __half g_woh[(size_t)DIM_ * HID_];

// ---------------------------------------------------------------------------
__device__ __forceinline__ uint32_t su32(const void* p) {
    uint32_t a;
    asm("{ .reg .u64 t; cvta.to.shared.u64 t, %1; cvt.u32.u64 %0, t; }"
        : "=r"(a) : "l"(p));
    return a;
}

__device__ __forceinline__ void cpasync16(uint32_t dst, const void* src) {
    asm volatile("cp.async.cg.shared.global [%0], [%1], 16;" :: "r"(dst), "l"(src));
}
#define CP_COMMIT() asm volatile("cp.async.commit_group;" ::: "memory")
#define CP_WAIT1()  asm volatile("cp.async.wait_group 1;" ::: "memory")

#define LDSM4(r, addr) \
    asm volatile("ldmatrix.sync.aligned.m8n8.x4.shared.b16 {%0,%1,%2,%3}, [%4];" \
        : "=r"((r)[0]), "=r"((r)[1]), "=r"((r)[2]), "=r"((r)[3]) : "r"(addr))

#define LDSM4T(r, addr) \
    asm volatile("ldmatrix.sync.aligned.m8n8.x4.trans.shared.b16 {%0,%1,%2,%3}, [%4];" \
        : "=r"((r)[0]), "=r"((r)[1]), "=r"((r)[2]), "=r"((r)[3]) : "r"(addr))

// fp16 mma
#define MMA16816H(d, a, b0, b1) \
    asm volatile("mma.sync.aligned.m16n8k16.row.col.f32.f16.f16.f32 " \
        "{%0,%1,%2,%3}, {%4,%5,%6,%7}, {%8,%9}, {%0,%1,%2,%3};" \
        : "+f"((d)[0]), "+f"((d)[1]), "+f"((d)[2]), "+f"((d)[3]) \
        : "r"((a)[0]), "r"((a)[1]), "r"((a)[2]), "r"((a)[3]), "r"(b0), "r"(b1))

// fp32x2 -> packed fp16x2 (single round)
__device__ __forceinline__ uint32_t pack2h(float a, float b) {
    __half2 H = __halves2half2(__float2half_rn(a), __float2half_rn(b));
    return *(uint32_t*)&H;
}

// ---------------------------------------------------------------------------
// fp16 single-pass GEMM: C[M,N] = Ah[M,K] @ Bh[Npad,K]^T
// 128x128 CTA, BK=64, 2-stage double buffer, 256 threads, warps 4(M)x2(N).
// ---------------------------------------------------------------------------
#define PAD_K       72
#define SUB_BYTES   (128 * PAD_K * 2)
#define STAGE_BYTES (2 * SUB_BYTES)
#define GM_SMEM_TOTAL (2 * STAGE_BYTES)

__global__ __launch_bounds__(256, 1) void gemm_mma(
    const __half* __restrict__ Ah, const __half* __restrict__ Bh,
    float* __restrict__ C, int N, int K)
{
    extern __shared__ char smem[];
    const uint32_t sb = su32(smem);
    const int tid = threadIdx.x;
    const int lane = tid & 31;
    const int warp = tid >> 5;
    const int warpM = warp & 3;
    const int warpN = warp >> 2;
    const int m0 = blockIdx.y * 128, n0 = blockIdx.x * 128;

    float acc[2][8][4];
#pragma unroll
    for (int i = 0; i < 2; i++)
#pragma unroll
        for (int j = 0; j < 8; j++)
#pragma unroll
            for (int v = 0; v < 4; v++) acc[i][j][v] = 0.f;

    auto load_chunk = [&](int i, int s) {
        const size_t k0 = (size_t)i * 64;
#pragma unroll
        for (int t = 0; t < 8; t++) {
            const int idx = t * 256 + tid;
            const int sub = idx >> 10;
            const int r = (idx >> 3) & 127;
            const int cs = idx & 7;
            const uint32_t d = sb + s * STAGE_BYTES + sub * SUB_BYTES
                             + (uint32_t)(r * PAD_K + cs * 8) * 2;
            const __half* bp = (sub == 0) ? Ah : Bh;
            const int rg = (sub == 0) ? (m0 + r) : (n0 + r);
            cpasync16(d, bp + (size_t)rg * K + k0 + cs * 8);
        }
    };

    const int nch = K >> 6;
    load_chunk(0, 0); CP_COMMIT();
    load_chunk(1, 1); CP_COMMIT();

    const int lr = lane & 15;
    const int lc8 = (lane >> 4) * 8;

    for (int i = 0; i < nch; i++) {
        const int s = i & 1;
        CP_WAIT1();
        __syncthreads();

        const uint32_t aB = sb + s * STAGE_BYTES;
        const uint32_t bB = aB + SUB_BYTES;
#pragma unroll
        for (int k16 = 0; k16 < 4; k16++) {
            const int kof = k16 * 16 + lc8;
            uint32_t a[2][4];
#pragma unroll
            for (int mt = 0; mt < 2; mt++) {
                const uint32_t ad = aB + (uint32_t)((warpM * 32 + mt * 16 + lr) * PAD_K + kof) * 2;
                LDSM4(a[mt], ad);
            }
            uint32_t b[4][4];
#pragma unroll
            for (int ng = 0; ng < 4; ng++) {
                const uint32_t bd = bB + (uint32_t)((warpN * 64 + ng * 16 + lr) * PAD_K + kof) * 2;
                LDSM4(b[ng], bd);
            }
#pragma unroll
            for (int mt = 0; mt < 2; mt++)
#pragma unroll
                for (int nt = 0; nt < 8; nt++) {
                    const int ng = nt >> 1, sel = nt & 1;
                    MMA16816H(acc[mt][nt], a[mt], b[ng][sel], b[ng][sel + 2]);
                }
        }
        __syncthreads();
        if (i + 2 < nch) load_chunk(i + 2, s);
        CP_COMMIT();
    }

#pragma unroll
    for (int mt = 0; mt < 2; mt++) {
        const int row = m0 + warpM * 32 + mt * 16 + (lane >> 2);
#pragma unroll
        for (int nt = 0; nt < 8; nt++) {
            const int col = n0 + warpN * 64 + nt * 8 + (lane & 3) * 2;
            if (col < N) {
                *(float2*)&C[(size_t)row * N + col] =
                    make_float2(acc[mt][nt][0], acc[mt][nt][1]);
                *(float2*)&C[(size_t)(row + 8) * N + col] =
                    make_float2(acc[mt][nt][2], acc[mt][nt][3]);
            }
        }
    }
}

// fp32 -> fp16 single round; zero-pads beyond n4_src
__global__ void round_f16(const float* __restrict__ src,
                          __half* __restrict__ hi, int n4_src, int n4_tot)
{
    const int i = blockIdx.x * blockDim.x + threadIdx.x;
    if (i >= n4_tot) return;
    float4 v = make_float4(0.f, 0.f, 0.f, 0.f);
    if (i < n4_src) v = ((const float4*)src)[i];
    ((uint32_t*)hi)[2 * i] = pack2h(v.x, v.y);
    ((uint32_t*)hi)[2 * i + 1] = pack2h(v.z, v.w);
}

// ---------------------------------------------------------------------------
// fp32 tiled SGEMM (small CB batch only): C = A @ B^T
// ---------------------------------------------------------------------------
__global__ __launch_bounds__(256) void gemm128(
    int M, int N, int K,
    const float* __restrict__ A, int lda, int strideA,
    const float* __restrict__ B, int ldb, int strideB,
    float* __restrict__ C, int ldc, int strideC)
{
    __shared__ float As[8 * 128];
    __shared__ float Bs[8 * 128];
    const int bz = blockIdx.z;
    A += (size_t)bz * strideA;
    B += (size_t)bz * strideB;
    C += (size_t)bz * strideC;
    const int m0 = blockIdx.y * 128;
    const int n0 = blockIdx.x * 128;
    const int tid = threadIdx.x;
    const int lrow = tid >> 1;
    const int lseg = (tid & 1) * 4;
    const int ty = tid >> 4;
    const int tx = tid & 15;

    float acc[8][8];
#pragma unroll
    for (int i = 0; i < 8; i++)
#pragma unroll
        for (int j = 0; j < 8; j++) acc[i][j] = 0.f;

    const float* aptr = A + (size_t)(m0 + lrow) * lda + lseg;
    const float* bptr = B + (size_t)(n0 + lrow) * ldb + lseg;

    for (int k0 = 0; k0 < K; k0 += 8) {
        float4 a4 = *(const float4*)(aptr + k0);
        float4 b4 = *(const float4*)(bptr + k0);
        As[(lseg + 0) * 128 + lrow] = a4.x;
        As[(lseg + 1) * 128 + lrow] = a4.y;
        As[(lseg + 2) * 128 + lrow] = a4.z;
        As[(lseg + 3) * 128 + lrow] = a4.w;
        Bs[(lseg + 0) * 128 + lrow] = b4.x;
        Bs[(lseg + 1) * 128 + lrow] = b4.y;
        Bs[(lseg + 2) * 128 + lrow] = b4.z;
        Bs[(lseg + 3) * 128 + lrow] = b4.w;
        __syncthreads();
#pragma unroll
        for (int k = 0; k < 8; k++) {
            float ar[8], br[8];
            *(float4*)&ar[0] = *(const float4*)&As[k * 128 + ty * 8];
            *(float4*)&ar[4] = *(const float4*)&As[k * 128 + ty * 8 + 4];
            *(float4*)&br[0] = *(const float4*)&Bs[k * 128 + tx * 8];
            *(float4*)&br[4] = *(const float4*)&Bs[k * 128 + tx * 8 + 4];
#pragma unroll
            for (int i = 0; i < 8; i++)
#pragma unroll
                for (int j = 0; j < 8; j++)
                    acc[i][j] = fmaf(ar[i], br[j], acc[i][j]);
        }
        __syncthreads();
    }

#pragma unroll
    for (int i = 0; i < 8; i++) {
        const int m = m0 + ty * 8 + i;
#pragma unroll
        for (int j4 = 0; j4 < 8; j4 += 4) {
            const int n = n0 + tx * 8 + j4;
            *(float4*)(C + (size_t)m * ldc + n) =
                make_float4(acc[i][j4], acc[i][j4 + 1], acc[i][j4 + 2], acc[i][j4 + 3]);
        }
    }
}

// ---------------------------------------------------------------------------
// conv1d + SiLU: each thread computes 8 timesteps x 4 channels with a rolling
// 4-row window (11 row loads per 8 outputs).
// ---------------------------------------------------------------------------
#define CT_T 8
__global__ void conv_silu_kernel(const float* __restrict__ w)
{
    const int idx = blockIdx.x * blockDim.x + threadIdx.x;
    const int NQ = CONVD_ / 4;
    if (idx >= (S_LEN / CT_T) * NQ) return;
    const int c4 = idx % NQ;
    const int t0 = (idx / NQ) * CT_T;

    const float4 w0 = *(const float4*)&w[(c4 * 4 + 0) * 4];
    const float4 w1 = *(const float4*)&w[(c4 * 4 + 1) * 4];
    const float4 w2 = *(const float4*)&w[(c4 * 4 + 2) * 4];
    const float4 w3 = *(const float4*)&w[(c4 * 4 + 3) * 4];

    float4 win[4] = {make_float4(0.f, 0.f, 0.f, 0.f), make_float4(0.f, 0.f, 0.f, 0.f),
                     make_float4(0.f, 0.f, 0.f, 0.f), make_float4(0.f, 0.f, 0.f, 0.f)};
#pragma unroll
    for (int i = 0; i < CT_T + 3; i++) {
        const int row = t0 - 3 + i;
        float4 xv = make_float4(0.f, 0.f, 0.f, 0.f);
        if (row >= 0)
            xv = *(const float4*)&g_zx[(size_t)row * D_IN_ + HID_ + c4 * 4];
        win[0] = win[1]; win[1] = win[2]; win[2] = win[3]; win[3] = xv;
        if (i >= 3) {
            float4 a;
            a.x = win[0].x * w0.x + win[1].x * w0.y + win[2].x * w0.z + win[3].x * w0.w;
            a.y = win[0].y * w1.x + win[1].y * w1.y + win[2].y * w1.z + win[3].y * w1.w;
            a.z = win[0].z * w2.x + win[1].z * w2.y + win[2].z * w2.z + win[3].z * w2.w;
            a.w = win[0].w * w3.x + win[1].w * w3.y + win[2].w * w3.z + win[3].w * w3.w;
            float4 o;
            o.x = a.x / (1.f + __expf(-a.x));
            o.y = a.y / (1.f + __expf(-a.y));
            o.z = a.z / (1.f + __expf(-a.z));
            o.w = a.w / (1.f + __expf(-a.w));
            *(float4*)&g_conv[(size_t)(t0 + i - 3) * CONVD_ + c4 * 4] = o;
        }
    }
}

__global__ void dt_kernel(const float* __restrict__ dt_bias,
                          const float* __restrict__ A_log)
{
    const int idx = blockIdx.x * blockDim.x + threadIdx.x;
    if (idx >= S_LEN * NH_) return;
    const int h = idx % NH_;
    const int t = idx / NH_;
    const float raw = g_zx[(size_t)t * D_IN_ + (HID_ + CONVD_) + h] + dt_bias[h];
    const float dt = (raw > 20.f) ? raw : log1pf(__expf(raw));
    g_dt[idx] = dt;
    g_dAc[idx] = dt * (-__expf(A_log[h]));
}

__global__ __launch_bounds__(CH_) void cumsum_kernel()
{
    const int c = blockIdx.x, h = blockIdx.y;
    const int l = threadIdx.x;
    __shared__ float sbuf[CH_];
    const int gi = (c * CH_ + l) * NH_ + h;
    sbuf[l] = g_dAc[gi];
    __syncthreads();
    for (int off = 1; off < CH_; off <<= 1) {
        const float add = (l >= off) ? sbuf[l - off] : 0.f;
        __syncthreads();
        sbuf[l] += add;
        __syncthreads();
    }
    g_dAc[gi] = sbuf[l];
}

// ---------------------------------------------------------------------------
// states via single-pass fp16 mma:
// states[c][h][p][n] = sum_l (x[l,p]*dt[l]*exp(dAlast-dAc[l])) * B[l,n]
// ---------------------------------------------------------------------------
__global__ __launch_bounds__(256) void states_mma()
{
    const int c = blockIdx.x, h = blockIdx.y;
    __shared__ float sdec[CH_];
    __shared__ __half sA[32 * 72];
    __shared__ __half sB[32 * 136];
    const int tid = threadIdx.x;
    const int lane = tid & 31, warp = tid >> 5;
    const int warpM = warp & 1, warpN = warp >> 1;

    {
        const float dalast = g_dAc[(c * CH_ + CH_ - 1) * NH_ + h];
        const int gi = (c * CH_ + tid) * NH_ + h;
        sdec[tid] = g_dt[gi] * __expf(dalast - g_dAc[gi]);
    }
    __syncthreads();

    float acc[2][4][4];
#pragma unroll
    for (int i = 0; i < 2; i++)
#pragma unroll
        for (int j = 0; j < 4; j++)
#pragma unroll
            for (int v = 0; v < 4; v++) acc[i][j][v] = 0.f;

    const int krA = (lane & 7) | ((lane >> 4) << 3);
    const int mbA = ((lane >> 3) & 1) * 8;
    const int krB = (lane & 7) | (((lane >> 3) & 1) << 3);
    const int nbB = (lane >> 4) * 8;

    for (int s0 = 0; s0 < CH_; s0 += 32) {
#pragma unroll
        for (int t = 0; t < 2; t++) {
            const int gi = t * 256 + tid;
            const int row = gi >> 4, p4 = (gi & 15) * 4;
            const float wv = sdec[s0 + row];
            float4 v = *(const float4*)&g_conv[(size_t)(c * CH_ + s0 + row) * CONVD_ + h * HD_ + p4];
            uint32_t* d_ = (uint32_t*)&sA[row * 72 + p4];
            d_[0] = pack2h(v.x * wv, v.y * wv);
            d_[1] = pack2h(v.z * wv, v.w * wv);
        }
#pragma unroll
        for (int t = 0; t < 4; t++) {
            const int gi = t * 256 + tid;
            const int row = gi >> 5, n4 = (gi & 31) * 4;
            float4 v = *(const float4*)&g_conv[(size_t)(c * CH_ + s0 + row) * CONVD_ + HID_ + n4];
            uint32_t* d_ = (uint32_t*)&sB[row * 136 + n4];
            d_[0] = pack2h(v.x, v.y);
            d_[1] = pack2h(v.z, v.w);
        }
        __syncthreads();
#pragma unroll
        for (int k16 = 0; k16 < 2; k16++) {
            uint32_t a[2][4];
#pragma unroll
            for (int mt = 0; mt < 2; mt++) {
                const int mc = warpM * 32 + mt * 16 + mbA;
                LDSM4T(a[mt], su32(&sA[(k16 * 16 + krA) * 72 + mc]));
            }
            uint32_t b[4][2];
#pragma unroll
            for (int nh2 = 0; nh2 < 2; nh2++) {
                const int nc = warpN * 32 + nh2 * 16 + nbB;
                uint32_t r[4];
                LDSM4T(r, su32(&sB[(k16 * 16 + krB) * 136 + nc]));
                b[nh2 * 2][0] = r[0]; b[nh2 * 2][1] = r[1];
                b[nh2 * 2 + 1][0] = r[2]; b[nh2 * 2 + 1][1] = r[3];
            }
#pragma unroll
            for (int mt = 0; mt < 2; mt++)
#pragma unroll
                for (int ng = 0; ng < 4; ng++)
                    MMA16816H(acc[mt][ng], a[mt], b[ng][0], b[ng][1]);
        }
        __syncthreads();
    }

    const size_t base = ((size_t)(c * NH_ + h)) * HD_ * NST_;
#pragma unroll
    for (int mt = 0; mt < 2; mt++) {
        const int row = warpM * 32 + mt * 16 + (lane >> 2);
#pragma unroll
        for (int ng = 0; ng < 4; ng++) {
            const int col = warpN * 32 + ng * 8 + (lane & 3) * 2;
            *(float2*)&g_states[base + (size_t)row * NST_ + col] =
                make_float2(acc[mt][ng][0], acc[mt][ng][1]);
            *(float2*)&g_states[base + (size_t)(row + 8) * NST_ + col] =
                make_float2(acc[mt][ng][2], acc[mt][ng][3]);
        }
    }
}

__global__ void chunkscan_kernel()
{
    const int idx = blockIdx.x * blockDim.x + threadIdx.x;
    if (idx >= NH_ * HD_ * NST_) return;
    const int h = idx / (HD_ * NST_);
    const int rem = idx % (HD_ * NST_);
    float carry = 0.f;
#pragma unroll
    for (int c = 0; c < NC_; c++) {
        const size_t off = ((size_t)(c * NH_ + h)) * HD_ * NST_ + rem;
        g_prev[off] = carry;
        const float dec = __expf(g_dAc[(c * CH_ + CH_ - 1) * NH_ + h]);
        carry = carry * dec + g_states[off];
    }
}

// ---------------------------------------------------------------------------
// ydiag via single-pass fp16 mma, two phases.
// smem halves layout (elems): phase A: M[64*40]@0, X[32*72]@2560
//                             phase B: C[64*72]@0, P[64*72]@4608
// ---------------------------------------------------------------------------
#define YD_M 0
#define YD_X 2560
#define YD_C 0
#define YD_P 4608

__global__ __launch_bounds__(256) void ydiag_mma(const float* __restrict__ Dp)
{
    const int lt = blockIdx.x, c = blockIdx.y, h = blockIdx.z;
    __shared__ float sdAc[CH_], sdtv[CH_];
    __shared__ __half sbuf[9216];
    const int tid = threadIdx.x;
    const int lane = tid & 31, warp = tid >> 5;
    const int warpM = warp & 1, warpN = warp >> 1;
    const int l0 = lt * 64;

    {
        const int gi = (c * CH_ + tid) * NH_ + h;
        sdAc[tid] = g_dAc[gi];
        sdtv[tid] = g_dt[gi];
    }
    __syncthreads();

    float accA[2][2][4], acc2[2][2][4];
#pragma unroll
    for (int i = 0; i < 2; i++)
#pragma unroll
        for (int j = 0; j < 2; j++)
#pragma unroll
            for (int v = 0; v < 4; v++) { accA[i][j][v] = 0.f; acc2[i][j][v] = 0.f; }

    const int lr = lane & 15;
    const int lc8 = (lane >> 4) * 8;
    const int krB = (lane & 7) | (((lane >> 3) & 1) << 3);
    const int nbB = (lane >> 4) * 8;

    // ---- Phase A ----
    const int smax = l0 + 64;
    for (int s0 = 0; s0 < smax; s0 += 32) {
        {
            const int lrow = tid >> 2;
            const int sseg = (tid & 3) * 8;
            const float dacl = sdAc[l0 + lrow];
            const float* cbp = &g_CB[c * (CH_ * CH_) + (l0 + lrow) * CH_ + s0 + sseg];
            float4 cb0 = *(const float4*)cbp;
            float4 cb1 = *(const float4*)(cbp + 4);
            float cbv[8] = {cb0.x, cb0.y, cb0.z, cb0.w, cb1.x, cb1.y, cb1.z, cb1.w};
#pragma unroll
            for (int j = 0; j < 8; j++) {
                const int s = s0 + sseg + j;
                float v = 0.f;
                if (s <= l0 + lrow) v = cbv[j] * __expf(dacl - sdAc[s]);
                sbuf[YD_M + lrow * 40 + sseg + j] = __float2half_rn(v);
            }
        }
#pragma unroll
        for (int t = 0; t < 2; t++) {
            const int gi = t * 256 + tid;
            const int row = gi >> 4, p4 = (gi & 15) * 4;
            const float wv = sdtv[s0 + row];
            float4 v = *(const float4*)&g_conv[(size_t)(c * CH_ + s0 + row) * CONVD_ + h * HD_ + p4];
            uint32_t* d_ = (uint32_t*)&sbuf[YD_X + row * 72 + p4];
            d_[0] = pack2h(v.x * wv, v.y * wv);
            d_[1] = pack2h(v.z * wv, v.w * wv);
        }
        __syncthreads();
#pragma unroll
        for (int k16 = 0; k16 < 2; k16++) {
            uint32_t a[2][4];
#pragma unroll
            for (int mt = 0; mt < 2; mt++)
                LDSM4(a[mt], su32(&sbuf[YD_M + (warpM * 32 + mt * 16 + lr) * 40 + k16 * 16 + lc8]));
            uint32_t b[2][2];
            {
                const int nc = warpN * 16 + nbB;
                uint32_t r[4];
                LDSM4T(r, su32(&sbuf[YD_X + (k16 * 16 + krB) * 72 + nc]));
                b[0][0] = r[0]; b[0][1] = r[1]; b[1][0] = r[2]; b[1][1] = r[3];
            }
#pragma unroll
            for (int mt = 0; mt < 2; mt++)
#pragma unroll
                for (int ng = 0; ng < 2; ng++)
                    MMA16816H(accA[mt][ng], a[mt], b[ng][0], b[ng][1]);
        }
        __syncthreads();
    }

    // ---- Phase B ----
    const size_t pbase = ((size_t)(c * NH_ + h)) * HD_ * NST_;
    for (int n0c = 0; n0c < NST_; n0c += 64) {
#pragma unroll
        for (int t = 0; t < 4; t++) {
            const int gi = t * 256 + tid;
            const int row = gi >> 4, n4 = (gi & 15) * 4;
            float4 v = *(const float4*)&g_conv[(size_t)(c * CH_ + l0 + row) * CONVD_ +
                                               HID_ + NST_ + n0c + n4];
            uint32_t* d_ = (uint32_t*)&sbuf[YD_C + row * 72 + n4];
            d_[0] = pack2h(v.x, v.y);
            d_[1] = pack2h(v.z, v.w);

            float4 p = *(const float4*)&g_prev[pbase + (size_t)row * NST_ + n0c + n4];
            uint32_t* p_ = (uint32_t*)&sbuf[YD_P + row * 72 + n4];
            p_[0] = pack2h(p.x, p.y);
            p_[1] = pack2h(p.z, p.w);
        }
        __syncthreads();
#pragma unroll
        for (int k16 = 0; k16 < 4; k16++) {
            uint32_t a[2][4];
#pragma unroll
            for (int mt = 0; mt < 2; mt++)
                LDSM4(a[mt], su32(&sbuf[YD_C + (warpM * 32 + mt * 16 + lr) * 72 + k16 * 16 + lc8]));
            uint32_t b[4];
            LDSM4(b, su32(&sbuf[YD_P + (warpN * 16 + lr) * 72 + k16 * 16 + lc8]));
#pragma unroll
            for (int mt = 0; mt < 2; mt++)
#pragma unroll
                for (int ng = 0; ng < 2; ng++)
                    MMA16816H(acc2[mt][ng], a[mt], b[ng], b[ng + 2]);
        }
        __syncthreads();
    }

    // ---- epilogue ----
    const float dh = Dp[h];
#pragma unroll
    for (int mt = 0; mt < 2; mt++) {
        const int lrow = warpM * 32 + mt * 16 + (lane >> 2);
#pragma unroll
        for (int ng = 0; ng < 2; ng++) {
            const int col = warpN * 16 + ng * 8 + (lane & 3) * 2;
#pragma unroll
            for (int half = 0; half < 2; half++) {
                const int l = l0 + lrow + half * 8;
                const int t = c * CH_ + l;
                const float el = __expf(sdAc[l]);
                const float2 x2 = *(const float2*)&g_conv[(size_t)t * CONVD_ + h * HD_ + col];
                float2 o;
                o.x = accA[mt][ng][half * 2]     + el * acc2[mt][ng][half * 2]     + x2.x * dh;
                o.y = accA[mt][ng][half * 2 + 1] + el * acc2[mt][ng][half * 2 + 1] + x2.y * dh;
                *(float2*)&g_y[(size_t)t * HID_ + h * HD_ + col] = o;
            }
        }
    }
}

// ---------------------------------------------------------------------------
// gate + RMSNorm, fused fp16 output for out_proj
// ---------------------------------------------------------------------------
__global__ __launch_bounds__(256) void gatenorm_kernel(const float* __restrict__ nw)
{
    const int t = blockIdx.x;
    const int tid = threadIdx.x;
    float vals[16];
    float ss = 0.f;
#pragma unroll
    for (int k = 0; k < 16; k++) {
        const int i = tid + k * 256;
        const float yv = g_y[(size_t)t * HID_ + i];
        const float zv = g_zx[(size_t)t * D_IN_ + i];
        const float v = yv * (zv / (1.f + __expf(-zv)));
        vals[k] = v;
        ss += v * v;
    }
    __shared__ float red[8];
#pragma unroll
    for (int o = 16; o > 0; o >>= 1) ss += __shfl_xor_sync(0xffffffffu, ss, o);
    if ((tid & 31) == 0) red[tid >> 5] = ss;
    __syncthreads();
    if (tid < 8) {
        float v = red[tid];
#pragma unroll
        for (int o = 4; o > 0; o >>= 1) v += __shfl_xor_sync(0xffu, v, o);
        if (tid == 0) red[0] = v;
    }
    __syncthreads();
    const float scale = rsqrtf(red[0] / (float)HID_ + 1e-5f);
#pragma unroll
    for (int k = 0; k < 16; k++) {
        const int i = tid + k * 256;
        g_yh[(size_t)t * HID_ + i] = __float2half_rn(vals[k] * scale * nw[i]);
    }
}

// ---------------------------------------------------------------------------
extern "C" void kernel_launch(void* const* d_in, const int* in_sizes, int n_in,
                              void* d_out, int out_size)
{
    const float* x       = (const float*)d_in[0];
    const float* in_w    = (const float*)d_in[1];
    const float* conv_w  = (const float*)d_in[2];
    const float* dt_bias = (const float*)d_in[3];
    const float* A_log   = (const float*)d_in[4];
    const float* Dp      = (const float*)d_in[5];
    const float* norm_w  = (const float*)d_in[6];
    const float* out_w   = (const float*)d_in[7];
    float* out = (float*)d_out;

    float *zx, *conv, *cb;
    __half *xh, *wih, *yh, *woh;
    cudaGetSymbolAddress((void**)&zx, g_zx);
    cudaGetSymbolAddress((void**)&conv, g_conv);
    cudaGetSymbolAddress((void**)&cb, g_CB);
    cudaGetSymbolAddress((void**)&xh, g_xh);
    cudaGetSymbolAddress((void**)&wih, g_wih);
    cudaGetSymbolAddress((void**)&yh, g_yh);
    cudaGetSymbolAddress((void**)&woh, g_woh);

    cudaFuncSetAttribute(gemm_mma, cudaFuncAttributeMaxDynamicSharedMemorySize,
                         GM_SMEM_TOTAL);

    // 0) fp16 rounds for in_proj operands
    {
        const int n4s = S_LEN * DIM_ / 4;
        round_f16<<<(n4s + 255) / 256, 256>>>(x, xh, n4s, n4s);
        const int n4w = D_IN_ * DIM_ / 4;
        const int n4wt = D_INP_ * DIM_ / 4;
        round_f16<<<(n4wt + 255) / 256, 256>>>(in_w, wih, n4w, n4wt);
    }

    // 1) in_proj
    gemm_mma<<<dim3(D_INP_ / 128, S_LEN / 128), 256, GM_SMEM_TOTAL>>>(
        xh, wih, zx, D_IN_, DIM_);

    // 2) conv1d + SiLU (time-tiled)
    conv_silu_kernel<<<((S_LEN / CT_T) * (CONVD_ / 4) + 255) / 256, 256>>>(conv_w);

    // 3) dt / dA
    dt_kernel<<<(S_LEN * NH_ + 255) / 256, 256>>>(dt_bias, A_log);

    // 4) cumsum
    cumsum_kernel<<<dim3(NC_, NH_), CH_>>>();

    // 5) CB per chunk
    gemm128<<<dim3(2, 2, NC_), 256>>>(
        CH_, CH_, NST_,
        conv + HID_ + NST_, CONVD_, CH_ * CONVD_,
        conv + HID_,        CONVD_, CH_ * CONVD_,
        cb, CH_, CH_ * CH_);

    // 6) states (fp16 mma)
    states_mma<<<dim3(NC_, NH_), 256>>>();

    // 7) inter-chunk scan
    chunkscan_kernel<<<(NH_ * HD_ * NST_) / 256, 256>>>();

    // 8) y_diag + y_off + D-skip (fp16 mma)
    ydiag_mma<<<dim3(4, NC_, NH_), 256>>>(Dp);

    // 9) gate + RMSNorm (+ fused fp16 round)
    gatenorm_kernel<<<S_LEN, 256>>>(norm_w);

    // 10) out_proj
    {
        const int n4o = DIM_ * HID_ / 4;
        round_f16<<<(n4o + 255) / 256, 256>>>(out_w, woh, n4o, n4o);
    }
    gemm_mma<<<dim3(DIM_ / 128, S_LEN / 128), 256, GM_SMEM_TOTAL>>>(
        yh, woh, out, DIM_, HID_);
}